// round 12
// baseline (speedup 1.0000x reference)
#include <cuda_runtime.h>
#include <cuda_fp16.h>
#include <cstdint>

// ---------------------------------------------------------------------------
// TransformerAgent: 4-layer FAVOR+ transformer.
// GEMMs: fp16 mma.sync with BOTH operands pre-swizzled into mma fragment
// layouts in gmem -> mainloop is pure LDG.128 + HMMA. No smem, no barriers.
// 128x128 tile, 64x32 warp tile. Layer 3: token-0 rows only.
// ---------------------------------------------------------------------------

#define Bc 64
#define Sc 512
#define SP 513
#define Dc 512
#define Hc 8
#define HDc 64
#define Fc 2048
#define Lc 4
#define Ac 16
#define OBSc 128
#define Tc (Bc * SP)          // 32832 tokens
#define TcPad 32896           // padded to 257*128 rows (2056 m-tiles)
#define QS (3 * Dc)

#define KEPS 1e-3f
#define LNEPS 1e-6f

typedef __half fp16;

// ------------------------- scratch (static device) ------------------------
__device__ float g_x  [Tc * Dc];                       // residual, linear
__device__ __align__(256) fp16 g_xh [TcPad * Dc];      // A-frag layout
__device__ fp16  g_qkv[Tc * QS];                       // linear (favor reads)
__device__ __align__(256) fp16 g_ah [TcPad * Dc];      // A-frag
__device__ float g_tmp[Tc * Dc];
__device__ __align__(256) fp16 g_fh [(size_t)TcPad * Fc]; // A-frag
__device__ float g_kv [Bc * Hc * HDc * HDc];
__device__ float g_ks [Bc * Hc * HDc];
__device__ __align__(256) fp16 g_ih [Bc * Sc * OBSc];  // A-frag
// layer-3 compact (token-0 rows only, padded to 128 rows = 8 m-tiles)
__device__ float g_x0  [Bc * Dc];
__device__ __align__(256) fp16 g_xh0 [128 * Dc];
__device__ __align__(256) fp16 g_xg0 [128 * Dc];
__device__ float g_q0  [Bc * Dc];
__device__ __align__(256) fp16 g_ah0 [128 * Dc];
__device__ float g_tmp0[Bc * Dc];
__device__ __align__(256) fp16 g_fh0 [128 * Fc];
// weights in mma B-fragment layout (ntPair-major), fp16
__device__ __align__(256) fp16 g_wqkv[Lc * QS * Dc];
__device__ float g_bqkv[Lc * QS];
__device__ __align__(256) fp16 g_wo [Lc * Dc * Dc];
__device__ __align__(256) fp16 g_w1 [Lc * Fc * Dc];
__device__ __align__(256) fp16 g_w2 [Lc * Dc * Fc];
__device__ __align__(256) fp16 g_we [Dc * OBSc];

// --------------------------- helpers ---------------------------------------
// A-fragment layout: uint32 index of the (k,k+1) pair of element (m,k), k even.
__device__ __forceinline__ uint32_t afrag(int m, int k, int ktiles) {
    return ((uint32_t)((m >> 4) * ktiles + (k >> 4)) * 32
            + ((m & 7) << 2) + ((k & 7) >> 1)) * 4
           + (((k & 15) >> 3) << 1) + ((m & 15) >> 3);
}

#define MMA16816(d, a, b0, b1) \
    asm volatile("mma.sync.aligned.m16n8k16.row.col.f32.f16.f16.f32 " \
        "{%0,%1,%2,%3},{%4,%5,%6,%7},{%8,%9},{%0,%1,%2,%3};" \
        : "+f"((d)[0]), "+f"((d)[1]), "+f"((d)[2]), "+f"((d)[3]) \
        : "r"((a)[0]), "r"((a)[1]), "r"((a)[2]), "r"((a)[3]), "r"(b0), "r"(b1))

// ---------------------------------------------------------------------------
// fragment GEMM: C[M,N] = A @ W^T + bias. A and W both pre-swizzled.
// grid.x = m-blocks (8 m-tiles = 128 rows), grid.y = n-blocks (128 cols).
// 8 warps: wm in {0,1} x wn in {0..3}, warp tile 64x32. No smem. No barriers.
// ---------------------------------------------------------------------------
__global__ __launch_bounds__(256, 2)
void gemm_frag(const uint4* __restrict__ Aq, const uint4* __restrict__ Wq,
               const float* __restrict__ bias,
               float* __restrict__ Cf, fp16* __restrict__ Ch,
               int M, int N, int K, int ldc, int ldchkt,
               int relu, int rowmap, int fragC)
{
    const int tid  = threadIdx.x;
    const int wid  = tid >> 5;
    const int lane = tid & 31;
    const int wm = wid >> 2;
    const int wn = wid & 3;
    const int ktiles = K >> 4;
    const int mt0 = blockIdx.x * 8 + wm * 4;
    const int n0  = blockIdx.y * 128;
    const int ntp0 = (n0 >> 4) + wn * 2;

    float acc[4][4][4];
#pragma unroll
    for (int a = 0; a < 4; a++)
#pragma unroll
        for (int b = 0; b < 4; b++)
#pragma unroll
            for (int c = 0; c < 4; c++) acc[a][b][c] = 0.f;

#pragma unroll 4
    for (int kt = 0; kt < ktiles; kt++) {
        uint4 b0 = Wq[((size_t)ntp0       * ktiles + kt) * 32 + lane];
        uint4 b1 = Wq[((size_t)(ntp0 + 1) * ktiles + kt) * 32 + lane];
        uint4 a0 = Aq[((size_t)(mt0 + 0) * ktiles + kt) * 32 + lane];
        uint4 a1 = Aq[((size_t)(mt0 + 1) * ktiles + kt) * 32 + lane];
        uint4 a2 = Aq[((size_t)(mt0 + 2) * ktiles + kt) * 32 + lane];
        uint4 a3 = Aq[((size_t)(mt0 + 3) * ktiles + kt) * 32 + lane];

        MMA16816(acc[0][0], ((const uint32_t*)&a0), b0.x, b0.y);
        MMA16816(acc[0][1], ((const uint32_t*)&a0), b0.z, b0.w);
        MMA16816(acc[0][2], ((const uint32_t*)&a0), b1.x, b1.y);
        MMA16816(acc[0][3], ((const uint32_t*)&a0), b1.z, b1.w);
        MMA16816(acc[1][0], ((const uint32_t*)&a1), b0.x, b0.y);
        MMA16816(acc[1][1], ((const uint32_t*)&a1), b0.z, b0.w);
        MMA16816(acc[1][2], ((const uint32_t*)&a1), b1.x, b1.y);
        MMA16816(acc[1][3], ((const uint32_t*)&a1), b1.z, b1.w);
        MMA16816(acc[2][0], ((const uint32_t*)&a2), b0.x, b0.y);
        MMA16816(acc[2][1], ((const uint32_t*)&a2), b0.z, b0.w);
        MMA16816(acc[2][2], ((const uint32_t*)&a2), b1.x, b1.y);
        MMA16816(acc[2][3], ((const uint32_t*)&a2), b1.z, b1.w);
        MMA16816(acc[3][0], ((const uint32_t*)&a3), b0.x, b0.y);
        MMA16816(acc[3][1], ((const uint32_t*)&a3), b0.z, b0.w);
        MMA16816(acc[3][2], ((const uint32_t*)&a3), b1.x, b1.y);
        MMA16816(acc[3][3], ((const uint32_t*)&a3), b1.z, b1.w);
    }

    // ---- epilogue ----
    const int rq = lane >> 2;
    const int cq = (lane & 3) * 2;
#pragma unroll
    for (int mi = 0; mi < 4; mi++) {
#pragma unroll
        for (int half = 0; half < 2; half++) {
            int rr = (mt0 + mi) * 16 + rq + half * 8;
            if (rr >= M) continue;
            int orow = rowmap ? (rr + rr / Sc + 1) : rr;
#pragma unroll
            for (int nj = 0; nj < 4; nj++) {
                int cc = n0 + wn * 32 + nj * 8 + cq;
                float v0 = acc[mi][nj][half * 2 + 0] + bias[cc];
                float v1 = acc[mi][nj][half * 2 + 1] + bias[cc + 1];
                if (relu) { v0 = fmaxf(v0, 0.f); v1 = fmaxf(v1, 0.f); }
                if (Cf)
                    *(float2*)(Cf + (size_t)orow * ldc + cc) = make_float2(v0, v1);
                if (Ch) {
                    __half2 hp = __floats2half2_rn(v0, v1);
                    if (fragC)
                        ((uint32_t*)Ch)[afrag(orow, cc, ldchkt)] = *(uint32_t*)&hp;
                    else
                        *(__half2*)(Ch + (size_t)orow * ldc + cc) = hp;
                }
            }
        }
    }
}

// ----- batched weight transpose + fp16 + B-fragment swizzle ----------------
struct WJob { const float* src; fp16* dst; int K; int N; };
struct WJobs { WJob j[25]; };

__global__ void wconv_all(WJobs jobs)
{
    WJob jb = jobs.j[blockIdx.z];
    int nbx = jb.N >> 5;
    int nb  = nbx * (jb.K >> 5);
    int bid = blockIdx.x;
    if (bid >= nb) return;
    int x = (bid % nbx) * 32;
    int y = (bid / nbx) * 32;

    __shared__ float t[32][33];
#pragma unroll
    for (int r = 0; r < 4; r++) {
        int row = y + threadIdx.y + r * 8;
        t[threadIdx.y + r * 8][threadIdx.x] = jb.src[(size_t)row * jb.N + x + threadIdx.x];
    }
    __syncthreads();
    int ktiles = jb.K >> 4;
#pragma unroll
    for (int r = 0; r < 4; r++) {
        int n = x + threadIdx.y + r * 8;
        int k = y + threadIdx.x;
        float v = t[threadIdx.x][threadIdx.y + r * 8];
        int k0 = k & 15;
        int lane = ((n & 7) << 2) | ((k0 >> 1) & 3);
        int sub  = ((n >> 3) & 1) * 4 + ((k0 >= 8) ? 2 : 0) + (k0 & 1);
        size_t idx = (((size_t)(n >> 4) * ktiles + (k >> 4)) * 32 + lane) * 8 + sub;
        jb.dst[idx] = __float2half_rn(v);
    }
}

// ------------------ pack qkv biases: [L][3*D] ------------------------------
__global__ void bpack(const float* __restrict__ bq, const float* __restrict__ bk,
                      const float* __restrict__ bv, float* __restrict__ dst)
{
    int l = blockIdx.x;
    int i = threadIdx.x;
    dst[l * QS + i]          = bq[l * Dc + i];
    dst[l * QS + Dc + i]     = bk[l * Dc + i];
    dst[l * QS + 2 * Dc + i] = bv[l * Dc + i];
}

// --------------- ins (fp32, linear) -> ih (fp16, A-frag) --------------------
__global__ void fcvt_frag(const float* __restrict__ src, fp16* __restrict__ dst)
{
    int idx = blockIdx.x * 256 + threadIdx.x;     // one per (m, k8)
    int m  = idx >> 4;                            // OBSc/8 = 16
    int k0 = (idx & 15) * 8;
    const float4* p = (const float4*)(src + (size_t)m * OBSc + k0);
    float4 v0 = p[0], v1 = p[1];
    uint32_t* d = (uint32_t*)dst;
    const int kt = OBSc >> 4;
    __half2 h;
    h = __floats2half2_rn(v0.x, v0.y); d[afrag(m, k0 + 0, kt)] = *(uint32_t*)&h;
    h = __floats2half2_rn(v0.z, v0.w); d[afrag(m, k0 + 2, kt)] = *(uint32_t*)&h;
    h = __floats2half2_rn(v1.x, v1.y); d[afrag(m, k0 + 4, kt)] = *(uint32_t*)&h;
    h = __floats2half2_rn(v1.z, v1.w); d[afrag(m, k0 + 6, kt)] = *(uint32_t*)&h;
}

// --------------------- init: hidden-state row per batch -------------------
__global__ void init_h0(const float* __restrict__ hs, const void* __restrict__ resets,
                        float* __restrict__ x, fp16* __restrict__ xh)
{
    __shared__ int mode;
    int b = blockIdx.x;
    if (threadIdx.x == 0) {
        const unsigned int* w = (const unsigned int*)resets;
        bool allint = true, allflt = true;
        for (int i = 0; i < 16; i++) {
            unsigned int u = w[i];
            if (u != 0u && u != 1u) allint = false;
            if (u != 0u && u != 0x3F800000u) allflt = false;
        }
        mode = allint ? 0 : (allflt ? 2 : 1);
    }
    __syncthreads();
    bool rst;
    if (mode == 0)      rst = ((const int*)resets)[b] != 0;
    else if (mode == 2) rst = ((const float*)resets)[b] != 0.f;
    else                rst = ((const unsigned char*)resets)[b] != 0;

    int k = threadIdx.x * 2;    // 256 threads, pairs
    float v0 = rst ? 0.f : hs[b * Dc + k];
    float v1 = rst ? 0.f : hs[b * Dc + k + 1];
    int m = b * SP;
    *(float2*)(x + (size_t)m * Dc + k) = make_float2(v0, v1);
    __half2 h = __floats2half2_rn(v0, v1);
    ((uint32_t*)xh)[afrag(m, k, Dc >> 4)] = *(uint32_t*)&h;
}

// ------------------- FAVOR: kv = sum_s pk^T outer v, ksum ------------------
__global__ __launch_bounds__(256)
void favor_kv(const fp16* __restrict__ qkv, float* __restrict__ kv,
              float* __restrict__ ksum)
{
    int bh = blockIdx.x;
    int b = bh / Hc, h = bh % Hc;
    const fp16* kb = qkv + (size_t)b * SP * QS + Dc + h * HDc;
    const fp16* vb = qkv + (size_t)b * SP * QS + 2 * Dc + h * HDc;

    __shared__ float spk[8][HDc];
    __shared__ float sv [8][HDc];

    int tid = threadIdx.x;
    int tm = (tid >> 4) * 4;
    int td = (tid & 15) * 4;

    float acc[4][4];
#pragma unroll
    for (int i = 0; i < 4; i++)
#pragma unroll
        for (int j = 0; j < 4; j++) acc[i][j] = 0.f;
    float ks = 0.f;

    for (int s0 = 0; s0 < SP; s0 += 8) {
        int nch = min(8, SP - s0);
        for (int i = tid; i < nch * HDc; i += 256) {
            int ss = i >> 6, dd = i & 63;
            float kk = __half2float(kb[(size_t)(s0 + ss) * QS + dd]);
            spk[ss][dd] = fmaxf(kk, 0.f) + KEPS;
            sv[ss][dd]  = __half2float(vb[(size_t)(s0 + ss) * QS + dd]);
        }
        __syncthreads();
        for (int j = 0; j < nch; j++) {
            float pa[4], va[4];
#pragma unroll
            for (int i = 0; i < 4; i++) { pa[i] = spk[j][tm + i]; va[i] = sv[j][td + i]; }
#pragma unroll
            for (int i = 0; i < 4; i++)
#pragma unroll
                for (int l = 0; l < 4; l++)
                    acc[i][l] = fmaf(pa[i], va[l], acc[i][l]);
            if (tid < HDc) ks += spk[j][tid];
        }
        __syncthreads();
    }

    float* kvb = kv + (size_t)bh * HDc * HDc;
#pragma unroll
    for (int i = 0; i < 4; i++)
#pragma unroll
        for (int l = 0; l < 4; l++)
            kvb[(tm + i) * HDc + td + l] = acc[i][l];
    if (tid < HDc) ksum[bh * HDc + tid] = ks;
}

// ---------- FAVOR: num = pq @ kv, den; out -> ah in A-frag layout -----------
__global__ __launch_bounds__(256)
void favor_num(const fp16* __restrict__ qkv, const float* __restrict__ kv,
               const float* __restrict__ ksum, fp16* __restrict__ ah)
{
    int bh = blockIdx.x;
    int b = bh / Hc, h = bh % Hc;
    int t0 = blockIdx.y * 16;

    __shared__ float skv[HDc][HDc];
    __shared__ float sks[HDc];
    __shared__ float spq[16][HDc];

    int tid = threadIdx.x;
    const float* kvb = kv + (size_t)bh * HDc * HDc;
    for (int i = tid; i < (HDc * HDc) / 4; i += 256)
        ((float4*)skv)[i] = ((const float4*)kvb)[i];
    if (tid < HDc) sks[tid] = ksum[bh * HDc + tid];
    for (int i = tid; i < 16 * HDc; i += 256) {
        int tt = i >> 6, dd = i & 63;
        int s = t0 + tt;
        float qv = 0.f;
        if (s < SP) qv = __half2float(qkv[((size_t)b * SP + s) * QS + h * HDc + dd]);
        spq[tt][dd] = fmaxf(qv, 0.f) + KEPS;
    }
    __syncthreads();

    int t = tid >> 4;
    int dq = (tid & 15) * 4;
    float a0 = 0.f, a1 = 0.f, a2 = 0.f, a3 = 0.f, den = 0.f;
#pragma unroll
    for (int m = 0; m < HDc; m++) {
        float pq = spq[t][m];
        den = fmaf(pq, sks[m], den);
        float4 kk = *(const float4*)&skv[m][dq];
        a0 = fmaf(pq, kk.x, a0);
        a1 = fmaf(pq, kk.y, a1);
        a2 = fmaf(pq, kk.z, a2);
        a3 = fmaf(pq, kk.w, a3);
    }
    int s = t0 + t;
    if (s < SP) {
        float inv = 1.f / den;
        __half2 p0 = __floats2half2_rn(a0 * inv, a1 * inv);
        __half2 p1 = __floats2half2_rn(a2 * inv, a3 * inv);
        int m = b * SP + s;
        int kb = h * HDc + dq;
        ((uint32_t*)ah)[afrag(m, kb,     Dc >> 4)] = *(uint32_t*)&p0;
        ((uint32_t*)ah)[afrag(m, kb + 2, Dc >> 4)] = *(uint32_t*)&p1;
    }
}

// --------------- x = LayerNorm(a + x) * s + b (xh -> A-frag) ----------------
__global__ __launch_bounds__(128)
void add_ln(const float* __restrict__ a, float* __restrict__ x,
            fp16* __restrict__ xh,
            const float* __restrict__ s, const float* __restrict__ bb)
{
    size_t r = blockIdx.x;
    const float* ar = a + r * Dc;
    float* xr = x + r * Dc;
    int tid = threadIdx.x;
    int c0 = tid * 4;

    float4 av = *(const float4*)(ar + c0);
    float4 xv = *(const float4*)(xr + c0);
    float v[4] = { av.x + xv.x, av.y + xv.y, av.z + xv.z, av.w + xv.w };
    float sum = v[0] + v[1] + v[2] + v[3];
    float sq  = fmaf(v[0], v[0], fmaf(v[1], v[1], fmaf(v[2], v[2], v[3] * v[3])));
#pragma unroll
    for (int o = 16; o > 0; o >>= 1) {
        sum += __shfl_xor_sync(0xFFFFFFFFu, sum, o);
        sq  += __shfl_xor_sync(0xFFFFFFFFu, sq, o);
    }
    __shared__ float rs[4], rq[4];
    int w = tid >> 5;
    if ((tid & 31) == 0) { rs[w] = sum; rq[w] = sq; }
    __syncthreads();
    sum = rs[0] + rs[1] + rs[2] + rs[3];
    sq  = rq[0] + rq[1] + rq[2] + rq[3];
    float mean = sum * (1.f / Dc);
    float var  = sq * (1.f / Dc) - mean * mean;
    float inv  = rsqrtf(var + LNEPS);

    float o0 = (v[0] - mean) * inv * s[c0 + 0] + bb[c0 + 0];
    float o1 = (v[1] - mean) * inv * s[c0 + 1] + bb[c0 + 1];
    float o2 = (v[2] - mean) * inv * s[c0 + 2] + bb[c0 + 2];
    float o3 = (v[3] - mean) * inv * s[c0 + 3] + bb[c0 + 3];
    *(float4*)(xr + c0) = make_float4(o0, o1, o2, o3);
    __half2 h0 = __floats2half2_rn(o0, o1);
    __half2 h1 = __floats2half2_rn(o2, o3);
    ((uint32_t*)xh)[afrag((int)r, c0,     Dc >> 4)] = *(uint32_t*)&h0;
    ((uint32_t*)xh)[afrag((int)r, c0 + 2, Dc >> 4)] = *(uint32_t*)&h1;
}

// ---- layer-3 compact variant -----------------------------------------------
__global__ __launch_bounds__(128)
void add_ln0(const float* __restrict__ a, const float* __restrict__ xin,
             size_t xin_stride, float* __restrict__ xout, fp16* __restrict__ xh,
             const float* __restrict__ s, const float* __restrict__ bb)
{
    int b = blockIdx.x;
    const float* ar = a + (size_t)b * Dc;
    const float* xr = xin + (size_t)b * xin_stride;
    int tid = threadIdx.x;
    int c0 = tid * 4;

    float4 av = *(const float4*)(ar + c0);
    float4 xv = *(const float4*)(xr + c0);
    float v[4] = { av.x + xv.x, av.y + xv.y, av.z + xv.z, av.w + xv.w };
    float sum = v[0] + v[1] + v[2] + v[3];
    float sq  = fmaf(v[0], v[0], fmaf(v[1], v[1], fmaf(v[2], v[2], v[3] * v[3])));
#pragma unroll
    for (int o = 16; o > 0; o >>= 1) {
        sum += __shfl_xor_sync(0xFFFFFFFFu, sum, o);
        sq  += __shfl_xor_sync(0xFFFFFFFFu, sq, o);
    }
    __shared__ float rs[4], rq[4];
    int w = tid >> 5;
    if ((tid & 31) == 0) { rs[w] = sum; rq[w] = sq; }
    __syncthreads();
    sum = rs[0] + rs[1] + rs[2] + rs[3];
    sq  = rq[0] + rq[1] + rq[2] + rq[3];
    float mean = sum * (1.f / Dc);
    float var  = sq * (1.f / Dc) - mean * mean;
    float inv  = rsqrtf(var + LNEPS);

    float o0 = (v[0] - mean) * inv * s[c0 + 0] + bb[c0 + 0];
    float o1 = (v[1] - mean) * inv * s[c0 + 1] + bb[c0 + 1];
    float o2 = (v[2] - mean) * inv * s[c0 + 2] + bb[c0 + 2];
    float o3 = (v[3] - mean) * inv * s[c0 + 3] + bb[c0 + 3];
    *(float4*)(xout + (size_t)b * Dc + c0) = make_float4(o0, o1, o2, o3);
    __half2 h0 = __floats2half2_rn(o0, o1);
    __half2 h1 = __floats2half2_rn(o2, o3);
    ((uint32_t*)xh)[afrag(b, c0,     Dc >> 4)] = *(uint32_t*)&h0;
    ((uint32_t*)xh)[afrag(b, c0 + 2, Dc >> 4)] = *(uint32_t*)&h1;
}

// ---- gather token-0 rows of xh (frag) into compact xg0 (frag) -------------
__global__ void gather_x0(const fp16* __restrict__ xh, fp16* __restrict__ xg0)
{
    int b = blockIdx.x;
    int k = threadIdx.x * 2;      // 256 threads
    uint32_t v = ((const uint32_t*)xh)[afrag(b * SP, k, Dc >> 4)];
    ((uint32_t*)xg0)[afrag(b, k, Dc >> 4)] = v;
}

// ---- layer-3: attention out for token 0 only (ah0 in A-frag) ---------------
__global__ __launch_bounds__(64)
void favor_num0(const float* __restrict__ q0, const float* __restrict__ kv,
                const float* __restrict__ ksum, fp16* __restrict__ ah0)
{
    int bh = blockIdx.x;
    int b = bh / Hc, h = bh % Hc;
    int d = threadIdx.x;   // 0..63

    __shared__ float spq[HDc];
    __shared__ float sks[HDc];
    float qv = q0[(size_t)b * Dc + h * HDc + d];
    spq[d] = fmaxf(qv, 0.f) + KEPS;
    sks[d] = ksum[bh * HDc + d];
    __syncthreads();

    const float* kvb = kv + (size_t)bh * HDc * HDc;
    float num = 0.f, den = 0.f;
#pragma unroll 8
    for (int m = 0; m < HDc; m++) {
        float pq = spq[m];
        num = fmaf(pq, kvb[m * HDc + d], num);
        den = fmaf(pq, sks[m], den);
    }
    float r_ = num / den;
    float r2 = __shfl_down_sync(0xFFFFFFFFu, r_, 1);
    if ((d & 1) == 0) {
        __half2 hp = __floats2half2_rn(r_, r2);
        ((uint32_t*)ah0)[afrag(b, h * HDc + d, Dc >> 4)] = *(uint32_t*)&hp;
    }
}

// ---------------- head: copy h_out and compute q_vals ----------------------
__global__ __launch_bounds__(512)
void head_kernel(const float* __restrict__ x0, const float* __restrict__ Wqp,
                 const float* __restrict__ bqp, float* __restrict__ out)
{
    int b = blockIdx.x;
    int tid = threadIdx.x;
    const float* hr = x0 + (size_t)b * Dc;
    out[b * Dc + tid] = hr[tid];

    int w = tid >> 5, lane = tid & 31;
    float sum = 0.f;
    for (int i = lane; i < Dc; i += 32)
        sum = fmaf(hr[i], Wqp[i * Ac + w], sum);
#pragma unroll
    for (int o = 16; o > 0; o >>= 1)
        sum += __shfl_xor_sync(0xFFFFFFFFu, sum, o);
    if (lane == 0) out[Bc * Dc + b * Ac + w] = sum + bqp[w];
}

// ---------------------------------------------------------------------------
extern "C" void kernel_launch(void* const* d_in, const int* in_sizes, int n_in,
                              void* d_out, int out_size)
{
    const float* hs    = (const float*)d_in[0];
    const float* ins   = (const float*)d_in[1];
    const void*  rsts  = d_in[2];
    const float* W_emb = (const float*)d_in[3];
    const float* b_emb = (const float*)d_in[4];
    const float* Wq    = (const float*)d_in[5];
    const float* bq    = (const float*)d_in[6];
    const float* Wk    = (const float*)d_in[7];
    const float* bk    = (const float*)d_in[8];
    const float* Wv    = (const float*)d_in[9];
    const float* bv    = (const float*)d_in[10];
    const float* Wo    = (const float*)d_in[11];
    const float* bo    = (const float*)d_in[12];
    const float* ln1s  = (const float*)d_in[13];
    const float* ln1b  = (const float*)d_in[14];
    const float* ln2s  = (const float*)d_in[15];
    const float* ln2b  = (const float*)d_in[16];
    const float* W1    = (const float*)d_in[17];
    const float* b1    = (const float*)d_in[18];
    const float* W2    = (const float*)d_in[19];
    const float* b2    = (const float*)d_in[20];
    const float* Wqp   = (const float*)d_in[21];
    const float* bqp   = (const float*)d_in[22];
    float* out = (float*)d_out;

    float *x, *tmp, *kv, *ks, *bqkv, *x0, *q0, *tmp0;
    fp16 *xh, *qkv, *ah, *fh, *ih, *xh0, *xg0, *ah0, *fh0;
    fp16 *wqkv, *wo, *w1, *w2, *we;
    cudaGetSymbolAddress((void**)&x,    g_x);
    cudaGetSymbolAddress((void**)&xh,   g_xh);
    cudaGetSymbolAddress((void**)&qkv,  g_qkv);
    cudaGetSymbolAddress((void**)&ah,   g_ah);
    cudaGetSymbolAddress((void**)&tmp,  g_tmp);
    cudaGetSymbolAddress((void**)&fh,   g_fh);
    cudaGetSymbolAddress((void**)&kv,   g_kv);
    cudaGetSymbolAddress((void**)&ks,   g_ks);
    cudaGetSymbolAddress((void**)&ih,   g_ih);
    cudaGetSymbolAddress((void**)&x0,   g_x0);
    cudaGetSymbolAddress((void**)&xh0,  g_xh0);
    cudaGetSymbolAddress((void**)&xg0,  g_xg0);
    cudaGetSymbolAddress((void**)&q0,   g_q0);
    cudaGetSymbolAddress((void**)&ah0,  g_ah0);
    cudaGetSymbolAddress((void**)&tmp0, g_tmp0);
    cudaGetSymbolAddress((void**)&fh0,  g_fh0);
    cudaGetSymbolAddress((void**)&bqkv, g_bqkv);
    cudaGetSymbolAddress((void**)&wqkv, g_wqkv);
    cudaGetSymbolAddress((void**)&wo,   g_wo);
    cudaGetSymbolAddress((void**)&w1,   g_w1);
    cudaGetSymbolAddress((void**)&w2,   g_w2);
    cudaGetSymbolAddress((void**)&we,   g_we);

    // ins -> A-frag fp16
    fcvt_frag<<<(Bc * Sc * OBSc / 8) / 256, 256>>>(ins, ih);

    // all weight conversions (transpose + fp16 + B-fragment swizzle)
    {
        WJobs jobs;
        int nj = 0;
        jobs.j[nj++] = { W_emb, we, OBSc, Dc };
        for (int l = 0; l < Lc; l++) {
            size_t od = (size_t)l * Dc * Dc;
            size_t oq = (size_t)l * QS * Dc;
            size_t o1 = (size_t)l * Fc * Dc;
            size_t o2 = (size_t)l * Dc * Fc;
            jobs.j[nj++] = { Wq + od, wqkv + oq,                       Dc, Dc };
            jobs.j[nj++] = { Wk + od, wqkv + oq + (size_t)Dc * Dc,     Dc, Dc };
            jobs.j[nj++] = { Wv + od, wqkv + oq + (size_t)2 * Dc * Dc, Dc, Dc };
            jobs.j[nj++] = { Wo + od, wo + od, Dc, Dc };
            jobs.j[nj++] = { W1 + o1, w1 + o1, Dc, Fc };
            jobs.j[nj++] = { W2 + o2, w2 + o2, Fc, Dc };
        }
        wconv_all<<<dim3(1024, 1, 25), dim3(32, 8)>>>(jobs);
    }
    // pack qkv biases
    bpack<<<Lc, Dc>>>(bq, bk, bv, bqkv);

    // embedding GEMM: A=ih (frag), out -> x (linear, rowmap) + xh (frag, rowmap)
    gemm_frag<<<dim3((Bc * Sc) / 128, Dc / 128), 256>>>(
        (const uint4*)ih, (const uint4*)we, b_emb, x, xh,
        Bc * Sc, Dc, OBSc, Dc, Dc >> 4, 0, 1, 1);

    // hidden-state rows
    init_h0<<<Bc, 256>>>(hs, rsts, x, xh);

    const int MB = (Tc + 127) / 128;              // 257 m-blocks
    const dim3 gQKV(MB, QS / 128);
    const dim3 gKV (MB, 1024 / 128);
    const dim3 gD  (MB, Dc / 128);
    const dim3 gF  (MB, Fc / 128);

    // ---- layers 0..2: full ----
    for (int l = 0; l < Lc - 1; l++) {
        size_t od = (size_t)l * Dc * Dc;
        size_t oq = (size_t)l * QS * Dc;
        size_t o1 = (size_t)l * Fc * Dc;
        size_t o2 = (size_t)l * Dc * Fc;

        gemm_frag<<<gQKV, 256>>>((const uint4*)xh, (const uint4*)(wqkv + oq),
                                 bqkv + l * QS, 0, qkv, Tc, QS, Dc, QS, 0, 0, 0, 0);

        favor_kv<<<Bc * Hc, 256>>>(qkv, kv, ks);
        favor_num<<<dim3(Bc * Hc, (SP + 15) / 16), 256>>>(qkv, kv, ks, ah);

        gemm_frag<<<gD, 256>>>((const uint4*)ah, (const uint4*)(wo + od),
                               bo + l * Dc, tmp, 0, Tc, Dc, Dc, Dc, 0, 0, 0, 0);
        add_ln<<<Tc, 128>>>(tmp, x, xh, ln1s + l * Dc, ln1b + l * Dc);

        gemm_frag<<<gF, 256>>>((const uint4*)xh, (const uint4*)(w1 + o1),
                               b1 + l * Fc, 0, fh, Tc, Fc, Dc, Fc, Fc >> 4, 1, 0, 1);
        gemm_frag<<<gD, 256>>>((const uint4*)fh, (const uint4*)(w2 + o2),
                               b2 + l * Dc, tmp, 0, Tc, Dc, Fc, Dc, 0, 0, 0, 0);
        add_ln<<<Tc, 128>>>(tmp, x, xh, ln2s + l * Dc, ln2b + l * Dc);
    }

    // ---- layer 3: only token-0 rows beyond the KV projection ----
    {
        const int l = Lc - 1;
        size_t od = (size_t)l * Dc * Dc;
        size_t oq = (size_t)l * QS * Dc;
        size_t o1 = (size_t)l * Fc * Dc;
        size_t o2 = (size_t)l * Dc * Fc;

        // K,V for all tokens
        gemm_frag<<<gKV, 256>>>((const uint4*)xh,
                                (const uint4*)(wqkv + oq + (size_t)Dc * Dc),
                                bqkv + l * QS + Dc, 0, qkv + Dc,
                                Tc, 1024, Dc, QS, 0, 0, 0, 0);
        // Q for the 64 token-0 rows
        gather_x0<<<Bc, 256>>>(xh, xg0);
        gemm_frag<<<dim3(1, Dc / 128), 256>>>(
            (const uint4*)xg0, (const uint4*)(wqkv + oq), bqkv + l * QS,
            q0, 0, Bc, Dc, Dc, Dc, 0, 0, 0, 0);

        favor_kv<<<Bc * Hc, 256>>>(qkv, kv, ks);
        favor_num0<<<Bc * Hc, 64>>>(q0, kv, ks, ah0);

        // AO on 64 rows
        gemm_frag<<<dim3(1, Dc / 128), 256>>>(
            (const uint4*)ah0, (const uint4*)(wo + od), bo + l * Dc,
            tmp0, 0, Bc, Dc, Dc, Dc, 0, 0, 0, 0);
        add_ln0<<<Bc, 128>>>(tmp0, x, (size_t)SP * Dc, x0, xh0,
                             ln1s + l * Dc, ln1b + l * Dc);

        // FFN on 64 rows
        gemm_frag<<<dim3(1, Fc / 128), 256>>>(
            (const uint4*)xh0, (const uint4*)(w1 + o1), b1 + l * Fc,
            0, fh0, Bc, Fc, Dc, Fc, Fc >> 4, 1, 0, 1);
        gemm_frag<<<dim3(1, Dc / 128), 256>>>(
            (const uint4*)fh0, (const uint4*)(w2 + o2), b2 + l * Dc,
            tmp0, 0, Bc, Dc, Fc, Dc, 0, 0, 0, 0);
        add_ln0<<<Bc, 128>>>(tmp0, x0, (size_t)Dc, x0, xh0,
                             ln2s + l * Dc, ln2b + l * Dc);
    }

    head_kernel<<<Bc, Dc>>>(x0, Wqp, bqp, out);
}

// round 13
// speedup vs baseline: 1.0864x; 1.0864x over previous
#include <cuda_runtime.h>
#include <cuda_fp16.h>
#include <cstdint>

// ---------------------------------------------------------------------------
// TransformerAgent: 4-layer FAVOR+ transformer.
// GEMMs: fp16 mma.sync; A via cp.async+ldmatrix (BK=128, 2-stage double
// buffer), B weights pre-swizzled into mma fragment layout fed by LDG.128.
// 128x128 tile, 64x32 warp tile, 2 CTAs/SM. Layer 3: token-0 rows only.
// ---------------------------------------------------------------------------

#define Bc 64
#define Sc 512
#define SP 513
#define Dc 512
#define Hc 8
#define HDc 64
#define Fc 2048
#define Lc 4
#define Ac 16
#define OBSc 128
#define Tc (Bc * SP)          // 32832 tokens
#define QS (3 * Dc)           // fused qkv row stride = 1536

#define KEPS 1e-3f
#define LNEPS 1e-6f

typedef __half fp16;

// ------------------------- scratch (static device) ------------------------
__device__ float g_x  [Tc * Dc];
__device__ fp16  g_xh [Tc * Dc];
__device__ fp16  g_qkv[Tc * QS];
__device__ fp16  g_ah [Tc * Dc];
__device__ float g_tmp[Tc * Dc];
__device__ fp16  g_fh [Tc * Fc];
__device__ float g_kv [Bc * Hc * HDc * HDc];
__device__ float g_ks [Bc * Hc * HDc];
__device__ fp16  g_ih [Bc * Sc * OBSc];
// layer-3 compact (token-0 rows only)
__device__ float g_x0  [Bc * Dc];
__device__ fp16  g_xh0 [Bc * Dc];
__device__ fp16  g_xg0 [Bc * Dc];
__device__ float g_q0  [Bc * Dc];
__device__ fp16  g_ah0 [Bc * Dc];
__device__ float g_tmp0[Bc * Dc];
__device__ fp16  g_fh0 [Bc * Fc];
// weights in mma B-fragment layout (ntPair-major), fp16
__device__ __align__(256) fp16 g_wqkv[Lc * QS * Dc];
__device__ float g_bqkv[Lc * QS];
__device__ __align__(256) fp16 g_wo [Lc * Dc * Dc];
__device__ __align__(256) fp16 g_w1 [Lc * Fc * Dc];
__device__ __align__(256) fp16 g_w2 [Lc * Dc * Fc];
__device__ __align__(256) fp16 g_we [Dc * OBSc];

// --------------------------- PTX helpers -----------------------------------
__device__ __forceinline__ uint32_t smem_u32(const void* p) {
    uint32_t a;
    asm("{ .reg .u64 t; cvta.to.shared.u64 t, %1; cvt.u32.u64 %0, t; }"
        : "=r"(a) : "l"(p));
    return a;
}

#define CP_ASYNC16(s, g) \
    asm volatile("cp.async.ca.shared.global [%0], [%1], 16;" :: "r"(s), "l"(g))
#define CP_COMMIT() asm volatile("cp.async.commit_group;" ::: "memory")
#define CP_WAIT0()  asm volatile("cp.async.wait_group 0;" ::: "memory")

#define LDSM4(r, a) \
    asm volatile("ldmatrix.sync.aligned.m8n8.x4.shared.b16 {%0,%1,%2,%3}, [%4];" \
        : "=r"((r)[0]), "=r"((r)[1]), "=r"((r)[2]), "=r"((r)[3]) : "r"(a))

#define MMA16816(d, a, b0, b1) \
    asm volatile("mma.sync.aligned.m16n8k16.row.col.f32.f16.f16.f32 " \
        "{%0,%1,%2,%3},{%4,%5,%6,%7},{%8,%9},{%0,%1,%2,%3};" \
        : "+f"((d)[0]), "+f"((d)[1]), "+f"((d)[2]), "+f"((d)[3]) \
        : "r"((a)[0]), "r"((a)[1]), "r"((a)[2]), "r"((a)[3]), "r"(b0), "r"(b1))

// ---------------------------------------------------------------------------
// fp16 GEMM: C[M,N] = A[M,K] @ W^T + bias, W pre-swizzled in B-frag layout:
//   uint4 index = (ntPair * (K/16) + kt) * 32 + lane.
// Block 128x128 (grid.x = m-blocks, grid.y = n-blocks), 8 warps 64x32,
// A: BK=128 chunks, 2-stage double buffer, one barrier per chunk.
// smem row stride 272 B (128 halves + pad) -> conflict-free ldmatrix.
// ---------------------------------------------------------------------------
#define GROW   272
#define GARR   (128 * GROW)       // 34816 B per stage
#define NSTAGE 2
#define GSMEM  (NSTAGE * GARR)    // 69632 B

__global__ __launch_bounds__(256, 2)
void gemm_mma(const fp16* __restrict__ A, const fp16* __restrict__ W,
              const float* __restrict__ bias,
              float* __restrict__ Cf, fp16* __restrict__ Ch,
              int M, int N, int K, int ldc, int relu, int rowmap)
{
    extern __shared__ char smem[];
    const uint32_t sbase = smem_u32(smem);
    const int tid  = threadIdx.x;
    const int wid  = tid >> 5;
    const int lane = tid & 31;
    const int m0 = blockIdx.x * 128;
    const int n0 = blockIdx.y * 128;
    const int nch = K >> 7;
    const int ktiles = K >> 4;

    const int wm = wid >> 2;          // 0..1
    const int wn = wid & 3;           // 0..3
    const uint4* __restrict__ Wq = (const uint4*)W;
    const size_t ntp0 = (size_t)((n0 >> 4) + wn * 2);

    float acc[4][4][4];
#pragma unroll
    for (int a = 0; a < 4; a++)
#pragma unroll
        for (int b = 0; b < 4; b++)
#pragma unroll
            for (int c = 0; c < 4; c++) acc[a][b][c] = 0.f;

    auto load_chunk = [&](int c) {
        const int s = c & 1;
        const size_t kb = (size_t)c * 128;
        const uint32_t sA = sbase + s * GARR;
#pragma unroll
        for (int it = 0; it < 8; it++) {
            int i = tid + it * 256;            // 0..2047
            int row = i >> 4;
            int c8  = (i & 15) * 8;
            int gr = min(m0 + row, M - 1);
            CP_ASYNC16(sA + row * GROW + (i & 15) * 16,
                       (const char*)(A + (size_t)gr * K + kb + c8));
        }
        CP_COMMIT();
    };

    load_chunk(0);

    for (int c = 0; c < nch; c++) {
        const int s = c & 1;
        CP_WAIT0();          // all issued groups retired -> chunk c resident
        __syncthreads();     // all threads past compute(c-1); c data visible

        // prefetch c+1 into the other stage (last read in compute(c-1))
        if (c + 1 < nch) load_chunk(c + 1);

        const uint32_t sA = sbase + s * GARR;

#pragma unroll 4
        for (int ks = 0; ks < 8; ks++) {
            const int kt = c * 8 + ks;
            uint4 bf0 = Wq[(ntp0       * ktiles + kt) * 32 + lane];
            uint4 bf1 = Wq[((ntp0 + 1) * ktiles + kt) * 32 + lane];
            uint32_t af[4][4];
            {
                const int r  = lane & 15;
                const int kh = (lane >> 4) * 8;
                const uint32_t kofs = (ks * 16 + kh) * 2;
#pragma unroll
                for (int mi = 0; mi < 4; mi++)
                    LDSM4(af[mi], sA + (wm * 64 + mi * 16 + r) * GROW + kofs);
            }
#pragma unroll
            for (int mi = 0; mi < 4; mi++) {
                MMA16816(acc[mi][0], af[mi], bf0.x, bf0.y);
                MMA16816(acc[mi][1], af[mi], bf0.z, bf0.w);
                MMA16816(acc[mi][2], af[mi], bf1.x, bf1.y);
                MMA16816(acc[mi][3], af[mi], bf1.z, bf1.w);
            }
        }
    }

    // ---- epilogue ----
    const int rq = lane >> 2;
    const int cq = (lane & 3) * 2;
#pragma unroll
    for (int mi = 0; mi < 4; mi++) {
#pragma unroll
        for (int half = 0; half < 2; half++) {
            int rr = m0 + wm * 64 + mi * 16 + rq + half * 8;
            if (rr >= M) continue;
            size_t orow = rowmap ? (size_t)(rr + rr / Sc + 1) : (size_t)rr;
#pragma unroll
            for (int nj = 0; nj < 4; nj++) {
                int cc = n0 + wn * 32 + nj * 8 + cq;
                float v0 = acc[mi][nj][half * 2 + 0] + bias[cc];
                float v1 = acc[mi][nj][half * 2 + 1] + bias[cc + 1];
                if (relu) { v0 = fmaxf(v0, 0.f); v1 = fmaxf(v1, 0.f); }
                if (Cf)
                    *(float2*)(Cf + orow * (size_t)ldc + cc) = make_float2(v0, v1);
                if (Ch) {
                    __half2 hp = __floats2half2_rn(v0, v1);
                    *(__half2*)(Ch + orow * (size_t)ldc + cc) = hp;
                }
            }
        }
    }
}

// ----- batched weight transpose + fp16 + B-fragment swizzle ----------------
struct WJob { const float* src; fp16* dst; int K; int N; };
struct WJobs { WJob j[25]; };

__global__ void wconv_all(WJobs jobs)
{
    WJob jb = jobs.j[blockIdx.z];
    int nbx = jb.N >> 5;
    int nb  = nbx * (jb.K >> 5);
    int bid = blockIdx.x;
    if (bid >= nb) return;
    int x = (bid % nbx) * 32;
    int y = (bid / nbx) * 32;

    __shared__ float t[32][33];
#pragma unroll
    for (int r = 0; r < 4; r++) {
        int row = y + threadIdx.y + r * 8;
        t[threadIdx.y + r * 8][threadIdx.x] = jb.src[(size_t)row * jb.N + x + threadIdx.x];
    }
    __syncthreads();
    int ktiles = jb.K >> 4;
#pragma unroll
    for (int r = 0; r < 4; r++) {
        int n = x + threadIdx.y + r * 8;
        int k = y + threadIdx.x;
        float v = t[threadIdx.x][threadIdx.y + r * 8];
        int k0 = k & 15;
        int lane = ((n & 7) << 2) | ((k0 >> 1) & 3);
        int sub  = ((n >> 3) & 1) * 4 + ((k0 >= 8) ? 2 : 0) + (k0 & 1);
        size_t idx = (((size_t)(n >> 4) * ktiles + (k >> 4)) * 32 + lane) * 8 + sub;
        jb.dst[idx] = __float2half_rn(v);
    }
}

// ------------------ pack qkv biases: [L][3*D] ------------------------------
__global__ void bpack(const float* __restrict__ bq, const float* __restrict__ bk,
                      const float* __restrict__ bv, float* __restrict__ dst)
{
    int l = blockIdx.x;
    int i = threadIdx.x;
    dst[l * QS + i]          = bq[l * Dc + i];
    dst[l * QS + Dc + i]     = bk[l * Dc + i];
    dst[l * QS + 2 * Dc + i] = bv[l * Dc + i];
}

// --------------------- fp32 -> fp16 convert (flat) --------------------------
__global__ void fcvt(const float* __restrict__ src, fp16* __restrict__ dst, int n4)
{
    int i = blockIdx.x * 256 + threadIdx.x;
    if (i < n4) {
        float4 v = ((const float4*)src)[i];
        __half2 a = __floats2half2_rn(v.x, v.y);
        __half2 b = __floats2half2_rn(v.z, v.w);
        uint2 o;
        o.x = *(uint32_t*)&a;
        o.y = *(uint32_t*)&b;
        ((uint2*)dst)[i] = o;
    }
}

// --------------------- init: hidden-state row per batch -------------------
__global__ void init_h0(const float* __restrict__ hs, const void* __restrict__ resets,
                        float* __restrict__ x, fp16* __restrict__ xh)
{
    __shared__ int mode;
    int b = blockIdx.x;
    if (threadIdx.x == 0) {
        const unsigned int* w = (const unsigned int*)resets;
        bool allint = true, allflt = true;
        for (int i = 0; i < 16; i++) {
            unsigned int u = w[i];
            if (u != 0u && u != 1u) allint = false;
            if (u != 0u && u != 0x3F800000u) allflt = false;
        }
        mode = allint ? 0 : (allflt ? 2 : 1);
    }
    __syncthreads();
    bool rst;
    if (mode == 0)      rst = ((const int*)resets)[b] != 0;
    else if (mode == 2) rst = ((const float*)resets)[b] != 0.f;
    else                rst = ((const unsigned char*)resets)[b] != 0;

    float val = rst ? 0.f : hs[b * Dc + threadIdx.x];
    size_t o = (size_t)b * SP * Dc + threadIdx.x;
    x[o] = val;
    xh[o] = __float2half_rn(val);
}

// ------------------- FAVOR: kv = sum_s pk^T outer v, ksum ------------------
__global__ __launch_bounds__(256)
void favor_kv(const fp16* __restrict__ qkv, float* __restrict__ kv,
              float* __restrict__ ksum)
{
    int bh = blockIdx.x;
    int b = bh / Hc, h = bh % Hc;
    const fp16* kb = qkv + (size_t)b * SP * QS + Dc + h * HDc;
    const fp16* vb = qkv + (size_t)b * SP * QS + 2 * Dc + h * HDc;

    __shared__ float spk[8][HDc];
    __shared__ float sv [8][HDc];

    int tid = threadIdx.x;
    int tm = (tid >> 4) * 4;
    int td = (tid & 15) * 4;

    float acc[4][4];
#pragma unroll
    for (int i = 0; i < 4; i++)
#pragma unroll
        for (int j = 0; j < 4; j++) acc[i][j] = 0.f;
    float ks = 0.f;

    for (int s0 = 0; s0 < SP; s0 += 8) {
        int nch = min(8, SP - s0);
        for (int i = tid; i < nch * HDc; i += 256) {
            int ss = i >> 6, dd = i & 63;
            float kk = __half2float(kb[(size_t)(s0 + ss) * QS + dd]);
            spk[ss][dd] = fmaxf(kk, 0.f) + KEPS;
            sv[ss][dd]  = __half2float(vb[(size_t)(s0 + ss) * QS + dd]);
        }
        __syncthreads();
        for (int j = 0; j < nch; j++) {
            float pa[4], va[4];
#pragma unroll
            for (int i = 0; i < 4; i++) { pa[i] = spk[j][tm + i]; va[i] = sv[j][td + i]; }
#pragma unroll
            for (int i = 0; i < 4; i++)
#pragma unroll
                for (int l = 0; l < 4; l++)
                    acc[i][l] = fmaf(pa[i], va[l], acc[i][l]);
            if (tid < HDc) ks += spk[j][tid];
        }
        __syncthreads();
    }

    float* kvb = kv + (size_t)bh * HDc * HDc;
#pragma unroll
    for (int i = 0; i < 4; i++)
#pragma unroll
        for (int l = 0; l < 4; l++)
            kvb[(tm + i) * HDc + td + l] = acc[i][l];
    if (tid < HDc) ksum[bh * HDc + tid] = ks;
}

// ---------- FAVOR: num = pq @ kv, den; out -> fp16 --------------------------
__global__ __launch_bounds__(256)
void favor_num(const fp16* __restrict__ qkv, const float* __restrict__ kv,
               const float* __restrict__ ksum, fp16* __restrict__ ah)
{
    int bh = blockIdx.x;
    int b = bh / Hc, h = bh % Hc;
    int t0 = blockIdx.y * 16;

    __shared__ float skv[HDc][HDc];
    __shared__ float sks[HDc];
    __shared__ float spq[16][HDc];

    int tid = threadIdx.x;
    const float* kvb = kv + (size_t)bh * HDc * HDc;
    for (int i = tid; i < (HDc * HDc) / 4; i += 256)
        ((float4*)skv)[i] = ((const float4*)kvb)[i];
    if (tid < HDc) sks[tid] = ksum[bh * HDc + tid];
    for (int i = tid; i < 16 * HDc; i += 256) {
        int tt = i >> 6, dd = i & 63;
        int s = t0 + tt;
        float qv = 0.f;
        if (s < SP) qv = __half2float(qkv[((size_t)b * SP + s) * QS + h * HDc + dd]);
        spq[tt][dd] = fmaxf(qv, 0.f) + KEPS;
    }
    __syncthreads();

    int t = tid >> 4;
    int dq = (tid & 15) * 4;
    float a0 = 0.f, a1 = 0.f, a2 = 0.f, a3 = 0.f, den = 0.f;
#pragma unroll
    for (int m = 0; m < HDc; m++) {
        float pq = spq[t][m];
        den = fmaf(pq, sks[m], den);
        float4 kk = *(const float4*)&skv[m][dq];
        a0 = fmaf(pq, kk.x, a0);
        a1 = fmaf(pq, kk.y, a1);
        a2 = fmaf(pq, kk.z, a2);
        a3 = fmaf(pq, kk.w, a3);
    }
    int s = t0 + t;
    if (s < SP) {
        float inv = 1.f / den;
        __half2 p0 = __floats2half2_rn(a0 * inv, a1 * inv);
        __half2 p1 = __floats2half2_rn(a2 * inv, a3 * inv);
        size_t idx = ((size_t)b * SP + s) * Dc + h * HDc + dq;
        uint2 o;
        o.x = *(uint32_t*)&p0;
        o.y = *(uint32_t*)&p1;
        *(uint2*)(ah + idx) = o;
    }
}

// --------------- x = LayerNorm(a + x) * s + b  (+ fp16 out) ----------------
__global__ __launch_bounds__(128)
void add_ln(const float* __restrict__ a, float* __restrict__ x,
            fp16* __restrict__ xh,
            const float* __restrict__ s, const float* __restrict__ bb)
{
    size_t r = blockIdx.x;
    const float* ar = a + r * Dc;
    float* xr = x + r * Dc;
    int tid = threadIdx.x;

    float v[4];
    float sum = 0.f, sq = 0.f;
#pragma unroll
    for (int i = 0; i < 4; i++) {
        int c = tid + i * 128;
        v[i] = ar[c] + xr[c];
        sum += v[i];
        sq  = fmaf(v[i], v[i], sq);
    }
#pragma unroll
    for (int o = 16; o > 0; o >>= 1) {
        sum += __shfl_xor_sync(0xFFFFFFFFu, sum, o);
        sq  += __shfl_xor_sync(0xFFFFFFFFu, sq, o);
    }
    __shared__ float rs[4], rq[4];
    int w = tid >> 5;
    if ((tid & 31) == 0) { rs[w] = sum; rq[w] = sq; }
    __syncthreads();
    sum = rs[0] + rs[1] + rs[2] + rs[3];
    sq  = rq[0] + rq[1] + rq[2] + rq[3];
    float mean = sum * (1.f / Dc);
    float var  = sq * (1.f / Dc) - mean * mean;
    float inv  = rsqrtf(var + LNEPS);
#pragma unroll
    for (int i = 0; i < 4; i++) {
        int c = tid + i * 128;
        float o = (v[i] - mean) * inv * s[c] + bb[c];
        xr[c] = o;
        xh[r * Dc + c] = __float2half_rn(o);
    }
}

// ---- layer-3 compact variant: reads residual from xin (stride), compact out
__global__ __launch_bounds__(128)
void add_ln0(const float* __restrict__ a, const float* __restrict__ xin,
             size_t xin_stride, float* __restrict__ xout, fp16* __restrict__ xh,
             const float* __restrict__ s, const float* __restrict__ bb)
{
    int b = blockIdx.x;
    const float* ar = a + (size_t)b * Dc;
    const float* xr = xin + (size_t)b * xin_stride;
    int tid = threadIdx.x;

    float v[4];
    float sum = 0.f, sq = 0.f;
#pragma unroll
    for (int i = 0; i < 4; i++) {
        int c = tid + i * 128;
        v[i] = ar[c] + xr[c];
        sum += v[i];
        sq  = fmaf(v[i], v[i], sq);
    }
#pragma unroll
    for (int o = 16; o > 0; o >>= 1) {
        sum += __shfl_xor_sync(0xFFFFFFFFu, sum, o);
        sq  += __shfl_xor_sync(0xFFFFFFFFu, sq, o);
    }
    __shared__ float rs[4], rq[4];
    int w = tid >> 5;
    if ((tid & 31) == 0) { rs[w] = sum; rq[w] = sq; }
    __syncthreads();
    sum = rs[0] + rs[1] + rs[2] + rs[3];
    sq  = rq[0] + rq[1] + rq[2] + rq[3];
    float mean = sum * (1.f / Dc);
    float var  = sq * (1.f / Dc) - mean * mean;
    float inv  = rsqrtf(var + LNEPS);
#pragma unroll
    for (int i = 0; i < 4; i++) {
        int c = tid + i * 128;
        float o = (v[i] - mean) * inv * s[c] + bb[c];
        xout[(size_t)b * Dc + c] = o;
        xh[(size_t)b * Dc + c] = __float2half_rn(o);
    }
}

// ---- gather token-0 rows of xh into compact A buffer ----------------------
__global__ void gather_x0(const fp16* __restrict__ xh, fp16* __restrict__ xg0)
{
    int b = blockIdx.x;
    int i = threadIdx.x;
    ((uint32_t*)xg0)[b * (Dc / 2) + i] =
        ((const uint32_t*)(xh + (size_t)b * SP * Dc))[i];
}

// ---- layer-3: attention out for token 0 only --------------------------------
__global__ __launch_bounds__(64)
void favor_num0(const float* __restrict__ q0, const float* __restrict__ kv,
                const float* __restrict__ ksum, fp16* __restrict__ ah0)
{
    int bh = blockIdx.x;
    int b = bh / Hc, h = bh % Hc;
    int d = threadIdx.x;   // 0..63

    __shared__ float spq[HDc];
    __shared__ float sks[HDc];
    float qv = q0[(size_t)b * Dc + h * HDc + d];
    spq[d] = fmaxf(qv, 0.f) + KEPS;
    sks[d] = ksum[bh * HDc + d];
    __syncthreads();

    const float* kvb = kv + (size_t)bh * HDc * HDc;
    float num = 0.f, den = 0.f;
#pragma unroll 8
    for (int m = 0; m < HDc; m++) {
        float pq = spq[m];
        num = fmaf(pq, kvb[m * HDc + d], num);
        den = fmaf(pq, sks[m], den);
    }
    ah0[(size_t)b * Dc + h * HDc + d] = __float2half_rn(num / den);
}

// ---------------- head: copy h_out and compute q_vals ----------------------
__global__ __launch_bounds__(512)
void head_kernel(const float* __restrict__ x0, const float* __restrict__ Wqp,
                 const float* __restrict__ bqp, float* __restrict__ out)
{
    int b = blockIdx.x;
    int tid = threadIdx.x;
    const float* hr = x0 + (size_t)b * Dc;
    out[b * Dc + tid] = hr[tid];

    int w = tid >> 5, lane = tid & 31;
    float sum = 0.f;
    for (int i = lane; i < Dc; i += 32)
        sum = fmaf(hr[i], Wqp[i * Ac + w], sum);
#pragma unroll
    for (int o = 16; o > 0; o >>= 1)
        sum += __shfl_xor_sync(0xFFFFFFFFu, sum, o);
    if (lane == 0) out[Bc * Dc + b * Ac + w] = sum + bqp[w];
}

// ---------------------------------------------------------------------------
extern "C" void kernel_launch(void* const* d_in, const int* in_sizes, int n_in,
                              void* d_out, int out_size)
{
    const float* hs    = (const float*)d_in[0];
    const float* ins   = (const float*)d_in[1];
    const void*  rsts  = d_in[2];
    const float* W_emb = (const float*)d_in[3];
    const float* b_emb = (const float*)d_in[4];
    const float* Wq    = (const float*)d_in[5];
    const float* bq    = (const float*)d_in[6];
    const float* Wk    = (const float*)d_in[7];
    const float* bk    = (const float*)d_in[8];
    const float* Wv    = (const float*)d_in[9];
    const float* bv    = (const float*)d_in[10];
    const float* Wo    = (const float*)d_in[11];
    const float* bo    = (const float*)d_in[12];
    const float* ln1s  = (const float*)d_in[13];
    const float* ln1b  = (const float*)d_in[14];
    const float* ln2s  = (const float*)d_in[15];
    const float* ln2b  = (const float*)d_in[16];
    const float* W1    = (const float*)d_in[17];
    const float* b1    = (const float*)d_in[18];
    const float* W2    = (const float*)d_in[19];
    const float* b2    = (const float*)d_in[20];
    const float* Wqp   = (const float*)d_in[21];
    const float* bqp   = (const float*)d_in[22];
    float* out = (float*)d_out;

    cudaFuncSetAttribute(gemm_mma, cudaFuncAttributeMaxDynamicSharedMemorySize, GSMEM);

    float *x, *tmp, *kv, *ks, *bqkv, *x0, *q0, *tmp0;
    fp16 *xh, *qkv, *ah, *fh, *ih, *xh0, *xg0, *ah0, *fh0;
    fp16 *wqkv, *wo, *w1, *w2, *we;
    cudaGetSymbolAddress((void**)&x,    g_x);
    cudaGetSymbolAddress((void**)&xh,   g_xh);
    cudaGetSymbolAddress((void**)&qkv,  g_qkv);
    cudaGetSymbolAddress((void**)&ah,   g_ah);
    cudaGetSymbolAddress((void**)&tmp,  g_tmp);
    cudaGetSymbolAddress((void**)&fh,   g_fh);
    cudaGetSymbolAddress((void**)&kv,   g_kv);
    cudaGetSymbolAddress((void**)&ks,   g_ks);
    cudaGetSymbolAddress((void**)&ih,   g_ih);
    cudaGetSymbolAddress((void**)&x0,   g_x0);
    cudaGetSymbolAddress((void**)&xh0,  g_xh0);
    cudaGetSymbolAddress((void**)&xg0,  g_xg0);
    cudaGetSymbolAddress((void**)&q0,   g_q0);
    cudaGetSymbolAddress((void**)&ah0,  g_ah0);
    cudaGetSymbolAddress((void**)&tmp0, g_tmp0);
    cudaGetSymbolAddress((void**)&fh0,  g_fh0);
    cudaGetSymbolAddress((void**)&bqkv, g_bqkv);
    cudaGetSymbolAddress((void**)&wqkv, g_wqkv);
    cudaGetSymbolAddress((void**)&wo,   g_wo);
    cudaGetSymbolAddress((void**)&w1,   g_w1);
    cudaGetSymbolAddress((void**)&w2,   g_w2);
    cudaGetSymbolAddress((void**)&we,   g_we);

    // ins convert
    {
        int n4 = (Bc * Sc * OBSc) / 4;
        fcvt<<<(n4 + 255) / 256, 256>>>(ins, ih, n4);
    }
    // all weight conversions (transpose + fp16 + B-fragment swizzle)
    {
        WJobs jobs;
        int nj = 0;
        jobs.j[nj++] = { W_emb, we, OBSc, Dc };
        for (int l = 0; l < Lc; l++) {
            size_t od = (size_t)l * Dc * Dc;
            size_t oq = (size_t)l * QS * Dc;
            size_t o1 = (size_t)l * Fc * Dc;
            size_t o2 = (size_t)l * Dc * Fc;
            jobs.j[nj++] = { Wq + od, wqkv + oq,                       Dc, Dc };
            jobs.j[nj++] = { Wk + od, wqkv + oq + (size_t)Dc * Dc,     Dc, Dc };
            jobs.j[nj++] = { Wv + od, wqkv + oq + (size_t)2 * Dc * Dc, Dc, Dc };
            jobs.j[nj++] = { Wo + od, wo + od, Dc, Dc };
            jobs.j[nj++] = { W1 + o1, w1 + o1, Dc, Fc };
            jobs.j[nj++] = { W2 + o2, w2 + o2, Fc, Dc };
        }
        wconv_all<<<dim3(1024, 1, 25), dim3(32, 8)>>>(jobs);
    }
    // pack qkv biases
    bpack<<<Lc, Dc>>>(bq, bk, bv, bqkv);

    // embedding GEMM (grid: x=m-blocks, y=n-blocks)
    gemm_mma<<<dim3((Bc * Sc) / 128, Dc / 128), 256, GSMEM>>>(
        ih, we, b_emb, x, xh, Bc * Sc, Dc, OBSc, Dc, 0, 1);

    // hidden-state rows
    init_h0<<<Bc, Dc>>>(hs, rsts, x, xh);

    const int MB = (Tc + 127) / 128;              // 257 m-blocks
    const dim3 gQKV(MB, QS / 128);                // (257, 12)
    const dim3 gKV (MB, 1024 / 128);              // (257, 8)
    const dim3 gD  (MB, Dc / 128);                // (257, 4)
    const dim3 gF  (MB, Fc / 128);                // (257, 16)

    // ---- layers 0..2: full ----
    for (int l = 0; l < Lc - 1; l++) {
        size_t od = (size_t)l * Dc * Dc;
        size_t oq = (size_t)l * QS * Dc;
        size_t o1 = (size_t)l * Fc * Dc;
        size_t o2 = (size_t)l * Dc * Fc;

        gemm_mma<<<gQKV, 256, GSMEM>>>(xh, wqkv + oq, bqkv + l * QS,
                                       0, qkv, Tc, QS, Dc, QS, 0, 0);

        favor_kv<<<Bc * Hc, 256>>>(qkv, kv, ks);
        favor_num<<<dim3(Bc * Hc, (SP + 15) / 16), 256>>>(qkv, kv, ks, ah);

        gemm_mma<<<gD, 256, GSMEM>>>(ah, wo + od, bo + l*Dc, tmp, 0, Tc, Dc, Dc, Dc, 0, 0);
        add_ln<<<Tc, 128>>>(tmp, x, xh, ln1s + l*Dc, ln1b + l*Dc);

        gemm_mma<<<gF, 256, GSMEM>>>(xh, w1 + o1, b1 + l*Fc, 0, fh, Tc, Fc, Dc, Fc, 1, 0);
        gemm_mma<<<gD, 256, GSMEM>>>(fh, w2 + o2, b2 + l*Dc, tmp, 0, Tc, Dc, Fc, Dc, 0, 0);
        add_ln<<<Tc, 128>>>(tmp, x, xh, ln2s + l*Dc, ln2b + l*Dc);
    }

    // ---- layer 3: only token-0 rows beyond the KV projection ----
    {
        const int l = Lc - 1;
        size_t od = (size_t)l * Dc * Dc;
        size_t oq = (size_t)l * QS * Dc;
        size_t o1 = (size_t)l * Fc * Dc;
        size_t o2 = (size_t)l * Dc * Fc;

        // K,V for all tokens (n-slice of packed QKV weights)
        gemm_mma<<<gKV, 256, GSMEM>>>(xh, wqkv + oq + (size_t)Dc * Dc,
                                      bqkv + l * QS + Dc,
                                      0, qkv + Dc, Tc, 1024, Dc, QS, 0, 0);
        // Q for the 64 token-0 rows: gather + small GEMM
        gather_x0<<<Bc, 256>>>(xh, xg0);
        gemm_mma<<<dim3(1, Dc / 128), 256, GSMEM>>>(
            xg0, wqkv + oq, bqkv + l * QS, q0, 0, Bc, Dc, Dc, Dc, 0, 0);

        favor_kv<<<Bc * Hc, 256>>>(qkv, kv, ks);
        favor_num0<<<Bc * Hc, 64>>>(q0, kv, ks, ah0);

        // AO on 64 rows
        gemm_mma<<<dim3(1, Dc / 128), 256, GSMEM>>>(
            ah0, wo + od, bo + l*Dc, tmp0, 0, Bc, Dc, Dc, Dc, 0, 0);
        add_ln0<<<Bc, 128>>>(tmp0, x, (size_t)SP * Dc, x0, xh0,
                             ln1s + l*Dc, ln1b + l*Dc);

        // FFN on 64 rows
        gemm_mma<<<dim3(1, Fc / 128), 256, GSMEM>>>(
            xh0, w1 + o1, b1 + l*Fc, 0, fh0, Bc, Fc, Dc, Fc, 1, 0);
        gemm_mma<<<dim3(1, Dc / 128), 256, GSMEM>>>(
            fh0, w2 + o2, b2 + l*Dc, tmp0, 0, Bc, Dc, Fc, Dc, 0, 0);
        add_ln0<<<Bc, 128>>>(tmp0, x0, (size_t)Dc, x0, xh0,
                             ln2s + l*Dc, ln2b + l*Dc);
    }

    head_kernel<<<Bc, Dc>>>(x0, Wqp, bqp, out);
}

// round 14
// speedup vs baseline: 1.1564x; 1.0644x over previous
#include <cuda_runtime.h>
#include <cuda_fp16.h>
#include <cstdint>

// ---------------------------------------------------------------------------
// TransformerAgent: 4-layer FAVOR+ transformer.
// GEMMs: fp16 mma.sync; A via cp.async+ldmatrix (BK=64, 3-stage), B weights
// pre-swizzled into mma fragment layout fed by LDG.128. 128x128 tile,
// 64x32 warp tile, 2 CTAs/SM. FAVOR: kv 16-row chunks, num 64 tokens/block.
// Layer 3: token-0 rows only.
// ---------------------------------------------------------------------------

#define Bc 64
#define Sc 512
#define SP 513
#define Dc 512
#define Hc 8
#define HDc 64
#define Fc 2048
#define Lc 4
#define Ac 16
#define OBSc 128
#define Tc (Bc * SP)          // 32832 tokens
#define QS (3 * Dc)           // fused qkv row stride = 1536

#define KEPS 1e-3f
#define LNEPS 1e-6f

typedef __half fp16;

// ------------------------- scratch (static device) ------------------------
__device__ float g_x  [Tc * Dc];
__device__ fp16  g_xh [Tc * Dc];
__device__ fp16  g_qkv[Tc * QS];
__device__ fp16  g_ah [Tc * Dc];
__device__ float g_tmp[Tc * Dc];
__device__ fp16  g_fh [Tc * Fc];
__device__ float g_kv [Bc * Hc * HDc * HDc];
__device__ float g_ks [Bc * Hc * HDc];
__device__ fp16  g_ih [Bc * Sc * OBSc];
// layer-3 compact (token-0 rows only)
__device__ float g_x0  [Bc * Dc];
__device__ fp16  g_xh0 [Bc * Dc];
__device__ fp16  g_xg0 [Bc * Dc];
__device__ float g_q0  [Bc * Dc];
__device__ fp16  g_ah0 [Bc * Dc];
__device__ float g_tmp0[Bc * Dc];
__device__ fp16  g_fh0 [Bc * Fc];
// weights in mma B-fragment layout (ntPair-major), fp16
__device__ __align__(256) fp16 g_wqkv[Lc * QS * Dc];
__device__ float g_bqkv[Lc * QS];
__device__ __align__(256) fp16 g_wo [Lc * Dc * Dc];
__device__ __align__(256) fp16 g_w1 [Lc * Fc * Dc];
__device__ __align__(256) fp16 g_w2 [Lc * Dc * Fc];
__device__ __align__(256) fp16 g_we [Dc * OBSc];

// --------------------------- PTX helpers -----------------------------------
__device__ __forceinline__ uint32_t smem_u32(const void* p) {
    uint32_t a;
    asm("{ .reg .u64 t; cvta.to.shared.u64 t, %1; cvt.u32.u64 %0, t; }"
        : "=r"(a) : "l"(p));
    return a;
}

#define CP_ASYNC16(s, g) \
    asm volatile("cp.async.ca.shared.global [%0], [%1], 16;" :: "r"(s), "l"(g))
#define CP_COMMIT() asm volatile("cp.async.commit_group;" ::: "memory")
#define CP_WAIT1()  asm volatile("cp.async.wait_group 1;" ::: "memory")

#define LDSM4(r, a) \
    asm volatile("ldmatrix.sync.aligned.m8n8.x4.shared.b16 {%0,%1,%2,%3}, [%4];" \
        : "=r"((r)[0]), "=r"((r)[1]), "=r"((r)[2]), "=r"((r)[3]) : "r"(a))

#define MMA16816(d, a, b0, b1) \
    asm volatile("mma.sync.aligned.m16n8k16.row.col.f32.f16.f16.f32 " \
        "{%0,%1,%2,%3},{%4,%5,%6,%7},{%8,%9},{%0,%1,%2,%3};" \
        : "+f"((d)[0]), "+f"((d)[1]), "+f"((d)[2]), "+f"((d)[3]) \
        : "r"((a)[0]), "r"((a)[1]), "r"((a)[2]), "r"((a)[3]), "r"(b0), "r"(b1))

// ---------------------------------------------------------------------------
// fp16 GEMM (round-11 config): C[M,N] = A[M,K] @ W^T + bias.
// W pre-swizzled: uint4 index = (ntPair * (K/16) + kt) * 32 + lane.
// Block 128x128 (grid.x = m-blocks, grid.y = n-blocks), 8 warps 64x32,
// A: BK=64 chunks, 3-stage cp.async + ldmatrix, one barrier per chunk.
// ---------------------------------------------------------------------------
#define GROW   144
#define GARR   (128 * GROW)       // 18432 B per stage
#define NSTAGE 3
#define GSMEM  (NSTAGE * GARR)    // 55296 B

__global__ __launch_bounds__(256, 2)
void gemm_mma(const fp16* __restrict__ A, const fp16* __restrict__ W,
              const float* __restrict__ bias,
              float* __restrict__ Cf, fp16* __restrict__ Ch,
              int M, int N, int K, int ldc, int relu, int rowmap)
{
    extern __shared__ char smem[];
    const uint32_t sbase = smem_u32(smem);
    const int tid  = threadIdx.x;
    const int wid  = tid >> 5;
    const int lane = tid & 31;
    const int m0 = blockIdx.x * 128;
    const int n0 = blockIdx.y * 128;
    const int nch = K >> 6;
    const int ktiles = K >> 4;

    const int wm = wid >> 2;          // 0..1
    const int wn = wid & 3;           // 0..3
    const uint4* __restrict__ Wq = (const uint4*)W;
    const size_t ntp0 = (size_t)((n0 >> 4) + wn * 2);

    float acc[4][4][4];
#pragma unroll
    for (int a = 0; a < 4; a++)
#pragma unroll
        for (int b = 0; b < 4; b++)
#pragma unroll
            for (int c = 0; c < 4; c++) acc[a][b][c] = 0.f;

    auto load_chunk = [&](int c) {
        const int s = c % NSTAGE;
        const size_t kb = (size_t)c * 64;
        const uint32_t sA = sbase + s * GARR;
#pragma unroll
        for (int it = 0; it < 4; it++) {
            int i = tid + it * 256;            // 0..1023
            int row = i >> 3;
            int c8  = (i & 7) * 8;
            int gr = min(m0 + row, M - 1);
            CP_ASYNC16(sA + row * GROW + (i & 7) * 16,
                       (const char*)(A + (size_t)gr * K + kb + c8));
        }
        CP_COMMIT();
    };

    load_chunk(0);
    if (nch > 1) load_chunk(1); else CP_COMMIT();

    for (int c = 0; c < nch; c++) {
        const int s = c % NSTAGE;
        CP_WAIT1();
        __syncthreads();

        if (c + 2 < nch) load_chunk(c + 2); else CP_COMMIT();

        const uint32_t sA = sbase + s * GARR;

#pragma unroll
        for (int ks = 0; ks < 4; ks++) {
            const int kt = c * 4 + ks;
            uint4 bf0 = Wq[(ntp0       * ktiles + kt) * 32 + lane];
            uint4 bf1 = Wq[((ntp0 + 1) * ktiles + kt) * 32 + lane];
            uint32_t af[4][4];
            {
                const int r  = lane & 15;
                const int kh = (lane >> 4) * 8;
                const uint32_t kofs = (ks * 16 + kh) * 2;
#pragma unroll
                for (int mi = 0; mi < 4; mi++)
                    LDSM4(af[mi], sA + (wm * 64 + mi * 16 + r) * GROW + kofs);
            }
#pragma unroll
            for (int mi = 0; mi < 4; mi++) {
                MMA16816(acc[mi][0], af[mi], bf0.x, bf0.y);
                MMA16816(acc[mi][1], af[mi], bf0.z, bf0.w);
                MMA16816(acc[mi][2], af[mi], bf1.x, bf1.y);
                MMA16816(acc[mi][3], af[mi], bf1.z, bf1.w);
            }
        }
    }

    // ---- epilogue ----
    const int rq = lane >> 2;
    const int cq = (lane & 3) * 2;
#pragma unroll
    for (int mi = 0; mi < 4; mi++) {
#pragma unroll
        for (int half = 0; half < 2; half++) {
            int rr = m0 + wm * 64 + mi * 16 + rq + half * 8;
            if (rr >= M) continue;
            size_t orow = rowmap ? (size_t)(rr + rr / Sc + 1) : (size_t)rr;
#pragma unroll
            for (int nj = 0; nj < 4; nj++) {
                int cc = n0 + wn * 32 + nj * 8 + cq;
                float v0 = acc[mi][nj][half * 2 + 0] + bias[cc];
                float v1 = acc[mi][nj][half * 2 + 1] + bias[cc + 1];
                if (relu) { v0 = fmaxf(v0, 0.f); v1 = fmaxf(v1, 0.f); }
                if (Cf)
                    *(float2*)(Cf + orow * (size_t)ldc + cc) = make_float2(v0, v1);
                if (Ch) {
                    __half2 hp = __floats2half2_rn(v0, v1);
                    *(__half2*)(Ch + orow * (size_t)ldc + cc) = hp;
                }
            }
        }
    }
}

// ----- batched weight transpose + fp16 + B-fragment swizzle ----------------
struct WJob { const float* src; fp16* dst; int K; int N; };
struct WJobs { WJob j[25]; };

__global__ void wconv_all(WJobs jobs)
{
    WJob jb = jobs.j[blockIdx.z];
    int nbx = jb.N >> 5;
    int nb  = nbx * (jb.K >> 5);
    int bid = blockIdx.x;
    if (bid >= nb) return;
    int x = (bid % nbx) * 32;
    int y = (bid / nbx) * 32;

    __shared__ float t[32][33];
#pragma unroll
    for (int r = 0; r < 4; r++) {
        int row = y + threadIdx.y + r * 8;
        t[threadIdx.y + r * 8][threadIdx.x] = jb.src[(size_t)row * jb.N + x + threadIdx.x];
    }
    __syncthreads();
    int ktiles = jb.K >> 4;
#pragma unroll
    for (int r = 0; r < 4; r++) {
        int n = x + threadIdx.y + r * 8;
        int k = y + threadIdx.x;
        float v = t[threadIdx.x][threadIdx.y + r * 8];
        int k0 = k & 15;
        int lane = ((n & 7) << 2) | ((k0 >> 1) & 3);
        int sub  = ((n >> 3) & 1) * 4 + ((k0 >= 8) ? 2 : 0) + (k0 & 1);
        size_t idx = (((size_t)(n >> 4) * ktiles + (k >> 4)) * 32 + lane) * 8 + sub;
        jb.dst[idx] = __float2half_rn(v);
    }
}

// ------------------ pack qkv biases: [L][3*D] ------------------------------
__global__ void bpack(const float* __restrict__ bq, const float* __restrict__ bk,
                      const float* __restrict__ bv, float* __restrict__ dst)
{
    int l = blockIdx.x;
    int i = threadIdx.x;
    dst[l * QS + i]          = bq[l * Dc + i];
    dst[l * QS + Dc + i]     = bk[l * Dc + i];
    dst[l * QS + 2 * Dc + i] = bv[l * Dc + i];
}

// --------------------- fp32 -> fp16 convert (flat) --------------------------
__global__ void fcvt(const float* __restrict__ src, fp16* __restrict__ dst, int n4)
{
    int i = blockIdx.x * 256 + threadIdx.x;
    if (i < n4) {
        float4 v = ((const float4*)src)[i];
        __half2 a = __floats2half2_rn(v.x, v.y);
        __half2 b = __floats2half2_rn(v.z, v.w);
        uint2 o;
        o.x = *(uint32_t*)&a;
        o.y = *(uint32_t*)&b;
        ((uint2*)dst)[i] = o;
    }
}

// --------------------- init: hidden-state row per batch -------------------
__global__ void init_h0(const float* __restrict__ hs, const void* __restrict__ resets,
                        float* __restrict__ x, fp16* __restrict__ xh)
{
    __shared__ int mode;
    int b = blockIdx.x;
    if (threadIdx.x == 0) {
        const unsigned int* w = (const unsigned int*)resets;
        bool allint = true, allflt = true;
        for (int i = 0; i < 16; i++) {
            unsigned int u = w[i];
            if (u != 0u && u != 1u) allint = false;
            if (u != 0u && u != 0x3F800000u) allflt = false;
        }
        mode = allint ? 0 : (allflt ? 2 : 1);
    }
    __syncthreads();
    bool rst;
    if (mode == 0)      rst = ((const int*)resets)[b] != 0;
    else if (mode == 2) rst = ((const float*)resets)[b] != 0.f;
    else                rst = ((const unsigned char*)resets)[b] != 0;

    float val = rst ? 0.f : hs[b * Dc + threadIdx.x];
    size_t o = (size_t)b * SP * Dc + threadIdx.x;
    x[o] = val;
    xh[o] = __float2half_rn(val);
}

// ------------------- FAVOR: kv = sum_s pk^T outer v, ksum ------------------
// 16-row chunks: half the barriers of the 8-row version; same math order.
__global__ __launch_bounds__(256)
void favor_kv(const fp16* __restrict__ qkv, float* __restrict__ kv,
              float* __restrict__ ksum)
{
    int bh = blockIdx.x;
    int b = bh / Hc, h = bh % Hc;
    const fp16* kb = qkv + (size_t)b * SP * QS + Dc + h * HDc;
    const fp16* vb = qkv + (size_t)b * SP * QS + 2 * Dc + h * HDc;

    __shared__ float spk[16][HDc];
    __shared__ float sv [16][HDc];

    int tid = threadIdx.x;
    int tm = (tid >> 4) * 4;
    int td = (tid & 15) * 4;

    float acc[4][4];
#pragma unroll
    for (int i = 0; i < 4; i++)
#pragma unroll
        for (int j = 0; j < 4; j++) acc[i][j] = 0.f;
    float ks = 0.f;

    for (int s0 = 0; s0 < SP; s0 += 16) {
        int nch = min(16, SP - s0);
        for (int i = tid; i < nch * HDc; i += 256) {
            int ss = i >> 6, dd = i & 63;
            float kk = __half2float(kb[(size_t)(s0 + ss) * QS + dd]);
            spk[ss][dd] = fmaxf(kk, 0.f) + KEPS;
            sv[ss][dd]  = __half2float(vb[(size_t)(s0 + ss) * QS + dd]);
        }
        __syncthreads();
        for (int j = 0; j < nch; j++) {
            float pa[4], va[4];
#pragma unroll
            for (int i = 0; i < 4; i++) { pa[i] = spk[j][tm + i]; va[i] = sv[j][td + i]; }
#pragma unroll
            for (int i = 0; i < 4; i++)
#pragma unroll
                for (int l = 0; l < 4; l++)
                    acc[i][l] = fmaf(pa[i], va[l], acc[i][l]);
            if (tid < HDc) ks += spk[j][tid];
        }
        __syncthreads();
    }

    float* kvb = kv + (size_t)bh * HDc * HDc;
#pragma unroll
    for (int i = 0; i < 4; i++)
#pragma unroll
        for (int l = 0; l < 4; l++)
            kvb[(tm + i) * HDc + td + l] = acc[i][l];
    if (tid < HDc) ksum[bh * HDc + tid] = ks;
}

// ---------- FAVOR: num = pq @ kv, den; 64 tokens/block; out -> fp16 ---------
// kv loaded into smem ONCE per block, reused for 4 passes of 16 tokens.
__global__ __launch_bounds__(256)
void favor_num(const fp16* __restrict__ qkv, const float* __restrict__ kv,
               const float* __restrict__ ksum, fp16* __restrict__ ah)
{
    int bh = blockIdx.x;
    int b = bh / Hc, h = bh % Hc;
    int tb = blockIdx.y * 64;

    __shared__ float skv[HDc][HDc];
    __shared__ float sks[HDc];
    __shared__ float spq[16][HDc];

    int tid = threadIdx.x;
    const float* kvb = kv + (size_t)bh * HDc * HDc;
    for (int i = tid; i < (HDc * HDc) / 4; i += 256)
        ((float4*)skv)[i] = ((const float4*)kvb)[i];
    if (tid < HDc) sks[tid] = ksum[bh * HDc + tid];
    __syncthreads();

    const int t = tid >> 4;
    const int dq = (tid & 15) * 4;

#pragma unroll 1
    for (int pass = 0; pass < 4; pass++) {
        int t0 = tb + pass * 16;
        if (t0 >= SP) break;
        for (int i = tid; i < 16 * HDc; i += 256) {
            int tt = i >> 6, dd = i & 63;
            int s = t0 + tt;
            float qv = 0.f;
            if (s < SP) qv = __half2float(qkv[((size_t)b * SP + s) * QS + h * HDc + dd]);
            spq[tt][dd] = fmaxf(qv, 0.f) + KEPS;
        }
        __syncthreads();

        float a0 = 0.f, a1 = 0.f, a2 = 0.f, a3 = 0.f, den = 0.f;
#pragma unroll
        for (int m = 0; m < HDc; m++) {
            float pq = spq[t][m];
            den = fmaf(pq, sks[m], den);
            float4 kk = *(const float4*)&skv[m][dq];
            a0 = fmaf(pq, kk.x, a0);
            a1 = fmaf(pq, kk.y, a1);
            a2 = fmaf(pq, kk.z, a2);
            a3 = fmaf(pq, kk.w, a3);
        }
        int s = t0 + t;
        if (s < SP) {
            float inv = 1.f / den;
            __half2 p0 = __floats2half2_rn(a0 * inv, a1 * inv);
            __half2 p1 = __floats2half2_rn(a2 * inv, a3 * inv);
            size_t idx = ((size_t)b * SP + s) * Dc + h * HDc + dq;
            uint2 o;
            o.x = *(uint32_t*)&p0;
            o.y = *(uint32_t*)&p1;
            *(uint2*)(ah + idx) = o;
        }
        __syncthreads();
    }
}

// --------------- x = LayerNorm(a + x) * s + b  (+ fp16 out) ----------------
__global__ __launch_bounds__(128)
void add_ln(const float* __restrict__ a, float* __restrict__ x,
            fp16* __restrict__ xh,
            const float* __restrict__ s, const float* __restrict__ bb)
{
    size_t r = blockIdx.x;
    const float* ar = a + r * Dc;
    float* xr = x + r * Dc;
    int tid = threadIdx.x;

    float v[4];
    float sum = 0.f, sq = 0.f;
#pragma unroll
    for (int i = 0; i < 4; i++) {
        int c = tid + i * 128;
        v[i] = ar[c] + xr[c];
        sum += v[i];
        sq  = fmaf(v[i], v[i], sq);
    }
#pragma unroll
    for (int o = 16; o > 0; o >>= 1) {
        sum += __shfl_xor_sync(0xFFFFFFFFu, sum, o);
        sq  += __shfl_xor_sync(0xFFFFFFFFu, sq, o);
    }
    __shared__ float rs[4], rq[4];
    int w = tid >> 5;
    if ((tid & 31) == 0) { rs[w] = sum; rq[w] = sq; }
    __syncthreads();
    sum = rs[0] + rs[1] + rs[2] + rs[3];
    sq  = rq[0] + rq[1] + rq[2] + rq[3];
    float mean = sum * (1.f / Dc);
    float var  = sq * (1.f / Dc) - mean * mean;
    float inv  = rsqrtf(var + LNEPS);
#pragma unroll
    for (int i = 0; i < 4; i++) {
        int c = tid + i * 128;
        float o = (v[i] - mean) * inv * s[c] + bb[c];
        xr[c] = o;
        xh[r * Dc + c] = __float2half_rn(o);
    }
}

// ---- layer-3 compact variant: reads residual from xin (stride), compact out
__global__ __launch_bounds__(128)
void add_ln0(const float* __restrict__ a, const float* __restrict__ xin,
             size_t xin_stride, float* __restrict__ xout, fp16* __restrict__ xh,
             const float* __restrict__ s, const float* __restrict__ bb)
{
    int b = blockIdx.x;
    const float* ar = a + (size_t)b * Dc;
    const float* xr = xin + (size_t)b * xin_stride;
    int tid = threadIdx.x;

    float v[4];
    float sum = 0.f, sq = 0.f;
#pragma unroll
    for (int i = 0; i < 4; i++) {
        int c = tid + i * 128;
        v[i] = ar[c] + xr[c];
        sum += v[i];
        sq  = fmaf(v[i], v[i], sq);
    }
#pragma unroll
    for (int o = 16; o > 0; o >>= 1) {
        sum += __shfl_xor_sync(0xFFFFFFFFu, sum, o);
        sq  += __shfl_xor_sync(0xFFFFFFFFu, sq, o);
    }
    __shared__ float rs[4], rq[4];
    int w = tid >> 5;
    if ((tid & 31) == 0) { rs[w] = sum; rq[w] = sq; }
    __syncthreads();
    sum = rs[0] + rs[1] + rs[2] + rs[3];
    sq  = rq[0] + rq[1] + rq[2] + rq[3];
    float mean = sum * (1.f / Dc);
    float var  = sq * (1.f / Dc) - mean * mean;
    float inv  = rsqrtf(var + LNEPS);
#pragma unroll
    for (int i = 0; i < 4; i++) {
        int c = tid + i * 128;
        float o = (v[i] - mean) * inv * s[c] + bb[c];
        xout[(size_t)b * Dc + c] = o;
        xh[(size_t)b * Dc + c] = __float2half_rn(o);
    }
}

// ---- gather token-0 rows of xh into compact A buffer ----------------------
__global__ void gather_x0(const fp16* __restrict__ xh, fp16* __restrict__ xg0)
{
    int b = blockIdx.x;
    int i = threadIdx.x;
    ((uint32_t*)xg0)[b * (Dc / 2) + i] =
        ((const uint32_t*)(xh + (size_t)b * SP * Dc))[i];
}

// ---- layer-3: attention out for token 0 only --------------------------------
__global__ __launch_bounds__(64)
void favor_num0(const float* __restrict__ q0, const float* __restrict__ kv,
                const float* __restrict__ ksum, fp16* __restrict__ ah0)
{
    int bh = blockIdx.x;
    int b = bh / Hc, h = bh % Hc;
    int d = threadIdx.x;   // 0..63

    __shared__ float spq[HDc];
    __shared__ float sks[HDc];
    float qv = q0[(size_t)b * Dc + h * HDc + d];
    spq[d] = fmaxf(qv, 0.f) + KEPS;
    sks[d] = ksum[bh * HDc + d];
    __syncthreads();

    const float* kvb = kv + (size_t)bh * HDc * HDc;
    float num = 0.f, den = 0.f;
#pragma unroll 8
    for (int m = 0; m < HDc; m++) {
        float pq = spq[m];
        num = fmaf(pq, kvb[m * HDc + d], num);
        den = fmaf(pq, sks[m], den);
    }
    ah0[(size_t)b * Dc + h * HDc + d] = __float2half_rn(num / den);
}

// ---------------- head: copy h_out and compute q_vals ----------------------
__global__ __launch_bounds__(512)
void head_kernel(const float* __restrict__ x0, const float* __restrict__ Wqp,
                 const float* __restrict__ bqp, float* __restrict__ out)
{
    int b = blockIdx.x;
    int tid = threadIdx.x;
    const float* hr = x0 + (size_t)b * Dc;
    out[b * Dc + tid] = hr[tid];

    int w = tid >> 5, lane = tid & 31;
    float sum = 0.f;
    for (int i = lane; i < Dc; i += 32)
        sum = fmaf(hr[i], Wqp[i * Ac + w], sum);
#pragma unroll
    for (int o = 16; o > 0; o >>= 1)
        sum += __shfl_xor_sync(0xFFFFFFFFu, sum, o);
    if (lane == 0) out[Bc * Dc + b * Ac + w] = sum + bqp[w];
}

// ---------------------------------------------------------------------------
extern "C" void kernel_launch(void* const* d_in, const int* in_sizes, int n_in,
                              void* d_out, int out_size)
{
    const float* hs    = (const float*)d_in[0];
    const float* ins   = (const float*)d_in[1];
    const void*  rsts  = d_in[2];
    const float* W_emb = (const float*)d_in[3];
    const float* b_emb = (const float*)d_in[4];
    const float* Wq    = (const float*)d_in[5];
    const float* bq    = (const float*)d_in[6];
    const float* Wk    = (const float*)d_in[7];
    const float* bk    = (const float*)d_in[8];
    const float* Wv    = (const float*)d_in[9];
    const float* bv    = (const float*)d_in[10];
    const float* Wo    = (const float*)d_in[11];
    const float* bo    = (const float*)d_in[12];
    const float* ln1s  = (const float*)d_in[13];
    const float* ln1b  = (const float*)d_in[14];
    const float* ln2s  = (const float*)d_in[15];
    const float* ln2b  = (const float*)d_in[16];
    const float* W1    = (const float*)d_in[17];
    const float* b1    = (const float*)d_in[18];
    const float* W2    = (const float*)d_in[19];
    const float* b2    = (const float*)d_in[20];
    const float* Wqp   = (const float*)d_in[21];
    const float* bqp   = (const float*)d_in[22];
    float* out = (float*)d_out;

    cudaFuncSetAttribute(gemm_mma, cudaFuncAttributeMaxDynamicSharedMemorySize, GSMEM);

    float *x, *tmp, *kv, *ks, *bqkv, *x0, *q0, *tmp0;
    fp16 *xh, *qkv, *ah, *fh, *ih, *xh0, *xg0, *ah0, *fh0;
    fp16 *wqkv, *wo, *w1, *w2, *we;
    cudaGetSymbolAddress((void**)&x,    g_x);
    cudaGetSymbolAddress((void**)&xh,   g_xh);
    cudaGetSymbolAddress((void**)&qkv,  g_qkv);
    cudaGetSymbolAddress((void**)&ah,   g_ah);
    cudaGetSymbolAddress((void**)&tmp,  g_tmp);
    cudaGetSymbolAddress((void**)&fh,   g_fh);
    cudaGetSymbolAddress((void**)&kv,   g_kv);
    cudaGetSymbolAddress((void**)&ks,   g_ks);
    cudaGetSymbolAddress((void**)&ih,   g_ih);
    cudaGetSymbolAddress((void**)&x0,   g_x0);
    cudaGetSymbolAddress((void**)&xh0,  g_xh0);
    cudaGetSymbolAddress((void**)&xg0,  g_xg0);
    cudaGetSymbolAddress((void**)&q0,   g_q0);
    cudaGetSymbolAddress((void**)&ah0,  g_ah0);
    cudaGetSymbolAddress((void**)&tmp0, g_tmp0);
    cudaGetSymbolAddress((void**)&fh0,  g_fh0);
    cudaGetSymbolAddress((void**)&bqkv, g_bqkv);
    cudaGetSymbolAddress((void**)&wqkv, g_wqkv);
    cudaGetSymbolAddress((void**)&wo,   g_wo);
    cudaGetSymbolAddress((void**)&w1,   g_w1);
    cudaGetSymbolAddress((void**)&w2,   g_w2);
    cudaGetSymbolAddress((void**)&we,   g_we);

    // ins convert
    {
        int n4 = (Bc * Sc * OBSc) / 4;
        fcvt<<<(n4 + 255) / 256, 256>>>(ins, ih, n4);
    }
    // all weight conversions (transpose + fp16 + B-fragment swizzle)
    {
        WJobs jobs;
        int nj = 0;
        jobs.j[nj++] = { W_emb, we, OBSc, Dc };
        for (int l = 0; l < Lc; l++) {
            size_t od = (size_t)l * Dc * Dc;
            size_t oq = (size_t)l * QS * Dc;
            size_t o1 = (size_t)l * Fc * Dc;
            size_t o2 = (size_t)l * Dc * Fc;
            jobs.j[nj++] = { Wq + od, wqkv + oq,                       Dc, Dc };
            jobs.j[nj++] = { Wk + od, wqkv + oq + (size_t)Dc * Dc,     Dc, Dc };
            jobs.j[nj++] = { Wv + od, wqkv + oq + (size_t)2 * Dc * Dc, Dc, Dc };
            jobs.j[nj++] = { Wo + od, wo + od, Dc, Dc };
            jobs.j[nj++] = { W1 + o1, w1 + o1, Dc, Fc };
            jobs.j[nj++] = { W2 + o2, w2 + o2, Fc, Dc };
        }
        wconv_all<<<dim3(1024, 1, 25), dim3(32, 8)>>>(jobs);
    }
    // pack qkv biases
    bpack<<<Lc, Dc>>>(bq, bk, bv, bqkv);

    // embedding GEMM (grid: x=m-blocks, y=n-blocks)
    gemm_mma<<<dim3((Bc * Sc) / 128, Dc / 128), 256, GSMEM>>>(
        ih, we, b_emb, x, xh, Bc * Sc, Dc, OBSc, Dc, 0, 1);

    // hidden-state rows
    init_h0<<<Bc, Dc>>>(hs, rsts, x, xh);

    const int MB = (Tc + 127) / 128;              // 257 m-blocks
    const dim3 gQKV(MB, QS / 128);                // (257, 12)
    const dim3 gKV (MB, 1024 / 128);              // (257, 8)
    const dim3 gD  (MB, Dc / 128);                // (257, 4)
    const dim3 gF  (MB, Fc / 128);                // (257, 16)
    const dim3 gFN (Bc * Hc, (SP + 63) / 64);     // (512, 9)

    // ---- layers 0..2: full ----
    for (int l = 0; l < Lc - 1; l++) {
        size_t od = (size_t)l * Dc * Dc;
        size_t oq = (size_t)l * QS * Dc;
        size_t o1 = (size_t)l * Fc * Dc;
        size_t o2 = (size_t)l * Dc * Fc;

        gemm_mma<<<gQKV, 256, GSMEM>>>(xh, wqkv + oq, bqkv + l * QS,
                                       0, qkv, Tc, QS, Dc, QS, 0, 0);

        favor_kv<<<Bc * Hc, 256>>>(qkv, kv, ks);
        favor_num<<<gFN, 256>>>(qkv, kv, ks, ah);

        gemm_mma<<<gD, 256, GSMEM>>>(ah, wo + od, bo + l*Dc, tmp, 0, Tc, Dc, Dc, Dc, 0, 0);
        add_ln<<<Tc, 128>>>(tmp, x, xh, ln1s + l*Dc, ln1b + l*Dc);

        gemm_mma<<<gF, 256, GSMEM>>>(xh, w1 + o1, b1 + l*Fc, 0, fh, Tc, Fc, Dc, Fc, 1, 0);
        gemm_mma<<<gD, 256, GSMEM>>>(fh, w2 + o2, b2 + l*Dc, tmp, 0, Tc, Dc, Fc, Dc, 0, 0);
        add_ln<<<Tc, 128>>>(tmp, x, xh, ln2s + l*Dc, ln2b + l*Dc);
    }

    // ---- layer 3: only token-0 rows beyond the KV projection ----
    {
        const int l = Lc - 1;
        size_t od = (size_t)l * Dc * Dc;
        size_t oq = (size_t)l * QS * Dc;
        size_t o1 = (size_t)l * Fc * Dc;
        size_t o2 = (size_t)l * Dc * Fc;

        // K,V for all tokens (n-slice of packed QKV weights)
        gemm_mma<<<gKV, 256, GSMEM>>>(xh, wqkv + oq + (size_t)Dc * Dc,
                                      bqkv + l * QS + Dc,
                                      0, qkv + Dc, Tc, 1024, Dc, QS, 0, 0);
        // Q for the 64 token-0 rows: gather + small GEMM
        gather_x0<<<Bc, 256>>>(xh, xg0);
        gemm_mma<<<dim3(1, Dc / 128), 256, GSMEM>>>(
            xg0, wqkv + oq, bqkv + l * QS, q0, 0, Bc, Dc, Dc, Dc, 0, 0);

        favor_kv<<<Bc * Hc, 256>>>(qkv, kv, ks);
        favor_num0<<<Bc * Hc, 64>>>(q0, kv, ks, ah0);

        // AO on 64 rows
        gemm_mma<<<dim3(1, Dc / 128), 256, GSMEM>>>(
            ah0, wo + od, bo + l*Dc, tmp0, 0, Bc, Dc, Dc, Dc, 0, 0);
        add_ln0<<<Bc, 128>>>(tmp0, x, (size_t)SP * Dc, x0, xh0,
                             ln1s + l*Dc, ln1b + l*Dc);

        // FFN on 64 rows
        gemm_mma<<<dim3(1, Fc / 128), 256, GSMEM>>>(
            xh0, w1 + o1, b1 + l*Fc, 0, fh0, Bc, Fc, Dc, Fc, 1, 0);
        gemm_mma<<<dim3(1, Dc / 128), 256, GSMEM>>>(
            fh0, w2 + o2, b2 + l*Dc, tmp0, 0, Bc, Dc, Fc, Dc, 0, 0);
        add_ln0<<<Bc, 128>>>(tmp0, x0, (size_t)Dc, x0, xh0,
                             ln2s + l*Dc, ln2b + l*Dc);
    }

    head_kernel<<<Bc, Dc>>>(x0, Wqp, bqp, out);
}

// round 15
// speedup vs baseline: 1.1773x; 1.0181x over previous
#include <cuda_runtime.h>
#include <cuda_fp16.h>
#include <cstdint>

// ---------------------------------------------------------------------------
// TransformerAgent: 4-layer FAVOR+ transformer.
// GEMMs: fp16 mma.sync; A via cp.async+ldmatrix (BK=64, 3-stage), B weights
// pre-swizzled into mma fragment layout fed by LDG.128. 128x128 tile,
// 64x32 warp tile, 2 CTAs/SM. tmp buffer fp16. FAVOR: kv 16-row chunks,
// num 128 tokens/block. Layer 3: token-0 rows only.
// ---------------------------------------------------------------------------

#define Bc 64
#define Sc 512
#define SP 513
#define Dc 512
#define Hc 8
#define HDc 64
#define Fc 2048
#define Lc 4
#define Ac 16
#define OBSc 128
#define Tc (Bc * SP)          // 32832 tokens
#define QS (3 * Dc)           // fused qkv row stride = 1536

#define KEPS 1e-3f
#define LNEPS 1e-6f

typedef __half fp16;

// ------------------------- scratch (static device) ------------------------
__device__ float g_x  [Tc * Dc];
__device__ fp16  g_xh [Tc * Dc];
__device__ fp16  g_qkv[Tc * QS];
__device__ fp16  g_ah [Tc * Dc];
__device__ fp16  g_th [Tc * Dc];      // fp16 pre-LN GEMM output
__device__ fp16  g_fh [Tc * Fc];
__device__ float g_kv [Bc * Hc * HDc * HDc];
__device__ float g_ks [Bc * Hc * HDc];
__device__ fp16  g_ih [Bc * Sc * OBSc];
// layer-3 compact (token-0 rows only)
__device__ float g_x0  [Bc * Dc];
__device__ fp16  g_xh0 [Bc * Dc];
__device__ fp16  g_xg0 [Bc * Dc];
__device__ float g_q0  [Bc * Dc];
__device__ fp16  g_ah0 [Bc * Dc];
__device__ fp16  g_th0 [Bc * Dc];
__device__ fp16  g_fh0 [Bc * Fc];
// weights in mma B-fragment layout (ntPair-major), fp16
__device__ __align__(256) fp16 g_wqkv[Lc * QS * Dc];
__device__ float g_bqkv[Lc * QS];
__device__ __align__(256) fp16 g_wo [Lc * Dc * Dc];
__device__ __align__(256) fp16 g_w1 [Lc * Fc * Dc];
__device__ __align__(256) fp16 g_w2 [Lc * Dc * Fc];
__device__ __align__(256) fp16 g_we [Dc * OBSc];

// --------------------------- PTX helpers -----------------------------------
__device__ __forceinline__ uint32_t smem_u32(const void* p) {
    uint32_t a;
    asm("{ .reg .u64 t; cvta.to.shared.u64 t, %1; cvt.u32.u64 %0, t; }"
        : "=r"(a) : "l"(p));
    return a;
}

#define CP_ASYNC16(s, g) \
    asm volatile("cp.async.ca.shared.global [%0], [%1], 16;" :: "r"(s), "l"(g))
#define CP_COMMIT() asm volatile("cp.async.commit_group;" ::: "memory")
#define CP_WAIT1()  asm volatile("cp.async.wait_group 1;" ::: "memory")

#define LDSM4(r, a) \
    asm volatile("ldmatrix.sync.aligned.m8n8.x4.shared.b16 {%0,%1,%2,%3}, [%4];" \
        : "=r"((r)[0]), "=r"((r)[1]), "=r"((r)[2]), "=r"((r)[3]) : "r"(a))

#define MMA16816(d, a, b0, b1) \
    asm volatile("mma.sync.aligned.m16n8k16.row.col.f32.f16.f16.f32 " \
        "{%0,%1,%2,%3},{%4,%5,%6,%7},{%8,%9},{%0,%1,%2,%3};" \
        : "+f"((d)[0]), "+f"((d)[1]), "+f"((d)[2]), "+f"((d)[3]) \
        : "r"((a)[0]), "r"((a)[1]), "r"((a)[2]), "r"((a)[3]), "r"(b0), "r"(b1))

// ---------------------------------------------------------------------------
// fp16 GEMM (round-11 config): C[M,N] = A[M,K] @ W^T + bias.
// W pre-swizzled: uint4 index = (ntPair * (K/16) + kt) * 32 + lane.
// Block 128x128 (grid.x = m-blocks, grid.y = n-blocks), 8 warps 64x32,
// A: BK=64 chunks, 3-stage cp.async + ldmatrix, one barrier per chunk.
// ---------------------------------------------------------------------------
#define GROW   144
#define GARR   (128 * GROW)       // 18432 B per stage
#define NSTAGE 3
#define GSMEM  (NSTAGE * GARR)    // 55296 B

__global__ __launch_bounds__(256, 2)
void gemm_mma(const fp16* __restrict__ A, const fp16* __restrict__ W,
              const float* __restrict__ bias,
              float* __restrict__ Cf, fp16* __restrict__ Ch,
              int M, int N, int K, int ldc, int relu, int rowmap)
{
    extern __shared__ char smem[];
    const uint32_t sbase = smem_u32(smem);
    const int tid  = threadIdx.x;
    const int wid  = tid >> 5;
    const int lane = tid & 31;
    const int m0 = blockIdx.x * 128;
    const int n0 = blockIdx.y * 128;
    const int nch = K >> 6;
    const int ktiles = K >> 4;

    const int wm = wid >> 2;          // 0..1
    const int wn = wid & 3;           // 0..3
    const uint4* __restrict__ Wq = (const uint4*)W;
    const size_t ntp0 = (size_t)((n0 >> 4) + wn * 2);

    float acc[4][4][4];
#pragma unroll
    for (int a = 0; a < 4; a++)
#pragma unroll
        for (int b = 0; b < 4; b++)
#pragma unroll
            for (int c = 0; c < 4; c++) acc[a][b][c] = 0.f;

    auto load_chunk = [&](int c) {
        const int s = c % NSTAGE;
        const size_t kb = (size_t)c * 64;
        const uint32_t sA = sbase + s * GARR;
#pragma unroll
        for (int it = 0; it < 4; it++) {
            int i = tid + it * 256;            // 0..1023
            int row = i >> 3;
            int c8  = (i & 7) * 8;
            int gr = min(m0 + row, M - 1);
            CP_ASYNC16(sA + row * GROW + (i & 7) * 16,
                       (const char*)(A + (size_t)gr * K + kb + c8));
        }
        CP_COMMIT();
    };

    load_chunk(0);
    if (nch > 1) load_chunk(1); else CP_COMMIT();

    for (int c = 0; c < nch; c++) {
        const int s = c % NSTAGE;
        CP_WAIT1();
        __syncthreads();

        if (c + 2 < nch) load_chunk(c + 2); else CP_COMMIT();

        const uint32_t sA = sbase + s * GARR;

#pragma unroll
        for (int ks = 0; ks < 4; ks++) {
            const int kt = c * 4 + ks;
            uint4 bf0 = Wq[(ntp0       * ktiles + kt) * 32 + lane];
            uint4 bf1 = Wq[((ntp0 + 1) * ktiles + kt) * 32 + lane];
            uint32_t af[4][4];
            {
                const int r  = lane & 15;
                const int kh = (lane >> 4) * 8;
                const uint32_t kofs = (ks * 16 + kh) * 2;
#pragma unroll
                for (int mi = 0; mi < 4; mi++)
                    LDSM4(af[mi], sA + (wm * 64 + mi * 16 + r) * GROW + kofs);
            }
#pragma unroll
            for (int mi = 0; mi < 4; mi++) {
                MMA16816(acc[mi][0], af[mi], bf0.x, bf0.y);
                MMA16816(acc[mi][1], af[mi], bf0.z, bf0.w);
                MMA16816(acc[mi][2], af[mi], bf1.x, bf1.y);
                MMA16816(acc[mi][3], af[mi], bf1.z, bf1.w);
            }
        }
    }

    // ---- epilogue ----
    const int rq = lane >> 2;
    const int cq = (lane & 3) * 2;
#pragma unroll
    for (int mi = 0; mi < 4; mi++) {
#pragma unroll
        for (int half = 0; half < 2; half++) {
            int rr = m0 + wm * 64 + mi * 16 + rq + half * 8;
            if (rr >= M) continue;
            size_t orow = rowmap ? (size_t)(rr + rr / Sc + 1) : (size_t)rr;
#pragma unroll
            for (int nj = 0; nj < 4; nj++) {
                int cc = n0 + wn * 32 + nj * 8 + cq;
                float v0 = acc[mi][nj][half * 2 + 0] + bias[cc];
                float v1 = acc[mi][nj][half * 2 + 1] + bias[cc + 1];
                if (relu) { v0 = fmaxf(v0, 0.f); v1 = fmaxf(v1, 0.f); }
                if (Cf)
                    *(float2*)(Cf + orow * (size_t)ldc + cc) = make_float2(v0, v1);
                if (Ch) {
                    __half2 hp = __floats2half2_rn(v0, v1);
                    *(__half2*)(Ch + orow * (size_t)ldc + cc) = hp;
                }
            }
        }
    }
}

// ----- batched weight transpose + fp16 + B-fragment swizzle ----------------
struct WJob { const float* src; fp16* dst; int K; int N; };
struct WJobs { WJob j[25]; };

__global__ void wconv_all(WJobs jobs)
{
    WJob jb = jobs.j[blockIdx.z];
    int nbx = jb.N >> 5;
    int nb  = nbx * (jb.K >> 5);
    int bid = blockIdx.x;
    if (bid >= nb) return;
    int x = (bid % nbx) * 32;
    int y = (bid / nbx) * 32;

    __shared__ float t[32][33];
#pragma unroll
    for (int r = 0; r < 4; r++) {
        int row = y + threadIdx.y + r * 8;
        t[threadIdx.y + r * 8][threadIdx.x] = jb.src[(size_t)row * jb.N + x + threadIdx.x];
    }
    __syncthreads();
    int ktiles = jb.K >> 4;
#pragma unroll
    for (int r = 0; r < 4; r++) {
        int n = x + threadIdx.y + r * 8;
        int k = y + threadIdx.x;
        float v = t[threadIdx.x][threadIdx.y + r * 8];
        int k0 = k & 15;
        int lane = ((n & 7) << 2) | ((k0 >> 1) & 3);
        int sub  = ((n >> 3) & 1) * 4 + ((k0 >= 8) ? 2 : 0) + (k0 & 1);
        size_t idx = (((size_t)(n >> 4) * ktiles + (k >> 4)) * 32 + lane) * 8 + sub;
        jb.dst[idx] = __float2half_rn(v);
    }
}

// ------------------ pack qkv biases: [L][3*D] ------------------------------
__global__ void bpack(const float* __restrict__ bq, const float* __restrict__ bk,
                      const float* __restrict__ bv, float* __restrict__ dst)
{
    int l = blockIdx.x;
    int i = threadIdx.x;
    dst[l * QS + i]          = bq[l * Dc + i];
    dst[l * QS + Dc + i]     = bk[l * Dc + i];
    dst[l * QS + 2 * Dc + i] = bv[l * Dc + i];
}

// --------------------- fp32 -> fp16 convert (flat) --------------------------
__global__ void fcvt(const float* __restrict__ src, fp16* __restrict__ dst, int n4)
{
    int i = blockIdx.x * 256 + threadIdx.x;
    if (i < n4) {
        float4 v = ((const float4*)src)[i];
        __half2 a = __floats2half2_rn(v.x, v.y);
        __half2 b = __floats2half2_rn(v.z, v.w);
        uint2 o;
        o.x = *(uint32_t*)&a;
        o.y = *(uint32_t*)&b;
        ((uint2*)dst)[i] = o;
    }
}

// --------------------- init: hidden-state row per batch -------------------
__global__ void init_h0(const float* __restrict__ hs, const void* __restrict__ resets,
                        float* __restrict__ x, fp16* __restrict__ xh)
{
    __shared__ int mode;
    int b = blockIdx.x;
    if (threadIdx.x == 0) {
        const unsigned int* w = (const unsigned int*)resets;
        bool allint = true, allflt = true;
        for (int i = 0; i < 16; i++) {
            unsigned int u = w[i];
            if (u != 0u && u != 1u) allint = false;
            if (u != 0u && u != 0x3F800000u) allflt = false;
        }
        mode = allint ? 0 : (allflt ? 2 : 1);
    }
    __syncthreads();
    bool rst;
    if (mode == 0)      rst = ((const int*)resets)[b] != 0;
    else if (mode == 2) rst = ((const float*)resets)[b] != 0.f;
    else                rst = ((const unsigned char*)resets)[b] != 0;

    float val = rst ? 0.f : hs[b * Dc + threadIdx.x];
    size_t o = (size_t)b * SP * Dc + threadIdx.x;
    x[o] = val;
    xh[o] = __float2half_rn(val);
}

// ------------------- FAVOR: kv = sum_s pk^T outer v, ksum ------------------
__global__ __launch_bounds__(256)
void favor_kv(const fp16* __restrict__ qkv, float* __restrict__ kv,
              float* __restrict__ ksum)
{
    int bh = blockIdx.x;
    int b = bh / Hc, h = bh % Hc;
    const fp16* kb = qkv + (size_t)b * SP * QS + Dc + h * HDc;
    const fp16* vb = qkv + (size_t)b * SP * QS + 2 * Dc + h * HDc;

    __shared__ float spk[16][HDc];
    __shared__ float sv [16][HDc];

    int tid = threadIdx.x;
    int tm = (tid >> 4) * 4;
    int td = (tid & 15) * 4;

    float acc[4][4];
#pragma unroll
    for (int i = 0; i < 4; i++)
#pragma unroll
        for (int j = 0; j < 4; j++) acc[i][j] = 0.f;
    float ks = 0.f;

    for (int s0 = 0; s0 < SP; s0 += 16) {
        int nch = min(16, SP - s0);
        for (int i = tid; i < nch * HDc; i += 256) {
            int ss = i >> 6, dd = i & 63;
            float kk = __half2float(kb[(size_t)(s0 + ss) * QS + dd]);
            spk[ss][dd] = fmaxf(kk, 0.f) + KEPS;
            sv[ss][dd]  = __half2float(vb[(size_t)(s0 + ss) * QS + dd]);
        }
        __syncthreads();
        for (int j = 0; j < nch; j++) {
            float pa[4], va[4];
#pragma unroll
            for (int i = 0; i < 4; i++) { pa[i] = spk[j][tm + i]; va[i] = sv[j][td + i]; }
#pragma unroll
            for (int i = 0; i < 4; i++)
#pragma unroll
                for (int l = 0; l < 4; l++)
                    acc[i][l] = fmaf(pa[i], va[l], acc[i][l]);
            if (tid < HDc) ks += spk[j][tid];
        }
        __syncthreads();
    }

    float* kvb = kv + (size_t)bh * HDc * HDc;
#pragma unroll
    for (int i = 0; i < 4; i++)
#pragma unroll
        for (int l = 0; l < 4; l++)
            kvb[(tm + i) * HDc + td + l] = acc[i][l];
    if (tid < HDc) ksum[bh * HDc + tid] = ks;
}

// ---------- FAVOR: num = pq @ kv, den; 128 tokens/block; out -> fp16 --------
__global__ __launch_bounds__(256)
void favor_num(const fp16* __restrict__ qkv, const float* __restrict__ kv,
               const float* __restrict__ ksum, fp16* __restrict__ ah)
{
    int bh = blockIdx.x;
    int b = bh / Hc, h = bh % Hc;
    int tb = blockIdx.y * 128;

    __shared__ float skv[HDc][HDc];
    __shared__ float sks[HDc];
    __shared__ float spq[16][HDc];

    int tid = threadIdx.x;
    const float* kvb = kv + (size_t)bh * HDc * HDc;
    for (int i = tid; i < (HDc * HDc) / 4; i += 256)
        ((float4*)skv)[i] = ((const float4*)kvb)[i];
    if (tid < HDc) sks[tid] = ksum[bh * HDc + tid];
    __syncthreads();

    const int t = tid >> 4;
    const int dq = (tid & 15) * 4;

#pragma unroll 1
    for (int pass = 0; pass < 8; pass++) {
        int t0 = tb + pass * 16;
        if (t0 >= SP) break;
        for (int i = tid; i < 16 * HDc; i += 256) {
            int tt = i >> 6, dd = i & 63;
            int s = t0 + tt;
            float qv = 0.f;
            if (s < SP) qv = __half2float(qkv[((size_t)b * SP + s) * QS + h * HDc + dd]);
            spq[tt][dd] = fmaxf(qv, 0.f) + KEPS;
        }
        __syncthreads();

        float a0 = 0.f, a1 = 0.f, a2 = 0.f, a3 = 0.f, den = 0.f;
#pragma unroll
        for (int m = 0; m < HDc; m++) {
            float pq = spq[t][m];
            den = fmaf(pq, sks[m], den);
            float4 kk = *(const float4*)&skv[m][dq];
            a0 = fmaf(pq, kk.x, a0);
            a1 = fmaf(pq, kk.y, a1);
            a2 = fmaf(pq, kk.z, a2);
            a3 = fmaf(pq, kk.w, a3);
        }
        int s = t0 + t;
        if (s < SP) {
            float inv = 1.f / den;
            __half2 p0 = __floats2half2_rn(a0 * inv, a1 * inv);
            __half2 p1 = __floats2half2_rn(a2 * inv, a3 * inv);
            size_t idx = ((size_t)b * SP + s) * Dc + h * HDc + dq;
            uint2 o;
            o.x = *(uint32_t*)&p0;
            o.y = *(uint32_t*)&p1;
            *(uint2*)(ah + idx) = o;
        }
        __syncthreads();
    }
}

// --------------- x = LayerNorm(a + x) * s + b  (a fp16, + fp16 out) --------
__global__ __launch_bounds__(128)
void add_ln(const fp16* __restrict__ a, float* __restrict__ x,
            fp16* __restrict__ xh,
            const float* __restrict__ s, const float* __restrict__ bb)
{
    size_t r = blockIdx.x;
    const fp16* ar = a + r * Dc;
    float* xr = x + r * Dc;
    int tid = threadIdx.x;
    int c0 = tid * 4;

    uint2 au = *(const uint2*)(ar + c0);
    __half2 ah0 = *(__half2*)&au.x;
    __half2 ah1 = *(__half2*)&au.y;
    float4 xv = *(const float4*)(xr + c0);
    float v[4] = { __low2float(ah0) + xv.x, __high2float(ah0) + xv.y,
                   __low2float(ah1) + xv.z, __high2float(ah1) + xv.w };
    float sum = v[0] + v[1] + v[2] + v[3];
    float sq  = fmaf(v[0], v[0], fmaf(v[1], v[1], fmaf(v[2], v[2], v[3] * v[3])));
#pragma unroll
    for (int o = 16; o > 0; o >>= 1) {
        sum += __shfl_xor_sync(0xFFFFFFFFu, sum, o);
        sq  += __shfl_xor_sync(0xFFFFFFFFu, sq, o);
    }
    __shared__ float rs[4], rq[4];
    int w = tid >> 5;
    if ((tid & 31) == 0) { rs[w] = sum; rq[w] = sq; }
    __syncthreads();
    sum = rs[0] + rs[1] + rs[2] + rs[3];
    sq  = rq[0] + rq[1] + rq[2] + rq[3];
    float mean = sum * (1.f / Dc);
    float var  = sq * (1.f / Dc) - mean * mean;
    float inv  = rsqrtf(var + LNEPS);

    float o0 = (v[0] - mean) * inv * s[c0 + 0] + bb[c0 + 0];
    float o1 = (v[1] - mean) * inv * s[c0 + 1] + bb[c0 + 1];
    float o2 = (v[2] - mean) * inv * s[c0 + 2] + bb[c0 + 2];
    float o3 = (v[3] - mean) * inv * s[c0 + 3] + bb[c0 + 3];
    *(float4*)(xr + c0) = make_float4(o0, o1, o2, o3);
    __half2 h0 = __floats2half2_rn(o0, o1);
    __half2 h1 = __floats2half2_rn(o2, o3);
    uint2 ou;
    ou.x = *(uint32_t*)&h0;
    ou.y = *(uint32_t*)&h1;
    *(uint2*)(xh + r * Dc + c0) = ou;
}

// ---- layer-3 compact variant: a fp16; reads residual from xin (stride) ----
__global__ __launch_bounds__(128)
void add_ln0(const fp16* __restrict__ a, const float* __restrict__ xin,
             size_t xin_stride, float* __restrict__ xout, fp16* __restrict__ xh,
             const float* __restrict__ s, const float* __restrict__ bb)
{
    int b = blockIdx.x;
    const fp16* ar = a + (size_t)b * Dc;
    const float* xr = xin + (size_t)b * xin_stride;
    int tid = threadIdx.x;
    int c0 = tid * 4;

    uint2 au = *(const uint2*)(ar + c0);
    __half2 ah0 = *(__half2*)&au.x;
    __half2 ah1 = *(__half2*)&au.y;
    float4 xv = *(const float4*)(xr + c0);
    float v[4] = { __low2float(ah0) + xv.x, __high2float(ah0) + xv.y,
                   __low2float(ah1) + xv.z, __high2float(ah1) + xv.w };
    float sum = v[0] + v[1] + v[2] + v[3];
    float sq  = fmaf(v[0], v[0], fmaf(v[1], v[1], fmaf(v[2], v[2], v[3] * v[3])));
#pragma unroll
    for (int o = 16; o > 0; o >>= 1) {
        sum += __shfl_xor_sync(0xFFFFFFFFu, sum, o);
        sq  += __shfl_xor_sync(0xFFFFFFFFu, sq, o);
    }
    __shared__ float rs[4], rq[4];
    int w = tid >> 5;
    if ((tid & 31) == 0) { rs[w] = sum; rq[w] = sq; }
    __syncthreads();
    sum = rs[0] + rs[1] + rs[2] + rs[3];
    sq  = rq[0] + rq[1] + rq[2] + rq[3];
    float mean = sum * (1.f / Dc);
    float var  = sq * (1.f / Dc) - mean * mean;
    float inv  = rsqrtf(var + LNEPS);

    float o0 = (v[0] - mean) * inv * s[c0 + 0] + bb[c0 + 0];
    float o1 = (v[1] - mean) * inv * s[c0 + 1] + bb[c0 + 1];
    float o2 = (v[2] - mean) * inv * s[c0 + 2] + bb[c0 + 2];
    float o3 = (v[3] - mean) * inv * s[c0 + 3] + bb[c0 + 3];
    *(float4*)(xout + (size_t)b * Dc + c0) = make_float4(o0, o1, o2, o3);
    __half2 h0 = __floats2half2_rn(o0, o1);
    __half2 h1 = __floats2half2_rn(o2, o3);
    uint2 ou;
    ou.x = *(uint32_t*)&h0;
    ou.y = *(uint32_t*)&h1;
    *(uint2*)(xh + (size_t)b * Dc + c0) = ou;
}

// ---- gather token-0 rows of xh into compact A buffer ----------------------
__global__ void gather_x0(const fp16* __restrict__ xh, fp16* __restrict__ xg0)
{
    int b = blockIdx.x;
    int i = threadIdx.x;
    ((uint32_t*)xg0)[b * (Dc / 2) + i] =
        ((const uint32_t*)(xh + (size_t)b * SP * Dc))[i];
}

// ---- layer-3: attention out for token 0 only --------------------------------
__global__ __launch_bounds__(64)
void favor_num0(const float* __restrict__ q0, const float* __restrict__ kv,
                const float* __restrict__ ksum, fp16* __restrict__ ah0)
{
    int bh = blockIdx.x;
    int b = bh / Hc, h = bh % Hc;
    int d = threadIdx.x;   // 0..63

    __shared__ float spq[HDc];
    __shared__ float sks[HDc];
    float qv = q0[(size_t)b * Dc + h * HDc + d];
    spq[d] = fmaxf(qv, 0.f) + KEPS;
    sks[d] = ksum[bh * HDc + d];
    __syncthreads();

    const float* kvb = kv + (size_t)bh * HDc * HDc;
    float num = 0.f, den = 0.f;
#pragma unroll 8
    for (int m = 0; m < HDc; m++) {
        float pq = spq[m];
        num = fmaf(pq, kvb[m * HDc + d], num);
        den = fmaf(pq, sks[m], den);
    }
    ah0[(size_t)b * Dc + h * HDc + d] = __float2half_rn(num / den);
}

// ---------------- head: copy h_out and compute q_vals ----------------------
__global__ __launch_bounds__(512)
void head_kernel(const float* __restrict__ x0, const float* __restrict__ Wqp,
                 const float* __restrict__ bqp, float* __restrict__ out)
{
    int b = blockIdx.x;
    int tid = threadIdx.x;
    const float* hr = x0 + (size_t)b * Dc;
    out[b * Dc + tid] = hr[tid];

    int w = tid >> 5, lane = tid & 31;
    float sum = 0.f;
    for (int i = lane; i < Dc; i += 32)
        sum = fmaf(hr[i], Wqp[i * Ac + w], sum);
#pragma unroll
    for (int o = 16; o > 0; o >>= 1)
        sum += __shfl_xor_sync(0xFFFFFFFFu, sum, o);
    if (lane == 0) out[Bc * Dc + b * Ac + w] = sum + bqp[w];
}

// ---------------------------------------------------------------------------
extern "C" void kernel_launch(void* const* d_in, const int* in_sizes, int n_in,
                              void* d_out, int out_size)
{
    const float* hs    = (const float*)d_in[0];
    const float* ins   = (const float*)d_in[1];
    const void*  rsts  = d_in[2];
    const float* W_emb = (const float*)d_in[3];
    const float* b_emb = (const float*)d_in[4];
    const float* Wq    = (const float*)d_in[5];
    const float* bq    = (const float*)d_in[6];
    const float* Wk    = (const float*)d_in[7];
    const float* bk    = (const float*)d_in[8];
    const float* Wv    = (const float*)d_in[9];
    const float* bv    = (const float*)d_in[10];
    const float* Wo    = (const float*)d_in[11];
    const float* bo    = (const float*)d_in[12];
    const float* ln1s  = (const float*)d_in[13];
    const float* ln1b  = (const float*)d_in[14];
    const float* ln2s  = (const float*)d_in[15];
    const float* ln2b  = (const float*)d_in[16];
    const float* W1    = (const float*)d_in[17];
    const float* b1    = (const float*)d_in[18];
    const float* W2    = (const float*)d_in[19];
    const float* b2    = (const float*)d_in[20];
    const float* Wqp   = (const float*)d_in[21];
    const float* bqp   = (const float*)d_in[22];
    float* out = (float*)d_out;

    cudaFuncSetAttribute(gemm_mma, cudaFuncAttributeMaxDynamicSharedMemorySize, GSMEM);

    float *x, *kv, *ks, *bqkv, *x0, *q0;
    fp16 *xh, *qkv, *ah, *th, *fh, *ih, *xh0, *xg0, *ah0, *th0, *fh0;
    fp16 *wqkv, *wo, *w1, *w2, *we;
    cudaGetSymbolAddress((void**)&x,    g_x);
    cudaGetSymbolAddress((void**)&xh,   g_xh);
    cudaGetSymbolAddress((void**)&qkv,  g_qkv);
    cudaGetSymbolAddress((void**)&ah,   g_ah);
    cudaGetSymbolAddress((void**)&th,   g_th);
    cudaGetSymbolAddress((void**)&fh,   g_fh);
    cudaGetSymbolAddress((void**)&kv,   g_kv);
    cudaGetSymbolAddress((void**)&ks,   g_ks);
    cudaGetSymbolAddress((void**)&ih,   g_ih);
    cudaGetSymbolAddress((void**)&x0,   g_x0);
    cudaGetSymbolAddress((void**)&xh0,  g_xh0);
    cudaGetSymbolAddress((void**)&xg0,  g_xg0);
    cudaGetSymbolAddress((void**)&q0,   g_q0);
    cudaGetSymbolAddress((void**)&ah0,  g_ah0);
    cudaGetSymbolAddress((void**)&th0,  g_th0);
    cudaGetSymbolAddress((void**)&fh0,  g_fh0);
    cudaGetSymbolAddress((void**)&bqkv, g_bqkv);
    cudaGetSymbolAddress((void**)&wqkv, g_wqkv);
    cudaGetSymbolAddress((void**)&wo,   g_wo);
    cudaGetSymbolAddress((void**)&w1,   g_w1);
    cudaGetSymbolAddress((void**)&w2,   g_w2);
    cudaGetSymbolAddress((void**)&we,   g_we);

    // ins convert
    {
        int n4 = (Bc * Sc * OBSc) / 4;
        fcvt<<<(n4 + 255) / 256, 256>>>(ins, ih, n4);
    }
    // all weight conversions (transpose + fp16 + B-fragment swizzle)
    {
        WJobs jobs;
        int nj = 0;
        jobs.j[nj++] = { W_emb, we, OBSc, Dc };
        for (int l = 0; l < Lc; l++) {
            size_t od = (size_t)l * Dc * Dc;
            size_t oq = (size_t)l * QS * Dc;
            size_t o1 = (size_t)l * Fc * Dc;
            size_t o2 = (size_t)l * Dc * Fc;
            jobs.j[nj++] = { Wq + od, wqkv + oq,                       Dc, Dc };
            jobs.j[nj++] = { Wk + od, wqkv + oq + (size_t)Dc * Dc,     Dc, Dc };
            jobs.j[nj++] = { Wv + od, wqkv + oq + (size_t)2 * Dc * Dc, Dc, Dc };
            jobs.j[nj++] = { Wo + od, wo + od, Dc, Dc };
            jobs.j[nj++] = { W1 + o1, w1 + o1, Dc, Fc };
            jobs.j[nj++] = { W2 + o2, w2 + o2, Fc, Dc };
        }
        wconv_all<<<dim3(1024, 1, 25), dim3(32, 8)>>>(jobs);
    }
    // pack qkv biases
    bpack<<<Lc, Dc>>>(bq, bk, bv, bqkv);

    // embedding GEMM (grid: x=m-blocks, y=n-blocks)
    gemm_mma<<<dim3((Bc * Sc) / 128, Dc / 128), 256, GSMEM>>>(
        ih, we, b_emb, x, xh, Bc * Sc, Dc, OBSc, Dc, 0, 1);

    // hidden-state rows
    init_h0<<<Bc, Dc>>>(hs, rsts, x, xh);

    const int MB = (Tc + 127) / 128;              // 257 m-blocks
    const dim3 gQKV(MB, QS / 128);                // (257, 12)
    const dim3 gKV (MB, 1024 / 128);              // (257, 8)
    const dim3 gD  (MB, Dc / 128);                // (257, 4)
    const dim3 gF  (MB, Fc / 128);                // (257, 16)
    const dim3 gFN (Bc * Hc, (SP + 127) / 128);   // (512, 5)

    // ---- layers 0..2: full ----
    for (int l = 0; l < Lc - 1; l++) {
        size_t od = (size_t)l * Dc * Dc;
        size_t oq = (size_t)l * QS * Dc;
        size_t o1 = (size_t)l * Fc * Dc;
        size_t o2 = (size_t)l * Dc * Fc;

        gemm_mma<<<gQKV, 256, GSMEM>>>(xh, wqkv + oq, bqkv + l * QS,
                                       0, qkv, Tc, QS, Dc, QS, 0, 0);

        favor_kv<<<Bc * Hc, 256>>>(qkv, kv, ks);
        favor_num<<<gFN, 256>>>(qkv, kv, ks, ah);

        gemm_mma<<<gD, 256, GSMEM>>>(ah, wo + od, bo + l*Dc, 0, th, Tc, Dc, Dc, Dc, 0, 0);
        add_ln<<<Tc, 128>>>(th, x, xh, ln1s + l*Dc, ln1b + l*Dc);

        gemm_mma<<<gF, 256, GSMEM>>>(xh, w1 + o1, b1 + l*Fc, 0, fh, Tc, Fc, Dc, Fc, 1, 0);
        gemm_mma<<<gD, 256, GSMEM>>>(fh, w2 + o2, b2 + l*Dc, 0, th, Tc, Dc, Fc, Dc, 0, 0);
        add_ln<<<Tc, 128>>>(th, x, xh, ln2s + l*Dc, ln2b + l*Dc);
    }

    // ---- layer 3: only token-0 rows beyond the KV projection ----
    {
        const int l = Lc - 1;
        size_t od = (size_t)l * Dc * Dc;
        size_t oq = (size_t)l * QS * Dc;
        size_t o1 = (size_t)l * Fc * Dc;
        size_t o2 = (size_t)l * Dc * Fc;

        // K,V for all tokens (n-slice of packed QKV weights)
        gemm_mma<<<gKV, 256, GSMEM>>>(xh, wqkv + oq + (size_t)Dc * Dc,
                                      bqkv + l * QS + Dc,
                                      0, qkv + Dc, Tc, 1024, Dc, QS, 0, 0);
        // Q for the 64 token-0 rows: gather + small GEMM
        gather_x0<<<Bc, 256>>>(xh, xg0);
        gemm_mma<<<dim3(1, Dc / 128), 256, GSMEM>>>(
            xg0, wqkv + oq, bqkv + l * QS, q0, 0, Bc, Dc, Dc, Dc, 0, 0);

        favor_kv<<<Bc * Hc, 256>>>(qkv, kv, ks);
        favor_num0<<<Bc * Hc, 64>>>(q0, kv, ks, ah0);

        // AO on 64 rows
        gemm_mma<<<dim3(1, Dc / 128), 256, GSMEM>>>(
            ah0, wo + od, bo + l*Dc, 0, th0, Bc, Dc, Dc, Dc, 0, 0);
        add_ln0<<<Bc, 128>>>(th0, x, (size_t)SP * Dc, x0, xh0,
                             ln1s + l*Dc, ln1b + l*Dc);

        // FFN on 64 rows
        gemm_mma<<<dim3(1, Fc / 128), 256, GSMEM>>>(
            xh0, w1 + o1, b1 + l*Fc, 0, fh0, Bc, Fc, Dc, Fc, 1, 0);
        gemm_mma<<<dim3(1, Dc / 128), 256, GSMEM>>>(
            fh0, w2 + o2, b2 + l*Dc, 0, th0, Bc, Dc, Fc, Dc, 0, 0);
        add_ln0<<<Bc, 128>>>(th0, x0, (size_t)Dc, x0, xh0,
                             ln2s + l*Dc, ln2b + l*Dc);
    }

    head_kernel<<<Bc, Dc>>>(x0, Wqp, bqp, out);
}

// round 16
// speedup vs baseline: 1.7675x; 1.5013x over previous
#include <cuda_runtime.h>
#include <cuda_fp16.h>
#include <cstdint>

// ---------------------------------------------------------------------------
// TransformerAgent: 4-layer FAVOR+ transformer.
// GEMMs: fp16 mma.sync; A via cp.async+ldmatrix (BK=64, 3-stage), B weights
// pre-swizzled into mma fragment layout fed by LDG.128. 128x128 tile,
// 64x32 warp tile, 2 CTAs/SM. FAVOR numerator on tensor cores (kv emitted
// in B-frag layout, ksum as column 64). Layer 3: token-0 rows only.
// ---------------------------------------------------------------------------

#define Bc 64
#define Sc 512
#define SP 513
#define Dc 512
#define Hc 8
#define HDc 64
#define Fc 2048
#define Lc 4
#define Ac 16
#define OBSc 128
#define Tc (Bc * SP)          // 32832 tokens
#define QS (3 * Dc)           // fused qkv row stride = 1536
#define KVB_H 8192            // halves per (b,h) kvB tile: 8 ntPairs*4 kt*32*8

#define KEPS 1e-3f
#define LNEPS 1e-6f

typedef __half fp16;

// ------------------------- scratch (static device) ------------------------
__device__ float g_x  [Tc * Dc];
__device__ fp16  g_xh [Tc * Dc];
__device__ fp16  g_qkv[Tc * QS];
__device__ fp16  g_ah [Tc * Dc];
__device__ fp16  g_th [Tc * Dc];
__device__ fp16  g_fh [Tc * Fc];
__device__ __align__(256) fp16 g_kvB[Bc * Hc * KVB_H];   // kv in B-frag (N=128 pad)
__device__ float g_ks [Bc * Hc * HDc];
__device__ fp16  g_ih [Bc * Sc * OBSc];
// layer-3 compact (token-0 rows only)
__device__ float g_x0  [Bc * Dc];
__device__ fp16  g_xh0 [Bc * Dc];
__device__ fp16  g_xg0 [Bc * Dc];
__device__ float g_q0  [Bc * Dc];
__device__ fp16  g_ah0 [Bc * Dc];
__device__ fp16  g_th0 [Bc * Dc];
__device__ fp16  g_fh0 [Bc * Fc];
// weights in mma B-fragment layout (ntPair-major), fp16
__device__ __align__(256) fp16 g_wqkv[Lc * QS * Dc];
__device__ float g_bqkv[Lc * QS];
__device__ __align__(256) fp16 g_wo [Lc * Dc * Dc];
__device__ __align__(256) fp16 g_w1 [Lc * Fc * Dc];
__device__ __align__(256) fp16 g_w2 [Lc * Dc * Fc];
__device__ __align__(256) fp16 g_we [Dc * OBSc];

// --------------------------- PTX helpers -----------------------------------
__device__ __forceinline__ uint32_t smem_u32(const void* p) {
    uint32_t a;
    asm("{ .reg .u64 t; cvta.to.shared.u64 t, %1; cvt.u32.u64 %0, t; }"
        : "=r"(a) : "l"(p));
    return a;
}

#define CP_ASYNC16(s, g) \
    asm volatile("cp.async.ca.shared.global [%0], [%1], 16;" :: "r"(s), "l"(g))
#define CP_COMMIT() asm volatile("cp.async.commit_group;" ::: "memory")
#define CP_WAIT1()  asm volatile("cp.async.wait_group 1;" ::: "memory")

#define LDSM4(r, a) \
    asm volatile("ldmatrix.sync.aligned.m8n8.x4.shared.b16 {%0,%1,%2,%3}, [%4];" \
        : "=r"((r)[0]), "=r"((r)[1]), "=r"((r)[2]), "=r"((r)[3]) : "r"(a))

#define MMA16816(d, a, b0, b1) \
    asm volatile("mma.sync.aligned.m16n8k16.row.col.f32.f16.f16.f32 " \
        "{%0,%1,%2,%3},{%4,%5,%6,%7},{%8,%9},{%0,%1,%2,%3};" \
        : "+f"((d)[0]), "+f"((d)[1]), "+f"((d)[2]), "+f"((d)[3]) \
        : "r"((a)[0]), "r"((a)[1]), "r"((a)[2]), "r"((a)[3]), "r"(b0), "r"(b1))

// B-fragment half index for element (n, k) with K = ktiles*16
__device__ __forceinline__ size_t bfrag_idx(int n, int k, int ktiles) {
    int k0 = k & 15;
    int lane = ((n & 7) << 2) | ((k0 >> 1) & 3);
    int sub  = ((n >> 3) & 1) * 4 + ((k0 >= 8) ? 2 : 0) + (k0 & 1);
    return (((size_t)(n >> 4) * ktiles + (k >> 4)) * 32 + lane) * 8 + sub;
}

// ---------------------------------------------------------------------------
// fp16 GEMM (round-11 config): C[M,N] = A[M,K] @ W^T + bias.
// ---------------------------------------------------------------------------
#define GROW   144
#define GARR   (128 * GROW)       // 18432 B per stage
#define NSTAGE 3
#define GSMEM  (NSTAGE * GARR)    // 55296 B

__global__ __launch_bounds__(256, 2)
void gemm_mma(const fp16* __restrict__ A, const fp16* __restrict__ W,
              const float* __restrict__ bias,
              float* __restrict__ Cf, fp16* __restrict__ Ch,
              int M, int N, int K, int ldc, int relu, int rowmap)
{
    extern __shared__ char smem[];
    const uint32_t sbase = smem_u32(smem);
    const int tid  = threadIdx.x;
    const int wid  = tid >> 5;
    const int lane = tid & 31;
    const int m0 = blockIdx.x * 128;
    const int n0 = blockIdx.y * 128;
    const int nch = K >> 6;
    const int ktiles = K >> 4;

    const int wm = wid >> 2;
    const int wn = wid & 3;
    const uint4* __restrict__ Wq = (const uint4*)W;
    const size_t ntp0 = (size_t)((n0 >> 4) + wn * 2);

    float acc[4][4][4];
#pragma unroll
    for (int a = 0; a < 4; a++)
#pragma unroll
        for (int b = 0; b < 4; b++)
#pragma unroll
            for (int c = 0; c < 4; c++) acc[a][b][c] = 0.f;

    auto load_chunk = [&](int c) {
        const int s = c % NSTAGE;
        const size_t kb = (size_t)c * 64;
        const uint32_t sA = sbase + s * GARR;
#pragma unroll
        for (int it = 0; it < 4; it++) {
            int i = tid + it * 256;
            int row = i >> 3;
            int c8  = (i & 7) * 8;
            int gr = min(m0 + row, M - 1);
            CP_ASYNC16(sA + row * GROW + (i & 7) * 16,
                       (const char*)(A + (size_t)gr * K + kb + c8));
        }
        CP_COMMIT();
    };

    load_chunk(0);
    if (nch > 1) load_chunk(1); else CP_COMMIT();

    for (int c = 0; c < nch; c++) {
        const int s = c % NSTAGE;
        CP_WAIT1();
        __syncthreads();

        if (c + 2 < nch) load_chunk(c + 2); else CP_COMMIT();

        const uint32_t sA = sbase + s * GARR;

#pragma unroll
        for (int ks = 0; ks < 4; ks++) {
            const int kt = c * 4 + ks;
            uint4 bf0 = Wq[(ntp0       * ktiles + kt) * 32 + lane];
            uint4 bf1 = Wq[((ntp0 + 1) * ktiles + kt) * 32 + lane];
            uint32_t af[4][4];
            {
                const int r  = lane & 15;
                const int kh = (lane >> 4) * 8;
                const uint32_t kofs = (ks * 16 + kh) * 2;
#pragma unroll
                for (int mi = 0; mi < 4; mi++)
                    LDSM4(af[mi], sA + (wm * 64 + mi * 16 + r) * GROW + kofs);
            }
#pragma unroll
            for (int mi = 0; mi < 4; mi++) {
                MMA16816(acc[mi][0], af[mi], bf0.x, bf0.y);
                MMA16816(acc[mi][1], af[mi], bf0.z, bf0.w);
                MMA16816(acc[mi][2], af[mi], bf1.x, bf1.y);
                MMA16816(acc[mi][3], af[mi], bf1.z, bf1.w);
            }
        }
    }

    const int rq = lane >> 2;
    const int cq = (lane & 3) * 2;
#pragma unroll
    for (int mi = 0; mi < 4; mi++) {
#pragma unroll
        for (int half = 0; half < 2; half++) {
            int rr = m0 + wm * 64 + mi * 16 + rq + half * 8;
            if (rr >= M) continue;
            size_t orow = rowmap ? (size_t)(rr + rr / Sc + 1) : (size_t)rr;
#pragma unroll
            for (int nj = 0; nj < 4; nj++) {
                int cc = n0 + wn * 32 + nj * 8 + cq;
                float v0 = acc[mi][nj][half * 2 + 0] + bias[cc];
                float v1 = acc[mi][nj][half * 2 + 1] + bias[cc + 1];
                if (relu) { v0 = fmaxf(v0, 0.f); v1 = fmaxf(v1, 0.f); }
                if (Cf)
                    *(float2*)(Cf + orow * (size_t)ldc + cc) = make_float2(v0, v1);
                if (Ch) {
                    __half2 hp = __floats2half2_rn(v0, v1);
                    *(__half2*)(Ch + orow * (size_t)ldc + cc) = hp;
                }
            }
        }
    }
}

// ----- batched weight transpose + fp16 + B-fragment swizzle ----------------
struct WJob { const float* src; fp16* dst; int K; int N; };
struct WJobs { WJob j[25]; };

__global__ void wconv_all(WJobs jobs)
{
    WJob jb = jobs.j[blockIdx.z];
    int nbx = jb.N >> 5;
    int nb  = nbx * (jb.K >> 5);
    int bid = blockIdx.x;
    if (bid >= nb) return;
    int x = (bid % nbx) * 32;
    int y = (bid / nbx) * 32;

    __shared__ float t[32][33];
#pragma unroll
    for (int r = 0; r < 4; r++) {
        int row = y + threadIdx.y + r * 8;
        t[threadIdx.y + r * 8][threadIdx.x] = jb.src[(size_t)row * jb.N + x + threadIdx.x];
    }
    __syncthreads();
    int ktiles = jb.K >> 4;
#pragma unroll
    for (int r = 0; r < 4; r++) {
        int n = x + threadIdx.y + r * 8;
        int k = y + threadIdx.x;
        float v = t[threadIdx.x][threadIdx.y + r * 8];
        jb.dst[bfrag_idx(n, k, ktiles)] = __float2half_rn(v);
    }
}

// ------------------ pack qkv biases: [L][3*D] ------------------------------
__global__ void bpack(const float* __restrict__ bq, const float* __restrict__ bk,
                      const float* __restrict__ bv, float* __restrict__ dst)
{
    int l = blockIdx.x;
    int i = threadIdx.x;
    dst[l * QS + i]          = bq[l * Dc + i];
    dst[l * QS + Dc + i]     = bk[l * Dc + i];
    dst[l * QS + 2 * Dc + i] = bv[l * Dc + i];
}

// --------------------- fp32 -> fp16 convert (flat) --------------------------
__global__ void fcvt(const float* __restrict__ src, fp16* __restrict__ dst, int n4)
{
    int i = blockIdx.x * 256 + threadIdx.x;
    if (i < n4) {
        float4 v = ((const float4*)src)[i];
        __half2 a = __floats2half2_rn(v.x, v.y);
        __half2 b = __floats2half2_rn(v.z, v.w);
        uint2 o;
        o.x = *(uint32_t*)&a;
        o.y = *(uint32_t*)&b;
        ((uint2*)dst)[i] = o;
    }
}

// --------------------- zero the kvB buffer (pad rows stay 0) ---------------
__global__ void kvb_zero(fp16* __restrict__ kvB)
{
    size_t i = (size_t)blockIdx.x * 256 + threadIdx.x;
    ((uint4*)kvB)[i] = make_uint4(0, 0, 0, 0);   // 8 halves each
}

// --------------------- init: hidden-state row per batch -------------------
__global__ void init_h0(const float* __restrict__ hs, const void* __restrict__ resets,
                        float* __restrict__ x, fp16* __restrict__ xh)
{
    __shared__ int mode;
    int b = blockIdx.x;
    if (threadIdx.x == 0) {
        const unsigned int* w = (const unsigned int*)resets;
        bool allint = true, allflt = true;
        for (int i = 0; i < 16; i++) {
            unsigned int u = w[i];
            if (u != 0u && u != 1u) allint = false;
            if (u != 0u && u != 0x3F800000u) allflt = false;
        }
        mode = allint ? 0 : (allflt ? 2 : 1);
    }
    __syncthreads();
    bool rst;
    if (mode == 0)      rst = ((const int*)resets)[b] != 0;
    else if (mode == 2) rst = ((const float*)resets)[b] != 0.f;
    else                rst = ((const unsigned char*)resets)[b] != 0;

    float val = rst ? 0.f : hs[b * Dc + threadIdx.x];
    size_t o = (size_t)b * SP * Dc + threadIdx.x;
    x[o] = val;
    xh[o] = __float2half_rn(val);
}

// ------------------- FAVOR: kv = sum_s pk^T outer v, ksum ------------------
// Epilogue writes kv into kvB B-frag layout (fp16, ktiles=4, ksum at n=64)
// plus fp32 ksum for the layer-3 token-0 path.
__global__ __launch_bounds__(256)
void favor_kv(const fp16* __restrict__ qkv, fp16* __restrict__ kvB,
              float* __restrict__ ksum)
{
    int bh = blockIdx.x;
    int b = bh / Hc, h = bh % Hc;
    const fp16* kb = qkv + (size_t)b * SP * QS + Dc + h * HDc;
    const fp16* vb = qkv + (size_t)b * SP * QS + 2 * Dc + h * HDc;

    __shared__ float spk[16][HDc];
    __shared__ float sv [16][HDc];

    int tid = threadIdx.x;
    int tm = (tid >> 4) * 4;
    int td = (tid & 15) * 4;

    float acc[4][4];
#pragma unroll
    for (int i = 0; i < 4; i++)
#pragma unroll
        for (int j = 0; j < 4; j++) acc[i][j] = 0.f;
    float ks = 0.f;

    for (int s0 = 0; s0 < SP; s0 += 16) {
        int nch = min(16, SP - s0);
        for (int i = tid; i < nch * HDc; i += 256) {
            int ss = i >> 6, dd = i & 63;
            float kk = __half2float(kb[(size_t)(s0 + ss) * QS + dd]);
            spk[ss][dd] = fmaxf(kk, 0.f) + KEPS;
            sv[ss][dd]  = __half2float(vb[(size_t)(s0 + ss) * QS + dd]);
        }
        __syncthreads();
        for (int j = 0; j < nch; j++) {
            float pa[4], va[4];
#pragma unroll
            for (int i = 0; i < 4; i++) { pa[i] = spk[j][tm + i]; va[i] = sv[j][td + i]; }
#pragma unroll
            for (int i = 0; i < 4; i++)
#pragma unroll
                for (int l = 0; l < 4; l++)
                    acc[i][l] = fmaf(pa[i], va[l], acc[i][l]);
            if (tid < HDc) ks += spk[j][tid];
        }
        __syncthreads();
    }

    fp16* kout = kvB + (size_t)bh * KVB_H;
#pragma unroll
    for (int i = 0; i < 4; i++)
#pragma unroll
        for (int l = 0; l < 4; l++)
            kout[bfrag_idx(td + l, tm + i, 4)] = __float2half_rn(acc[i][l]);
    if (tid < HDc) {
        ksum[bh * HDc + tid] = ks;
        kout[bfrag_idx(64, tid, 4)] = __float2half_rn(ks);   // den column
    }
}

// ---------- FAVOR numerator on tensor cores ---------------------------------
// Block = (128 tokens) x (128 cols: 0..63 = num, 64 = den, rest pad-zero).
// A = relu(q)+eps staged fp16 in smem; B = kvB fragments via LDG.128.
#define FROW 144

__global__ __launch_bounds__(256, 2)
void favor_num_mma(const fp16* __restrict__ qkv, const fp16* __restrict__ kvB,
                   fp16* __restrict__ ah)
{
    __shared__ fp16 sa[128 * (FROW / 2)];
    __shared__ float sden[128];
    const uint32_t sbase = smem_u32(sa);

    const int bh = blockIdx.y;
    const int b = bh / Hc, h = bh % Hc;
    const int s0 = blockIdx.x * 128;
    const int tid  = threadIdx.x;
    const int wid  = tid >> 5;
    const int lane = tid & 31;
    const int wm = wid >> 2;
    const int wn = wid & 3;

    // stage A: pq = relu(q) + eps, fp16, 128 rows x 64 cols
    const __half2 z2 = __floats2half2_rn(0.f, 0.f);
    const __half2 e2 = __floats2half2_rn(KEPS, KEPS);
    for (int i = tid; i < 128 * 32; i += 256) {
        int r = i >> 5, c2 = i & 31;
        int s = s0 + r;
        uint32_t val = 0;
        if (s < SP) {
            __half2 q = *(const __half2*)(qkv + ((size_t)b * SP + s) * QS
                                          + h * HDc + c2 * 2);
            __half2 p = __hadd2(__hmax2(q, z2), e2);
            val = *(uint32_t*)&p;
        }
        *(uint32_t*)((char*)sa + r * FROW + c2 * 4) = val;
    }
    __syncthreads();

    const uint4* __restrict__ Wq = (const uint4*)(kvB + (size_t)bh * KVB_H);
    const int ntp0 = wn * 2;

    float acc[4][4][4];
#pragma unroll
    for (int a = 0; a < 4; a++)
#pragma unroll
        for (int bb = 0; bb < 4; bb++)
#pragma unroll
            for (int c = 0; c < 4; c++) acc[a][bb][c] = 0.f;

#pragma unroll
    for (int kt = 0; kt < 4; kt++) {
        uint4 bf0 = Wq[(ntp0       * 4 + kt) * 32 + lane];
        uint4 bf1 = Wq[((ntp0 + 1) * 4 + kt) * 32 + lane];
        uint32_t af[4][4];
        {
            const int r  = lane & 15;
            const int kh = (lane >> 4) * 8;
            const uint32_t kofs = (kt * 16 + kh) * 2;
#pragma unroll
            for (int mi = 0; mi < 4; mi++)
                LDSM4(af[mi], sbase + (wm * 64 + mi * 16 + r) * FROW + kofs);
        }
#pragma unroll
        for (int mi = 0; mi < 4; mi++) {
            MMA16816(acc[mi][0], af[mi], bf0.x, bf0.y);
            MMA16816(acc[mi][1], af[mi], bf0.z, bf0.w);
            MMA16816(acc[mi][2], af[mi], bf1.x, bf1.y);
            MMA16816(acc[mi][3], af[mi], bf1.z, bf1.w);
        }
    }

    // den exchange: col 64 lives in warp wn==2, nj==0, cq==0
    if (wn == 2 && (lane & 3) == 0) {
        int rq = lane >> 2;
#pragma unroll
        for (int mi = 0; mi < 4; mi++)
#pragma unroll
            for (int half = 0; half < 2; half++)
                sden[wm * 64 + mi * 16 + rq + half * 8] = acc[mi][0][half * 2];
    }
    __syncthreads();

    if (wn < 2) {
        const int rq = lane >> 2;
        const int cq = (lane & 3) * 2;
#pragma unroll
        for (int mi = 0; mi < 4; mi++) {
#pragma unroll
            for (int half = 0; half < 2; half++) {
                int rl = wm * 64 + mi * 16 + rq + half * 8;
                int s = s0 + rl;
                if (s >= SP) continue;
                float inv = 1.f / sden[rl];
#pragma unroll
                for (int nj = 0; nj < 4; nj++) {
                    int c = wn * 32 + nj * 8 + cq;
                    __half2 hp = __floats2half2_rn(acc[mi][nj][half * 2] * inv,
                                                   acc[mi][nj][half * 2 + 1] * inv);
                    *(__half2*)(ah + ((size_t)b * SP + s) * Dc + h * HDc + c) = hp;
                }
            }
        }
    }
}

// --------------- x = LayerNorm(a + x) * s + b  (a fp16, + fp16 out) --------
__global__ __launch_bounds__(128)
void add_ln(const fp16* __restrict__ a, float* __restrict__ x,
            fp16* __restrict__ xh,
            const float* __restrict__ s, const float* __restrict__ bb)
{
    size_t r = blockIdx.x;
    const fp16* ar = a + r * Dc;
    float* xr = x + r * Dc;
    int tid = threadIdx.x;
    int c0 = tid * 4;

    uint2 au = *(const uint2*)(ar + c0);
    __half2 ah0 = *(__half2*)&au.x;
    __half2 ah1 = *(__half2*)&au.y;
    float4 xv = *(const float4*)(xr + c0);
    float v[4] = { __low2float(ah0) + xv.x, __high2float(ah0) + xv.y,
                   __low2float(ah1) + xv.z, __high2float(ah1) + xv.w };
    float sum = v[0] + v[1] + v[2] + v[3];
    float sq  = fmaf(v[0], v[0], fmaf(v[1], v[1], fmaf(v[2], v[2], v[3] * v[3])));
#pragma unroll
    for (int o = 16; o > 0; o >>= 1) {
        sum += __shfl_xor_sync(0xFFFFFFFFu, sum, o);
        sq  += __shfl_xor_sync(0xFFFFFFFFu, sq, o);
    }
    __shared__ float rs[4], rq[4];
    int w = tid >> 5;
    if ((tid & 31) == 0) { rs[w] = sum; rq[w] = sq; }
    __syncthreads();
    sum = rs[0] + rs[1] + rs[2] + rs[3];
    sq  = rq[0] + rq[1] + rq[2] + rq[3];
    float mean = sum * (1.f / Dc);
    float var  = sq * (1.f / Dc) - mean * mean;
    float inv  = rsqrtf(var + LNEPS);

    float o0 = (v[0] - mean) * inv * s[c0 + 0] + bb[c0 + 0];
    float o1 = (v[1] - mean) * inv * s[c0 + 1] + bb[c0 + 1];
    float o2 = (v[2] - mean) * inv * s[c0 + 2] + bb[c0 + 2];
    float o3 = (v[3] - mean) * inv * s[c0 + 3] + bb[c0 + 3];
    *(float4*)(xr + c0) = make_float4(o0, o1, o2, o3);
    __half2 h0 = __floats2half2_rn(o0, o1);
    __half2 h1 = __floats2half2_rn(o2, o3);
    uint2 ou;
    ou.x = *(uint32_t*)&h0;
    ou.y = *(uint32_t*)&h1;
    *(uint2*)(xh + r * Dc + c0) = ou;
}

// ---- layer-3 compact variant -----------------------------------------------
__global__ __launch_bounds__(128)
void add_ln0(const fp16* __restrict__ a, const float* __restrict__ xin,
             size_t xin_stride, float* __restrict__ xout, fp16* __restrict__ xh,
             const float* __restrict__ s, const float* __restrict__ bb)
{
    int b = blockIdx.x;
    const fp16* ar = a + (size_t)b * Dc;
    const float* xr = xin + (size_t)b * xin_stride;
    int tid = threadIdx.x;
    int c0 = tid * 4;

    uint2 au = *(const uint2*)(ar + c0);
    __half2 ah0 = *(__half2*)&au.x;
    __half2 ah1 = *(__half2*)&au.y;
    float4 xv = *(const float4*)(xr + c0);
    float v[4] = { __low2float(ah0) + xv.x, __high2float(ah0) + xv.y,
                   __low2float(ah1) + xv.z, __high2float(ah1) + xv.w };
    float sum = v[0] + v[1] + v[2] + v[3];
    float sq  = fmaf(v[0], v[0], fmaf(v[1], v[1], fmaf(v[2], v[2], v[3] * v[3])));
#pragma unroll
    for (int o = 16; o > 0; o >>= 1) {
        sum += __shfl_xor_sync(0xFFFFFFFFu, sum, o);
        sq  += __shfl_xor_sync(0xFFFFFFFFu, sq, o);
    }
    __shared__ float rs[4], rq[4];
    int w = tid >> 5;
    if ((tid & 31) == 0) { rs[w] = sum; rq[w] = sq; }
    __syncthreads();
    sum = rs[0] + rs[1] + rs[2] + rs[3];
    sq  = rq[0] + rq[1] + rq[2] + rq[3];
    float mean = sum * (1.f / Dc);
    float var  = sq * (1.f / Dc) - mean * mean;
    float inv  = rsqrtf(var + LNEPS);

    float o0 = (v[0] - mean) * inv * s[c0 + 0] + bb[c0 + 0];
    float o1 = (v[1] - mean) * inv * s[c0 + 1] + bb[c0 + 1];
    float o2 = (v[2] - mean) * inv * s[c0 + 2] + bb[c0 + 2];
    float o3 = (v[3] - mean) * inv * s[c0 + 3] + bb[c0 + 3];
    *(float4*)(xout + (size_t)b * Dc + c0) = make_float4(o0, o1, o2, o3);
    __half2 h0 = __floats2half2_rn(o0, o1);
    __half2 h1 = __floats2half2_rn(o2, o3);
    uint2 ou;
    ou.x = *(uint32_t*)&h0;
    ou.y = *(uint32_t*)&h1;
    *(uint2*)(xh + (size_t)b * Dc + c0) = ou;
}

// ---- gather token-0 rows of xh into compact A buffer ----------------------
__global__ void gather_x0(const fp16* __restrict__ xh, fp16* __restrict__ xg0)
{
    int b = blockIdx.x;
    int i = threadIdx.x;
    ((uint32_t*)xg0)[b * (Dc / 2) + i] =
        ((const uint32_t*)(xh + (size_t)b * SP * Dc))[i];
}

// ---- layer-3: attention out for token 0 only (kv read from frag layout) ----
__global__ __launch_bounds__(64)
void favor_num0(const float* __restrict__ q0, const fp16* __restrict__ kvB,
                const float* __restrict__ ksum, fp16* __restrict__ ah0)
{
    int bh = blockIdx.x;
    int b = bh / Hc, h = bh % Hc;
    int d = threadIdx.x;   // 0..63

    __shared__ float spq[HDc];
    __shared__ float sks[HDc];
    float qv = q0[(size_t)b * Dc + h * HDc + d];
    spq[d] = fmaxf(qv, 0.f) + KEPS;
    sks[d] = ksum[bh * HDc + d];
    __syncthreads();

    const fp16* kb = kvB + (size_t)bh * KVB_H;
    float num = 0.f, den = 0.f;
#pragma unroll 8
    for (int m = 0; m < HDc; m++) {
        float pq = spq[m];
        num = fmaf(pq, __half2float(kb[bfrag_idx(d, m, 4)]), num);
        den = fmaf(pq, sks[m], den);
    }
    ah0[(size_t)b * Dc + h * HDc + d] = __float2half_rn(num / den);
}

// ---------------- head: copy h_out and compute q_vals ----------------------
__global__ __launch_bounds__(512)
void head_kernel(const float* __restrict__ x0, const float* __restrict__ Wqp,
                 const float* __restrict__ bqp, float* __restrict__ out)
{
    int b = blockIdx.x;
    int tid = threadIdx.x;
    const float* hr = x0 + (size_t)b * Dc;
    out[b * Dc + tid] = hr[tid];

    int w = tid >> 5, lane = tid & 31;
    float sum = 0.f;
    for (int i = lane; i < Dc; i += 32)
        sum = fmaf(hr[i], Wqp[i * Ac + w], sum);
#pragma unroll
    for (int o = 16; o > 0; o >>= 1)
        sum += __shfl_xor_sync(0xFFFFFFFFu, sum, o);
    if (lane == 0) out[Bc * Dc + b * Ac + w] = sum + bqp[w];
}

// ---------------------------------------------------------------------------
extern "C" void kernel_launch(void* const* d_in, const int* in_sizes, int n_in,
                              void* d_out, int out_size)
{
    const float* hs    = (const float*)d_in[0];
    const float* ins   = (const float*)d_in[1];
    const void*  rsts  = d_in[2];
    const float* W_emb = (const float*)d_in[3];
    const float* b_emb = (const float*)d_in[4];
    const float* Wq    = (const float*)d_in[5];
    const float* bq    = (const float*)d_in[6];
    const float* Wk    = (const float*)d_in[7];
    const float* bk    = (const float*)d_in[8];
    const float* Wv    = (const float*)d_in[9];
    const float* bv    = (const float*)d_in[10];
    const float* Wo    = (const float*)d_in[11];
    const float* bo    = (const float*)d_in[12];
    const float* ln1s  = (const float*)d_in[13];
    const float* ln1b  = (const float*)d_in[14];
    const float* ln2s  = (const float*)d_in[15];
    const float* ln2b  = (const float*)d_in[16];
    const float* W1    = (const float*)d_in[17];
    const float* b1    = (const float*)d_in[18];
    const float* W2    = (const float*)d_in[19];
    const float* b2    = (const float*)d_in[20];
    const float* Wqp   = (const float*)d_in[21];
    const float* bqp   = (const float*)d_in[22];
    float* out = (float*)d_out;

    cudaFuncSetAttribute(gemm_mma, cudaFuncAttributeMaxDynamicSharedMemorySize, GSMEM);

    float *x, *ks, *bqkv, *x0, *q0;
    fp16 *xh, *qkv, *ah, *th, *fh, *ih, *kvB, *xh0, *xg0, *ah0, *th0, *fh0;
    fp16 *wqkv, *wo, *w1, *w2, *we;
    cudaGetSymbolAddress((void**)&x,    g_x);
    cudaGetSymbolAddress((void**)&xh,   g_xh);
    cudaGetSymbolAddress((void**)&qkv,  g_qkv);
    cudaGetSymbolAddress((void**)&ah,   g_ah);
    cudaGetSymbolAddress((void**)&th,   g_th);
    cudaGetSymbolAddress((void**)&fh,   g_fh);
    cudaGetSymbolAddress((void**)&kvB,  g_kvB);
    cudaGetSymbolAddress((void**)&ks,   g_ks);
    cudaGetSymbolAddress((void**)&ih,   g_ih);
    cudaGetSymbolAddress((void**)&x0,   g_x0);
    cudaGetSymbolAddress((void**)&xh0,  g_xh0);
    cudaGetSymbolAddress((void**)&xg0,  g_xg0);
    cudaGetSymbolAddress((void**)&q0,   g_q0);
    cudaGetSymbolAddress((void**)&ah0,  g_ah0);
    cudaGetSymbolAddress((void**)&th0,  g_th0);
    cudaGetSymbolAddress((void**)&fh0,  g_fh0);
    cudaGetSymbolAddress((void**)&bqkv, g_bqkv);
    cudaGetSymbolAddress((void**)&wqkv, g_wqkv);
    cudaGetSymbolAddress((void**)&wo,   g_wo);
    cudaGetSymbolAddress((void**)&w1,   g_w1);
    cudaGetSymbolAddress((void**)&w2,   g_w2);
    cudaGetSymbolAddress((void**)&we,   g_we);

    // zero the kvB pad rows (rows 65..127 stay zero forever)
    kvb_zero<<<(Bc * Hc * KVB_H) / 8 / 256, 256>>>(kvB);

    // ins convert
    {
        int n4 = (Bc * Sc * OBSc) / 4;
        fcvt<<<(n4 + 255) / 256, 256>>>(ins, ih, n4);
    }
    // all weight conversions
    {
        WJobs jobs;
        int nj = 0;
        jobs.j[nj++] = { W_emb, we, OBSc, Dc };
        for (int l = 0; l < Lc; l++) {
            size_t od = (size_t)l * Dc * Dc;
            size_t oq = (size_t)l * QS * Dc;
            size_t o1 = (size_t)l * Fc * Dc;
            size_t o2 = (size_t)l * Dc * Fc;
            jobs.j[nj++] = { Wq + od, wqkv + oq,                       Dc, Dc };
            jobs.j[nj++] = { Wk + od, wqkv + oq + (size_t)Dc * Dc,     Dc, Dc };
            jobs.j[nj++] = { Wv + od, wqkv + oq + (size_t)2 * Dc * Dc, Dc, Dc };
            jobs.j[nj++] = { Wo + od, wo + od, Dc, Dc };
            jobs.j[nj++] = { W1 + o1, w1 + o1, Dc, Fc };
            jobs.j[nj++] = { W2 + o2, w2 + o2, Fc, Dc };
        }
        wconv_all<<<dim3(1024, 1, 25), dim3(32, 8)>>>(jobs);
    }
    // pack qkv biases
    bpack<<<Lc, Dc>>>(bq, bk, bv, bqkv);

    // embedding GEMM
    gemm_mma<<<dim3((Bc * Sc) / 128, Dc / 128), 256, GSMEM>>>(
        ih, we, b_emb, x, xh, Bc * Sc, Dc, OBSc, Dc, 0, 1);

    // hidden-state rows
    init_h0<<<Bc, Dc>>>(hs, rsts, x, xh);

    const int MB = (Tc + 127) / 128;              // 257 m-blocks
    const dim3 gQKV(MB, QS / 128);                // (257, 12)
    const dim3 gKV (MB, 1024 / 128);              // (257, 8)
    const dim3 gD  (MB, Dc / 128);                // (257, 4)
    const dim3 gF  (MB, Fc / 128);                // (257, 16)
    const dim3 gFN ((SP + 127) / 128, Bc * Hc);   // (5, 512)

    // ---- layers 0..2: full ----
    for (int l = 0; l < Lc - 1; l++) {
        size_t od = (size_t)l * Dc * Dc;
        size_t oq = (size_t)l * QS * Dc;
        size_t o1 = (size_t)l * Fc * Dc;
        size_t o2 = (size_t)l * Dc * Fc;

        gemm_mma<<<gQKV, 256, GSMEM>>>(xh, wqkv + oq, bqkv + l * QS,
                                       0, qkv, Tc, QS, Dc, QS, 0, 0);

        favor_kv<<<Bc * Hc, 256>>>(qkv, kvB, ks);
        favor_num_mma<<<gFN, 256>>>(qkv, kvB, ah);

        gemm_mma<<<gD, 256, GSMEM>>>(ah, wo + od, bo + l*Dc, 0, th, Tc, Dc, Dc, Dc, 0, 0);
        add_ln<<<Tc, 128>>>(th, x, xh, ln1s + l*Dc, ln1b + l*Dc);

        gemm_mma<<<gF, 256, GSMEM>>>(xh, w1 + o1, b1 + l*Fc, 0, fh, Tc, Fc, Dc, Fc, 1, 0);
        gemm_mma<<<gD, 256, GSMEM>>>(fh, w2 + o2, b2 + l*Dc, 0, th, Tc, Dc, Fc, Dc, 0, 0);
        add_ln<<<Tc, 128>>>(th, x, xh, ln2s + l*Dc, ln2b + l*Dc);
    }

    // ---- layer 3: only token-0 rows beyond the KV projection ----
    {
        const int l = Lc - 1;
        size_t od = (size_t)l * Dc * Dc;
        size_t oq = (size_t)l * QS * Dc;
        size_t o1 = (size_t)l * Fc * Dc;
        size_t o2 = (size_t)l * Dc * Fc;

        gemm_mma<<<gKV, 256, GSMEM>>>(xh, wqkv + oq + (size_t)Dc * Dc,
                                      bqkv + l * QS + Dc,
                                      0, qkv + Dc, Tc, 1024, Dc, QS, 0, 0);
        gather_x0<<<Bc, 256>>>(xh, xg0);
        gemm_mma<<<dim3(1, Dc / 128), 256, GSMEM>>>(
            xg0, wqkv + oq, bqkv + l * QS, q0, 0, Bc, Dc, Dc, Dc, 0, 0);

        favor_kv<<<Bc * Hc, 256>>>(qkv, kvB, ks);
        favor_num0<<<Bc * Hc, 64>>>(q0, kvB, ks, ah0);

        gemm_mma<<<dim3(1, Dc / 128), 256, GSMEM>>>(
            ah0, wo + od, bo + l*Dc, 0, th0, Bc, Dc, Dc, Dc, 0, 0);
        add_ln0<<<Bc, 128>>>(th0, x, (size_t)SP * Dc, x0, xh0,
                             ln1s + l*Dc, ln1b + l*Dc);

        gemm_mma<<<dim3(1, Fc / 128), 256, GSMEM>>>(
            xh0, w1 + o1, b1 + l*Fc, 0, fh0, Bc, Fc, Dc, Fc, 1, 0);
        gemm_mma<<<dim3(1, Dc / 128), 256, GSMEM>>>(
            fh0, w2 + o2, b2 + l*Dc, 0, th0, Bc, Dc, Fc, Dc, 0, 0);
        add_ln0<<<Bc, 128>>>(th0, x0, (size_t)Dc, x0, xh0,
                             ln2s + l*Dc, ln2b + l*Dc);
    }

    head_kernel<<<Bc, Dc>>>(x0, Wqp, bqp, out);
}

// round 17
// speedup vs baseline: 1.9061x; 1.0784x over previous
#include <cuda_runtime.h>
#include <cuda_fp16.h>
#include <cstdint>

// ---------------------------------------------------------------------------
// TransformerAgent: 4-layer FAVOR+ transformer.
// GEMMs: fp16 mma.sync; A via cp.async+ldmatrix (BK=64, 3-stage), B weights
// pre-swizzled into mma fragment layout fed by LDG.128. FAVOR kv AND
// numerator on tensor cores (kv in B-frag layout, ksum as column 64).
// Layer 3: token-0 rows only.
// ---------------------------------------------------------------------------

#define Bc 64
#define Sc 512
#define SP 513
#define Dc 512
#define Hc 8
#define HDc 64
#define Fc 2048
#define Lc 4
#define Ac 16
#define OBSc 128
#define Tc (Bc * SP)          // 32832 tokens
#define QS (3 * Dc)           // fused qkv row stride = 1536
#define KVB_H 8192            // halves per (b,h) kvB tile

#define KEPS 1e-3f
#define LNEPS 1e-6f

typedef __half fp16;

// ------------------------- scratch (static device) ------------------------
__device__ float g_x  [Tc * Dc];
__device__ fp16  g_xh [Tc * Dc];
__device__ fp16  g_qkv[Tc * QS];
__device__ fp16  g_ah [Tc * Dc];
__device__ fp16  g_th [Tc * Dc];
__device__ fp16  g_fh [Tc * Fc];
__device__ __align__(256) fp16 g_kvB[Bc * Hc * KVB_H];
__device__ float g_ks [Bc * Hc * HDc];
__device__ fp16  g_ih [Bc * Sc * OBSc];
// layer-3 compact (token-0 rows only)
__device__ float g_x0  [Bc * Dc];
__device__ fp16  g_xh0 [Bc * Dc];
__device__ fp16  g_xg0 [Bc * Dc];
__device__ float g_q0  [Bc * Dc];
__device__ fp16  g_ah0 [Bc * Dc];
__device__ fp16  g_th0 [Bc * Dc];
__device__ fp16  g_fh0 [Bc * Fc];
// weights in mma B-fragment layout (ntPair-major), fp16
__device__ __align__(256) fp16 g_wqkv[Lc * QS * Dc];
__device__ float g_bqkv[Lc * QS];
__device__ __align__(256) fp16 g_wo [Lc * Dc * Dc];
__device__ __align__(256) fp16 g_w1 [Lc * Fc * Dc];
__device__ __align__(256) fp16 g_w2 [Lc * Dc * Fc];
__device__ __align__(256) fp16 g_we [Dc * OBSc];

// --------------------------- PTX helpers -----------------------------------
__device__ __forceinline__ uint32_t smem_u32(const void* p) {
    uint32_t a;
    asm("{ .reg .u64 t; cvta.to.shared.u64 t, %1; cvt.u32.u64 %0, t; }"
        : "=r"(a) : "l"(p));
    return a;
}

#define CP_ASYNC16(s, g) \
    asm volatile("cp.async.ca.shared.global [%0], [%1], 16;" :: "r"(s), "l"(g))
#define CP_COMMIT() asm volatile("cp.async.commit_group;" ::: "memory")
#define CP_WAIT1()  asm volatile("cp.async.wait_group 1;" ::: "memory")

#define LDSM4(r, a) \
    asm volatile("ldmatrix.sync.aligned.m8n8.x4.shared.b16 {%0,%1,%2,%3}, [%4];" \
        : "=r"((r)[0]), "=r"((r)[1]), "=r"((r)[2]), "=r"((r)[3]) : "r"(a))

#define LDSM4T(r, a) \
    asm volatile("ldmatrix.sync.aligned.m8n8.x4.trans.shared.b16 {%0,%1,%2,%3}, [%4];" \
        : "=r"((r)[0]), "=r"((r)[1]), "=r"((r)[2]), "=r"((r)[3]) : "r"(a))

#define MMA16816(d, a, b0, b1) \
    asm volatile("mma.sync.aligned.m16n8k16.row.col.f32.f16.f16.f32 " \
        "{%0,%1,%2,%3},{%4,%5,%6,%7},{%8,%9},{%0,%1,%2,%3};" \
        : "+f"((d)[0]), "+f"((d)[1]), "+f"((d)[2]), "+f"((d)[3]) \
        : "r"((a)[0]), "r"((a)[1]), "r"((a)[2]), "r"((a)[3]), "r"(b0), "r"(b1))

// B-fragment half index for element (n, k) with K = ktiles*16
__device__ __forceinline__ size_t bfrag_idx(int n, int k, int ktiles) {
    int k0 = k & 15;
    int lane = ((n & 7) << 2) | ((k0 >> 1) & 3);
    int sub  = ((n >> 3) & 1) * 4 + ((k0 >= 8) ? 2 : 0) + (k0 & 1);
    return (((size_t)(n >> 4) * ktiles + (k >> 4)) * 32 + lane) * 8 + sub;
}

// ---------------------------------------------------------------------------
// fp16 GEMM (round-11 config): C[M,N] = A[M,K] @ W^T + bias.
// ---------------------------------------------------------------------------
#define GROW   144
#define GARR   (128 * GROW)
#define NSTAGE 3
#define GSMEM  (NSTAGE * GARR)

__global__ __launch_bounds__(256, 2)
void gemm_mma(const fp16* __restrict__ A, const fp16* __restrict__ W,
              const float* __restrict__ bias,
              float* __restrict__ Cf, fp16* __restrict__ Ch,
              int M, int N, int K, int ldc, int relu, int rowmap)
{
    extern __shared__ char smem[];
    const uint32_t sbase = smem_u32(smem);
    const int tid  = threadIdx.x;
    const int wid  = tid >> 5;
    const int lane = tid & 31;
    const int m0 = blockIdx.x * 128;
    const int n0 = blockIdx.y * 128;
    const int nch = K >> 6;
    const int ktiles = K >> 4;

    const int wm = wid >> 2;
    const int wn = wid & 3;
    const uint4* __restrict__ Wq = (const uint4*)W;
    const size_t ntp0 = (size_t)((n0 >> 4) + wn * 2);

    float acc[4][4][4];
#pragma unroll
    for (int a = 0; a < 4; a++)
#pragma unroll
        for (int b = 0; b < 4; b++)
#pragma unroll
            for (int c = 0; c < 4; c++) acc[a][b][c] = 0.f;

    auto load_chunk = [&](int c) {
        const int s = c % NSTAGE;
        const size_t kb = (size_t)c * 64;
        const uint32_t sA = sbase + s * GARR;
#pragma unroll
        for (int it = 0; it < 4; it++) {
            int i = tid + it * 256;
            int row = i >> 3;
            int c8  = (i & 7) * 8;
            int gr = min(m0 + row, M - 1);
            CP_ASYNC16(sA + row * GROW + (i & 7) * 16,
                       (const char*)(A + (size_t)gr * K + kb + c8));
        }
        CP_COMMIT();
    };

    load_chunk(0);
    if (nch > 1) load_chunk(1); else CP_COMMIT();

    for (int c = 0; c < nch; c++) {
        const int s = c % NSTAGE;
        CP_WAIT1();
        __syncthreads();

        if (c + 2 < nch) load_chunk(c + 2); else CP_COMMIT();

        const uint32_t sA = sbase + s * GARR;

#pragma unroll
        for (int ks = 0; ks < 4; ks++) {
            const int kt = c * 4 + ks;
            uint4 bf0 = Wq[(ntp0       * ktiles + kt) * 32 + lane];
            uint4 bf1 = Wq[((ntp0 + 1) * ktiles + kt) * 32 + lane];
            uint32_t af[4][4];
            {
                const int r  = lane & 15;
                const int kh = (lane >> 4) * 8;
                const uint32_t kofs = (ks * 16 + kh) * 2;
#pragma unroll
                for (int mi = 0; mi < 4; mi++)
                    LDSM4(af[mi], sA + (wm * 64 + mi * 16 + r) * GROW + kofs);
            }
#pragma unroll
            for (int mi = 0; mi < 4; mi++) {
                MMA16816(acc[mi][0], af[mi], bf0.x, bf0.y);
                MMA16816(acc[mi][1], af[mi], bf0.z, bf0.w);
                MMA16816(acc[mi][2], af[mi], bf1.x, bf1.y);
                MMA16816(acc[mi][3], af[mi], bf1.z, bf1.w);
            }
        }
    }

    const int rq = lane >> 2;
    const int cq = (lane & 3) * 2;
#pragma unroll
    for (int mi = 0; mi < 4; mi++) {
#pragma unroll
        for (int half = 0; half < 2; half++) {
            int rr = m0 + wm * 64 + mi * 16 + rq + half * 8;
            if (rr >= M) continue;
            size_t orow = rowmap ? (size_t)(rr + rr / Sc + 1) : (size_t)rr;
#pragma unroll
            for (int nj = 0; nj < 4; nj++) {
                int cc = n0 + wn * 32 + nj * 8 + cq;
                float v0 = acc[mi][nj][half * 2 + 0] + bias[cc];
                float v1 = acc[mi][nj][half * 2 + 1] + bias[cc + 1];
                if (relu) { v0 = fmaxf(v0, 0.f); v1 = fmaxf(v1, 0.f); }
                if (Cf)
                    *(float2*)(Cf + orow * (size_t)ldc + cc) = make_float2(v0, v1);
                if (Ch) {
                    __half2 hp = __floats2half2_rn(v0, v1);
                    *(__half2*)(Ch + orow * (size_t)ldc + cc) = hp;
                }
            }
        }
    }
}

// ----- batched weight transpose + fp16 + B-fragment swizzle ----------------
struct WJob { const float* src; fp16* dst; int K; int N; };
struct WJobs { WJob j[25]; };

__global__ void wconv_all(WJobs jobs)
{
    WJob jb = jobs.j[blockIdx.z];
    int nbx = jb.N >> 5;
    int nb  = nbx * (jb.K >> 5);
    int bid = blockIdx.x;
    if (bid >= nb) return;
    int x = (bid % nbx) * 32;
    int y = (bid / nbx) * 32;

    __shared__ float t[32][33];
#pragma unroll
    for (int r = 0; r < 4; r++) {
        int row = y + threadIdx.y + r * 8;
        t[threadIdx.y + r * 8][threadIdx.x] = jb.src[(size_t)row * jb.N + x + threadIdx.x];
    }
    __syncthreads();
    int ktiles = jb.K >> 4;
#pragma unroll
    for (int r = 0; r < 4; r++) {
        int n = x + threadIdx.y + r * 8;
        int k = y + threadIdx.x;
        float v = t[threadIdx.x][threadIdx.y + r * 8];
        jb.dst[bfrag_idx(n, k, ktiles)] = __float2half_rn(v);
    }
}

// ------------------ pack qkv biases: [L][3*D] ------------------------------
__global__ void bpack(const float* __restrict__ bq, const float* __restrict__ bk,
                      const float* __restrict__ bv, float* __restrict__ dst)
{
    int l = blockIdx.x;
    int i = threadIdx.x;
    dst[l * QS + i]          = bq[l * Dc + i];
    dst[l * QS + Dc + i]     = bk[l * Dc + i];
    dst[l * QS + 2 * Dc + i] = bv[l * Dc + i];
}

// --------------------- fp32 -> fp16 convert (flat) --------------------------
__global__ void fcvt(const float* __restrict__ src, fp16* __restrict__ dst, int n4)
{
    int i = blockIdx.x * 256 + threadIdx.x;
    if (i < n4) {
        float4 v = ((const float4*)src)[i];
        __half2 a = __floats2half2_rn(v.x, v.y);
        __half2 b = __floats2half2_rn(v.z, v.w);
        uint2 o;
        o.x = *(uint32_t*)&a;
        o.y = *(uint32_t*)&b;
        ((uint2*)dst)[i] = o;
    }
}

// --------------------- zero the kvB buffer (pad rows stay 0) ---------------
__global__ void kvb_zero(fp16* __restrict__ kvB)
{
    size_t i = (size_t)blockIdx.x * 256 + threadIdx.x;
    ((uint4*)kvB)[i] = make_uint4(0, 0, 0, 0);
}

// --------------------- init: hidden-state row per batch -------------------
__global__ void init_h0(const float* __restrict__ hs, const void* __restrict__ resets,
                        float* __restrict__ x, fp16* __restrict__ xh)
{
    __shared__ int mode;
    int b = blockIdx.x;
    if (threadIdx.x == 0) {
        const unsigned int* w = (const unsigned int*)resets;
        bool allint = true, allflt = true;
        for (int i = 0; i < 16; i++) {
            unsigned int u = w[i];
            if (u != 0u && u != 1u) allint = false;
            if (u != 0u && u != 0x3F800000u) allflt = false;
        }
        mode = allint ? 0 : (allflt ? 2 : 1);
    }
    __syncthreads();
    bool rst;
    if (mode == 0)      rst = ((const int*)resets)[b] != 0;
    else if (mode == 2) rst = ((const float*)resets)[b] != 0.f;
    else                rst = ((const unsigned char*)resets)[b] != 0;

    float val = rst ? 0.f : hs[b * Dc + threadIdx.x];
    size_t o = (size_t)b * SP * Dc + threadIdx.x;
    x[o] = val;
    xh[o] = __float2half_rn(val);
}

// ---------- FAVOR kv on tensor cores ----------------------------------------
// kv[d1,d2] = sum_s pk[s,d1] * v[s,d2]; A = pk^T, B = v^T via ldmatrix.trans.
// 8 warps: 2(m: d1 32 each) x 4(n: d2 16 each). 5 chunks of 128 s-rows.
// Epilogue: kvB B-frag (ksum at column 64) + fp32 ksum.
#define KROW 144   // 72 halves pitch

__global__ __launch_bounds__(256)
void favor_kv_mma(const fp16* __restrict__ qkv, fp16* __restrict__ kvB,
                  float* __restrict__ ksum)
{
    __shared__ fp16 spk[128 * (KROW / 2)];
    __shared__ fp16 sv [128 * (KROW / 2)];
    const uint32_t pk_base = smem_u32(spk);
    const uint32_t v_base  = smem_u32(sv);

    const int bh = blockIdx.x;
    const int b = bh / Hc, h = bh % Hc;
    const fp16* kb = qkv + (size_t)b * SP * QS + Dc + h * HDc;
    const fp16* vb = qkv + (size_t)b * SP * QS + 2 * Dc + h * HDc;

    const int tid  = threadIdx.x;
    const int wid  = tid >> 5;
    const int lane = tid & 31;
    const int wm = wid >> 2;      // 0..1 -> d1 block of 32
    const int wn = wid & 3;       // 0..3 -> d2 block of 16

    float acc[2][2][4];
#pragma unroll
    for (int i = 0; i < 2; i++)
#pragma unroll
        for (int j = 0; j < 2; j++)
#pragma unroll
            for (int c = 0; c < 4; c++) acc[i][j][c] = 0.f;
    float ks = 0.f;

    const __half2 z2 = __floats2half2_rn(0.f, 0.f);
    const __half2 e2 = __floats2half2_rn(KEPS, KEPS);

    for (int chunk = 0; chunk < 5; chunk++) {
        const int s0 = chunk * 128;
        for (int i = tid; i < 128 * 32; i += 256) {
            int r = i >> 5, c2 = i & 31;
            int s = s0 + r;
            uint32_t kval = 0, vval = 0;
            if (s < SP) {
                __half2 kq = *(const __half2*)(kb + (size_t)s * QS + c2 * 2);
                __half2 p = __hadd2(__hmax2(kq, z2), e2);
                kval = *(uint32_t*)&p;
                vval = *(const uint32_t*)(vb + (size_t)s * QS + c2 * 2);
            }
            *(uint32_t*)((char*)spk + r * KROW + c2 * 4) = kval;
            *(uint32_t*)((char*)sv  + r * KROW + c2 * 4) = vval;
        }
        __syncthreads();

        // ksum partial: column tid over 128 rows
        if (tid < HDc) {
            float t = 0.f;
#pragma unroll 4
            for (int r = 0; r < 128; r++)
                t += __half2float(spk[r * (KROW / 2) + tid]);
            ks += t;
        }

#pragma unroll
        for (int k16 = 0; k16 < 8; k16++) {
            const int r = lane & 7;
            const int grp = lane >> 3;
            // A (pk^T): srow uses grp>>1, col uses grp&1
            const int a_srow = k16 * 16 + ((grp >> 1) & 1) * 8 + r;
            const int a_cbit = (grp & 1) * 8;
            uint32_t af[2][4];
#pragma unroll
            for (int mi = 0; mi < 2; mi++)
                LDSM4T(af[mi], pk_base + a_srow * KROW
                               + (wm * 32 + mi * 16 + a_cbit) * 2);
            // B (v^T): srow uses grp&1, col uses grp>>1
            const int b_srow = k16 * 16 + (grp & 1) * 8 + r;
            const int b_cbit = ((grp >> 1) & 1) * 8;
            uint32_t bf[4];
            LDSM4T(bf, v_base + b_srow * KROW + (wn * 16 + b_cbit) * 2);
#pragma unroll
            for (int mi = 0; mi < 2; mi++) {
                MMA16816(acc[mi][0], af[mi], bf[0], bf[1]);
                MMA16816(acc[mi][1], af[mi], bf[2], bf[3]);
            }
        }
        __syncthreads();
    }

    // epilogue: write kvB frags (n=d2, k=d1)
    fp16* kout = kvB + (size_t)bh * KVB_H;
    const int rq = lane >> 2;
    const int cq = (lane & 3) * 2;
#pragma unroll
    for (int mi = 0; mi < 2; mi++) {
#pragma unroll
        for (int half = 0; half < 2; half++) {
            int d1 = wm * 32 + mi * 16 + rq + half * 8;
#pragma unroll
            for (int nj = 0; nj < 2; nj++) {
                int d2 = wn * 16 + nj * 8 + cq;
                kout[bfrag_idx(d2,     d1, 4)] = __float2half_rn(acc[mi][nj][half * 2 + 0]);
                kout[bfrag_idx(d2 + 1, d1, 4)] = __float2half_rn(acc[mi][nj][half * 2 + 1]);
            }
        }
    }
    if (tid < HDc) {
        ksum[bh * HDc + tid] = ks;
        kout[bfrag_idx(64, tid, 4)] = __float2half_rn(ks);
    }
}

// ---------- FAVOR numerator on tensor cores ---------------------------------
#define FROW 144

__global__ __launch_bounds__(256, 2)
void favor_num_mma(const fp16* __restrict__ qkv, const fp16* __restrict__ kvB,
                   fp16* __restrict__ ah)
{
    __shared__ fp16 sa[128 * (FROW / 2)];
    __shared__ float sden[128];
    const uint32_t sbase = smem_u32(sa);

    const int bh = blockIdx.y;
    const int b = bh / Hc, h = bh % Hc;
    const int s0 = blockIdx.x * 128;
    const int tid  = threadIdx.x;
    const int wid  = tid >> 5;
    const int lane = tid & 31;
    const int wm = wid >> 2;
    const int wn = wid & 3;

    const __half2 z2 = __floats2half2_rn(0.f, 0.f);
    const __half2 e2 = __floats2half2_rn(KEPS, KEPS);
    for (int i = tid; i < 128 * 32; i += 256) {
        int r = i >> 5, c2 = i & 31;
        int s = s0 + r;
        uint32_t val = 0;
        if (s < SP) {
            __half2 q = *(const __half2*)(qkv + ((size_t)b * SP + s) * QS
                                          + h * HDc + c2 * 2);
            __half2 p = __hadd2(__hmax2(q, z2), e2);
            val = *(uint32_t*)&p;
        }
        *(uint32_t*)((char*)sa + r * FROW + c2 * 4) = val;
    }
    __syncthreads();

    const uint4* __restrict__ Wq = (const uint4*)(kvB + (size_t)bh * KVB_H);
    const int ntp0 = wn * 2;

    float acc[4][4][4];
#pragma unroll
    for (int a = 0; a < 4; a++)
#pragma unroll
        for (int bb = 0; bb < 4; bb++)
#pragma unroll
            for (int c = 0; c < 4; c++) acc[a][bb][c] = 0.f;

#pragma unroll
    for (int kt = 0; kt < 4; kt++) {
        uint4 bf0 = Wq[(ntp0       * 4 + kt) * 32 + lane];
        uint4 bf1 = Wq[((ntp0 + 1) * 4 + kt) * 32 + lane];
        uint32_t af[4][4];
        {
            const int r  = lane & 15;
            const int kh = (lane >> 4) * 8;
            const uint32_t kofs = (kt * 16 + kh) * 2;
#pragma unroll
            for (int mi = 0; mi < 4; mi++)
                LDSM4(af[mi], sbase + (wm * 64 + mi * 16 + r) * FROW + kofs);
        }
#pragma unroll
        for (int mi = 0; mi < 4; mi++) {
            MMA16816(acc[mi][0], af[mi], bf0.x, bf0.y);
            MMA16816(acc[mi][1], af[mi], bf0.z, bf0.w);
            MMA16816(acc[mi][2], af[mi], bf1.x, bf1.y);
            MMA16816(acc[mi][3], af[mi], bf1.z, bf1.w);
        }
    }

    if (wn == 2 && (lane & 3) == 0) {
        int rq = lane >> 2;
#pragma unroll
        for (int mi = 0; mi < 4; mi++)
#pragma unroll
            for (int half = 0; half < 2; half++)
                sden[wm * 64 + mi * 16 + rq + half * 8] = acc[mi][0][half * 2];
    }
    __syncthreads();

    if (wn < 2) {
        const int rq = lane >> 2;
        const int cq = (lane & 3) * 2;
#pragma unroll
        for (int mi = 0; mi < 4; mi++) {
#pragma unroll
            for (int half = 0; half < 2; half++) {
                int rl = wm * 64 + mi * 16 + rq + half * 8;
                int s = s0 + rl;
                if (s >= SP) continue;
                float inv = 1.f / sden[rl];
#pragma unroll
                for (int nj = 0; nj < 4; nj++) {
                    int c = wn * 32 + nj * 8 + cq;
                    __half2 hp = __floats2half2_rn(acc[mi][nj][half * 2] * inv,
                                                   acc[mi][nj][half * 2 + 1] * inv);
                    *(__half2*)(ah + ((size_t)b * SP + s) * Dc + h * HDc + c) = hp;
                }
            }
        }
    }
}

// --------------- x = LayerNorm(a + x) * s + b  (a fp16, + fp16 out) --------
__global__ __launch_bounds__(128)
void add_ln(const fp16* __restrict__ a, float* __restrict__ x,
            fp16* __restrict__ xh,
            const float* __restrict__ s, const float* __restrict__ bb)
{
    size_t r = blockIdx.x;
    const fp16* ar = a + r * Dc;
    float* xr = x + r * Dc;
    int tid = threadIdx.x;
    int c0 = tid * 4;

    uint2 au = *(const uint2*)(ar + c0);
    __half2 ah0 = *(__half2*)&au.x;
    __half2 ah1 = *(__half2*)&au.y;
    float4 xv = *(const float4*)(xr + c0);
    float v[4] = { __low2float(ah0) + xv.x, __high2float(ah0) + xv.y,
                   __low2float(ah1) + xv.z, __high2float(ah1) + xv.w };
    float sum = v[0] + v[1] + v[2] + v[3];
    float sq  = fmaf(v[0], v[0], fmaf(v[1], v[1], fmaf(v[2], v[2], v[3] * v[3])));
#pragma unroll
    for (int o = 16; o > 0; o >>= 1) {
        sum += __shfl_xor_sync(0xFFFFFFFFu, sum, o);
        sq  += __shfl_xor_sync(0xFFFFFFFFu, sq, o);
    }
    __shared__ float rs[4], rq[4];
    int w = tid >> 5;
    if ((tid & 31) == 0) { rs[w] = sum; rq[w] = sq; }
    __syncthreads();
    sum = rs[0] + rs[1] + rs[2] + rs[3];
    sq  = rq[0] + rq[1] + rq[2] + rq[3];
    float mean = sum * (1.f / Dc);
    float var  = sq * (1.f / Dc) - mean * mean;
    float inv  = rsqrtf(var + LNEPS);

    float o0 = (v[0] - mean) * inv * s[c0 + 0] + bb[c0 + 0];
    float o1 = (v[1] - mean) * inv * s[c0 + 1] + bb[c0 + 1];
    float o2 = (v[2] - mean) * inv * s[c0 + 2] + bb[c0 + 2];
    float o3 = (v[3] - mean) * inv * s[c0 + 3] + bb[c0 + 3];
    *(float4*)(xr + c0) = make_float4(o0, o1, o2, o3);
    __half2 h0 = __floats2half2_rn(o0, o1);
    __half2 h1 = __floats2half2_rn(o2, o3);
    uint2 ou;
    ou.x = *(uint32_t*)&h0;
    ou.y = *(uint32_t*)&h1;
    *(uint2*)(xh + r * Dc + c0) = ou;
}

// ---- layer-3 compact variant -----------------------------------------------
__global__ __launch_bounds__(128)
void add_ln0(const fp16* __restrict__ a, const float* __restrict__ xin,
             size_t xin_stride, float* __restrict__ xout, fp16* __restrict__ xh,
             const float* __restrict__ s, const float* __restrict__ bb)
{
    int b = blockIdx.x;
    const fp16* ar = a + (size_t)b * Dc;
    const float* xr = xin + (size_t)b * xin_stride;
    int tid = threadIdx.x;
    int c0 = tid * 4;

    uint2 au = *(const uint2*)(ar + c0);
    __half2 ah0 = *(__half2*)&au.x;
    __half2 ah1 = *(__half2*)&au.y;
    float4 xv = *(const float4*)(xr + c0);
    float v[4] = { __low2float(ah0) + xv.x, __high2float(ah0) + xv.y,
                   __low2float(ah1) + xv.z, __high2float(ah1) + xv.w };
    float sum = v[0] + v[1] + v[2] + v[3];
    float sq  = fmaf(v[0], v[0], fmaf(v[1], v[1], fmaf(v[2], v[2], v[3] * v[3])));
#pragma unroll
    for (int o = 16; o > 0; o >>= 1) {
        sum += __shfl_xor_sync(0xFFFFFFFFu, sum, o);
        sq  += __shfl_xor_sync(0xFFFFFFFFu, sq, o);
    }
    __shared__ float rs[4], rq[4];
    int w = tid >> 5;
    if ((tid & 31) == 0) { rs[w] = sum; rq[w] = sq; }
    __syncthreads();
    sum = rs[0] + rs[1] + rs[2] + rs[3];
    sq  = rq[0] + rq[1] + rq[2] + rq[3];
    float mean = sum * (1.f / Dc);
    float var  = sq * (1.f / Dc) - mean * mean;
    float inv  = rsqrtf(var + LNEPS);

    float o0 = (v[0] - mean) * inv * s[c0 + 0] + bb[c0 + 0];
    float o1 = (v[1] - mean) * inv * s[c0 + 1] + bb[c0 + 1];
    float o2 = (v[2] - mean) * inv * s[c0 + 2] + bb[c0 + 2];
    float o3 = (v[3] - mean) * inv * s[c0 + 3] + bb[c0 + 3];
    *(float4*)(xout + (size_t)b * Dc + c0) = make_float4(o0, o1, o2, o3);
    __half2 h0 = __floats2half2_rn(o0, o1);
    __half2 h1 = __floats2half2_rn(o2, o3);
    uint2 ou;
    ou.x = *(uint32_t*)&h0;
    ou.y = *(uint32_t*)&h1;
    *(uint2*)(xh + (size_t)b * Dc + c0) = ou;
}

// ---- gather token-0 rows of xh into compact A buffer ----------------------
__global__ void gather_x0(const fp16* __restrict__ xh, fp16* __restrict__ xg0)
{
    int b = blockIdx.x;
    int i = threadIdx.x;
    ((uint32_t*)xg0)[b * (Dc / 2) + i] =
        ((const uint32_t*)(xh + (size_t)b * SP * Dc))[i];
}

// ---- layer-3: attention out for token 0 only (kv read from frag layout) ----
__global__ __launch_bounds__(64)
void favor_num0(const float* __restrict__ q0, const fp16* __restrict__ kvB,
                const float* __restrict__ ksum, fp16* __restrict__ ah0)
{
    int bh = blockIdx.x;
    int b = bh / Hc, h = bh % Hc;
    int d = threadIdx.x;

    __shared__ float spq[HDc];
    __shared__ float sks[HDc];
    float qv = q0[(size_t)b * Dc + h * HDc + d];
    spq[d] = fmaxf(qv, 0.f) + KEPS;
    sks[d] = ksum[bh * HDc + d];
    __syncthreads();

    const fp16* kb = kvB + (size_t)bh * KVB_H;
    float num = 0.f, den = 0.f;
#pragma unroll 8
    for (int m = 0; m < HDc; m++) {
        float pq = spq[m];
        num = fmaf(pq, __half2float(kb[bfrag_idx(d, m, 4)]), num);
        den = fmaf(pq, sks[m], den);
    }
    ah0[(size_t)b * Dc + h * HDc + d] = __float2half_rn(num / den);
}

// ---------------- head: copy h_out and compute q_vals ----------------------
__global__ __launch_bounds__(512)
void head_kernel(const float* __restrict__ x0, const float* __restrict__ Wqp,
                 const float* __restrict__ bqp, float* __restrict__ out)
{
    int b = blockIdx.x;
    int tid = threadIdx.x;
    const float* hr = x0 + (size_t)b * Dc;
    out[b * Dc + tid] = hr[tid];

    int w = tid >> 5, lane = tid & 31;
    float sum = 0.f;
    for (int i = lane; i < Dc; i += 32)
        sum = fmaf(hr[i], Wqp[i * Ac + w], sum);
#pragma unroll
    for (int o = 16; o > 0; o >>= 1)
        sum += __shfl_xor_sync(0xFFFFFFFFu, sum, o);
    if (lane == 0) out[Bc * Dc + b * Ac + w] = sum + bqp[w];
}

// ---------------------------------------------------------------------------
extern "C" void kernel_launch(void* const* d_in, const int* in_sizes, int n_in,
                              void* d_out, int out_size)
{
    const float* hs    = (const float*)d_in[0];
    const float* ins   = (const float*)d_in[1];
    const void*  rsts  = d_in[2];
    const float* W_emb = (const float*)d_in[3];
    const float* b_emb = (const float*)d_in[4];
    const float* Wq    = (const float*)d_in[5];
    const float* bq    = (const float*)d_in[6];
    const float* Wk    = (const float*)d_in[7];
    const float* bk    = (const float*)d_in[8];
    const float* Wv    = (const float*)d_in[9];
    const float* bv    = (const float*)d_in[10];
    const float* Wo    = (const float*)d_in[11];
    const float* bo    = (const float*)d_in[12];
    const float* ln1s  = (const float*)d_in[13];
    const float* ln1b  = (const float*)d_in[14];
    const float* ln2s  = (const float*)d_in[15];
    const float* ln2b  = (const float*)d_in[16];
    const float* W1    = (const float*)d_in[17];
    const float* b1    = (const float*)d_in[18];
    const float* W2    = (const float*)d_in[19];
    const float* b2    = (const float*)d_in[20];
    const float* Wqp   = (const float*)d_in[21];
    const float* bqp   = (const float*)d_in[22];
    float* out = (float*)d_out;

    cudaFuncSetAttribute(gemm_mma, cudaFuncAttributeMaxDynamicSharedMemorySize, GSMEM);

    float *x, *ks, *bqkv, *x0, *q0;
    fp16 *xh, *qkv, *ah, *th, *fh, *ih, *kvB, *xh0, *xg0, *ah0, *th0, *fh0;
    fp16 *wqkv, *wo, *w1, *w2, *we;
    cudaGetSymbolAddress((void**)&x,    g_x);
    cudaGetSymbolAddress((void**)&xh,   g_xh);
    cudaGetSymbolAddress((void**)&qkv,  g_qkv);
    cudaGetSymbolAddress((void**)&ah,   g_ah);
    cudaGetSymbolAddress((void**)&th,   g_th);
    cudaGetSymbolAddress((void**)&fh,   g_fh);
    cudaGetSymbolAddress((void**)&kvB,  g_kvB);
    cudaGetSymbolAddress((void**)&ks,   g_ks);
    cudaGetSymbolAddress((void**)&ih,   g_ih);
    cudaGetSymbolAddress((void**)&x0,   g_x0);
    cudaGetSymbolAddress((void**)&xh0,  g_xh0);
    cudaGetSymbolAddress((void**)&xg0,  g_xg0);
    cudaGetSymbolAddress((void**)&q0,   g_q0);
    cudaGetSymbolAddress((void**)&ah0,  g_ah0);
    cudaGetSymbolAddress((void**)&th0,  g_th0);
    cudaGetSymbolAddress((void**)&fh0,  g_fh0);
    cudaGetSymbolAddress((void**)&bqkv, g_bqkv);
    cudaGetSymbolAddress((void**)&wqkv, g_wqkv);
    cudaGetSymbolAddress((void**)&wo,   g_wo);
    cudaGetSymbolAddress((void**)&w1,   g_w1);
    cudaGetSymbolAddress((void**)&w2,   g_w2);
    cudaGetSymbolAddress((void**)&we,   g_we);

    // zero the kvB pad rows
    kvb_zero<<<(Bc * Hc * KVB_H) / 8 / 256, 256>>>(kvB);

    // ins convert
    {
        int n4 = (Bc * Sc * OBSc) / 4;
        fcvt<<<(n4 + 255) / 256, 256>>>(ins, ih, n4);
    }
    // all weight conversions
    {
        WJobs jobs;
        int nj = 0;
        jobs.j[nj++] = { W_emb, we, OBSc, Dc };
        for (int l = 0; l < Lc; l++) {
            size_t od = (size_t)l * Dc * Dc;
            size_t oq = (size_t)l * QS * Dc;
            size_t o1 = (size_t)l * Fc * Dc;
            size_t o2 = (size_t)l * Dc * Fc;
            jobs.j[nj++] = { Wq + od, wqkv + oq,                       Dc, Dc };
            jobs.j[nj++] = { Wk + od, wqkv + oq + (size_t)Dc * Dc,     Dc, Dc };
            jobs.j[nj++] = { Wv + od, wqkv + oq + (size_t)2 * Dc * Dc, Dc, Dc };
            jobs.j[nj++] = { Wo + od, wo + od, Dc, Dc };
            jobs.j[nj++] = { W1 + o1, w1 + o1, Dc, Fc };
            jobs.j[nj++] = { W2 + o2, w2 + o2, Fc, Dc };
        }
        wconv_all<<<dim3(1024, 1, 25), dim3(32, 8)>>>(jobs);
    }
    // pack qkv biases
    bpack<<<Lc, Dc>>>(bq, bk, bv, bqkv);

    // embedding GEMM
    gemm_mma<<<dim3((Bc * Sc) / 128, Dc / 128), 256, GSMEM>>>(
        ih, we, b_emb, x, xh, Bc * Sc, Dc, OBSc, Dc, 0, 1);

    // hidden-state rows
    init_h0<<<Bc, Dc>>>(hs, rsts, x, xh);

    const int MB = (Tc + 127) / 128;
    const dim3 gQKV(MB, QS / 128);
    const dim3 gKV (MB, 1024 / 128);
    const dim3 gD  (MB, Dc / 128);
    const dim3 gF  (MB, Fc / 128);
    const dim3 gFN ((SP + 127) / 128, Bc * Hc);

    // ---- layers 0..2: full ----
    for (int l = 0; l < Lc - 1; l++) {
        size_t od = (size_t)l * Dc * Dc;
        size_t oq = (size_t)l * QS * Dc;
        size_t o1 = (size_t)l * Fc * Dc;
        size_t o2 = (size_t)l * Dc * Fc;

        gemm_mma<<<gQKV, 256, GSMEM>>>(xh, wqkv + oq, bqkv + l * QS,
                                       0, qkv, Tc, QS, Dc, QS, 0, 0);

        favor_kv_mma<<<Bc * Hc, 256>>>(qkv, kvB, ks);
        favor_num_mma<<<gFN, 256>>>(qkv, kvB, ah);

        gemm_mma<<<gD, 256, GSMEM>>>(ah, wo + od, bo + l*Dc, 0, th, Tc, Dc, Dc, Dc, 0, 0);
        add_ln<<<Tc, 128>>>(th, x, xh, ln1s + l*Dc, ln1b + l*Dc);

        gemm_mma<<<gF, 256, GSMEM>>>(xh, w1 + o1, b1 + l*Fc, 0, fh, Tc, Fc, Dc, Fc, 1, 0);
        gemm_mma<<<gD, 256, GSMEM>>>(fh, w2 + o2, b2 + l*Dc, 0, th, Tc, Dc, Fc, Dc, 0, 0);
        add_ln<<<Tc, 128>>>(th, x, xh, ln2s + l*Dc, ln2b + l*Dc);
    }

    // ---- layer 3: only token-0 rows beyond the KV projection ----
    {
        const int l = Lc - 1;
        size_t od = (size_t)l * Dc * Dc;
        size_t oq = (size_t)l * QS * Dc;
        size_t o1 = (size_t)l * Fc * Dc;
        size_t o2 = (size_t)l * Dc * Fc;

        gemm_mma<<<gKV, 256, GSMEM>>>(xh, wqkv + oq + (size_t)Dc * Dc,
                                      bqkv + l * QS + Dc,
                                      0, qkv + Dc, Tc, 1024, Dc, QS, 0, 0);
        gather_x0<<<Bc, 256>>>(xh, xg0);
        gemm_mma<<<dim3(1, Dc / 128), 256, GSMEM>>>(
            xg0, wqkv + oq, bqkv + l * QS, q0, 0, Bc, Dc, Dc, Dc, 0, 0);

        favor_kv_mma<<<Bc * Hc, 256>>>(qkv, kvB, ks);
        favor_num0<<<Bc * Hc, 64>>>(q0, kvB, ks, ah0);

        gemm_mma<<<dim3(1, Dc / 128), 256, GSMEM>>>(
            ah0, wo + od, bo + l*Dc, 0, th0, Bc, Dc, Dc, Dc, 0, 0);
        add_ln0<<<Bc, 128>>>(th0, x, (size_t)SP * Dc, x0, xh0,
                             ln1s + l*Dc, ln1b + l*Dc);

        gemm_mma<<<dim3(1, Fc / 128), 256, GSMEM>>>(
            xh0, w1 + o1, b1 + l*Fc, 0, fh0, Bc, Fc, Dc, Fc, 1, 0);
        gemm_mma<<<dim3(1, Dc / 128), 256, GSMEM>>>(
            fh0, w2 + o2, b2 + l*Dc, 0, th0, Bc, Dc, Fc, Dc, 0, 0);
        add_ln0<<<Bc, 128>>>(th0, x0, (size_t)Dc, x0, xh0,
                             ln2s + l*Dc, ln2b + l*Dc);
    }

    head_kernel<<<Bc, Dc>>>(x0, Wqp, bqp, out);
}